// round 11
// baseline (speedup 1.0000x reference)
#include <cuda_runtime.h>

#define PRNG_VARIANT 0  // 0 = threefry_partitionable (modern JAX default), 1 = legacy

namespace ta {
constexpr int Bb=2, Hh=12, BH=24, Ff=16, Pp=196, Nn=3136, Cc=768, Dd=64, Ll=128, PPAD=208;
constexpr int FB=4, NS=Nn/FB, NC4=NS/4;
constexpr long long QS = (long long)BH*Nn*Dd;
constexpr long long OQ=0, OKk=OQ+QS, OV=OKk+QS, OQKN=OV+QS, OLM=OQKN+QS;
constexpr long long OK1=OLM+(long long)BH*Ll*Dd;
constexpr long long OK2=OK1+(long long)BH*Nn*Ll;
constexpr long long OX1=OK2+(long long)BH*Ll*Ff*PPAD;
constexpr long long OXO=OX1+(long long)BH*Ll*Ff*Dd;
constexpr long long OXD=OXO+(long long)Bb*Nn*Ff*Cc;
constexpr long long OQ2=OXD+(long long)Bb*Nn*Cc;
constexpr long long OU =OQ2+(long long)Bb*Nn*Cc;                 // u[n,h,c]
constexpr long long OXW=OU +(long long)Bb*Nn*Hh*Cc;              // xo_w[n,h,c]
constexpr long long OWKT=OXW+(long long)Bb*Nn*Hh*Cc;             // Wk^T 768x768
constexpr long long OAO=OWKT+(long long)Cc*Cc;
constexpr long long TOT=OAO+(long long)Bb*Nn*Cc;
}
__device__ float g_s[ta::TOT];
__device__ int   g_idx[ta::BH*ta::Ll];

using namespace ta;

// ------------------------- threefry2x32 (general key) -----------------------
__device__ __forceinline__ void tf(unsigned k0, unsigned k1, unsigned x0, unsigned x1,
                                   unsigned &y0, unsigned &y1) {
    const unsigned k2 = 0x1BD11BDAu ^ k0 ^ k1;
    x0 += k0; x1 += k1;
#define TFR(r) { x0 += x1; x1 = (x1<<(r))|(x1>>(32-(r))); x1 ^= x0; }
    TFR(13) TFR(15) TFR(26) TFR(6)   x0 += k1; x1 += k2 + 1u;
    TFR(17) TFR(29) TFR(16) TFR(24)  x0 += k2; x1 += k0 + 2u;
    TFR(13) TFR(15) TFR(26) TFR(6)   x0 += k0; x1 += k1 + 3u;
    TFR(17) TFR(29) TFR(16) TFR(24)  x0 += k1; x1 += k2 + 4u;
    TFR(13) TFR(15) TFR(26) TFR(6)   x0 += k2; x1 += k0 + 5u;
#undef TFR
    y0 = x0; y1 = x1;
}

__device__ int jax_idx0(int i) {
    const unsigned span = (unsigned)Nn;
    const unsigned mult = 2048u;
    unsigned hi, lo;
#if PRNG_VARIANT == 0
    unsigned a0,a1,b0,b1,y0,y1;
    tf(0u,42u, 0u,0u, a0,a1);
    tf(0u,42u, 0u,1u, b0,b1);
    tf(a0,a1, 0u,(unsigned)i, y0,y1); hi = y0 ^ y1;
    tf(b0,b1, 0u,(unsigned)i, y0,y1); lo = y0 ^ y1;
#else
    unsigned s00,s01,s10,s11,y0,y1;
    tf(0u,42u, 0u,2u, s00,s01);
    tf(0u,42u, 1u,3u, s10,s11);
    unsigned k1a=s00, k1b=s10, k2a=s01, k2b=s11;
    if (i < 12) { tf(k1a,k1b,(unsigned)i,(unsigned)(i+12),y0,y1); hi = y0; }
    else        { tf(k1a,k1b,(unsigned)(i-12),(unsigned)i,y0,y1); hi = y1; }
    if (i < 12) { tf(k2a,k2b,(unsigned)i,(unsigned)(i+12),y0,y1); lo = y0; }
    else        { tf(k2a,k2b,(unsigned)(i-12),(unsigned)i,y0,y1); lo = y1; }
#endif
    return (int)((((hi % span) * mult) + (lo % span)) % span);
}

// ------------------------- generic tiled f32 SIMT GEMM ----------------------
template <int BM, int BN, int BK, int TM, int TN, bool NT, class Epi>
__global__ __launch_bounds__(256) void gemm_kernel(
    const float* __restrict__ A, const float* __restrict__ B,
    int M, int N, int K, int lda, int ldb,
    long long sA1, long long sA2, long long sB1, long long sB2, int zdiv, Epi epi)
{
    __shared__ float As[BK][BM];
    __shared__ float Bs[BK][BN];
    const int z = blockIdx.z, za = z / zdiv, zb = z % zdiv;
    A += za * sA1 + zb * sA2;
    B += za * sB1 + zb * sB2;
    const int m0 = blockIdx.y * BM, n0 = blockIdx.x * BN;
    const int tid = threadIdx.x;
    const int tx = tid % (BN / TN), ty = tid / (BN / TN);
    float acc[TM][TN];
#pragma unroll
    for (int i = 0; i < TM; i++)
#pragma unroll
        for (int j = 0; j < TN; j++) acc[i][j] = 0.f;

    for (int k0 = 0; k0 < K; k0 += BK) {
        for (int i = tid; i < BM * BK / 4; i += 256) {
            int m = i / (BK / 4), kq = i % (BK / 4);
            float4 v = *(const float4*)(A + (long long)(m0 + m) * lda + k0 + kq * 4);
            As[kq*4+0][m] = v.x; As[kq*4+1][m] = v.y; As[kq*4+2][m] = v.z; As[kq*4+3][m] = v.w;
        }
        if (!NT) {
            for (int i = tid; i < BK * BN / 4; i += 256) {
                int kk = i / (BN / 4), nq = i % (BN / 4);
                *(float4*)&Bs[kk][nq*4] = *(const float4*)(B + (long long)(k0 + kk) * ldb + n0 + nq * 4);
            }
        } else {
            for (int i = tid; i < BN * BK / 4; i += 256) {
                int n = i / (BK / 4), kq = i % (BK / 4);
                float4 v = *(const float4*)(B + (long long)(n0 + n) * ldb + k0 + kq * 4);
                Bs[kq*4+0][n] = v.x; Bs[kq*4+1][n] = v.y; Bs[kq*4+2][n] = v.z; Bs[kq*4+3][n] = v.w;
            }
        }
        __syncthreads();
#pragma unroll
        for (int kk = 0; kk < BK; kk++) {
            float a[TM], b[TN];
#pragma unroll
            for (int i = 0; i < TM; i++) a[i] = As[kk][ty * TM + i];
#pragma unroll
            for (int j = 0; j < TN; j++) b[j] = Bs[kk][tx * TN + j];
#pragma unroll
            for (int i = 0; i < TM; i++)
#pragma unroll
                for (int j = 0; j < TN; j++) acc[i][j] += a[i] * b[j];
        }
        __syncthreads();
    }
#pragma unroll
    for (int i = 0; i < TM; i++)
#pragma unroll
        for (int j = 0; j < TN; j++)
            epi(z, m0 + ty * TM + i, n0 + tx * TN + j, acc[i][j]);
}

// --------- K1 logits GEMM with fused row softmax (BN=128 = full L row) ------
__global__ __launch_bounds__(256) void k1_softmax_kernel() {
    constexpr int BM = 64, BN = 128, BK = 16, TM = 4, TN = 8;
    __shared__ float As[BK][BM];
    __shared__ float Bs[BK][BN];
    const int z = blockIdx.z;
    const float* A = g_s + OQ  + (long long)z * Nn * Dd;
    const float* B = g_s + OLM + (long long)z * Ll * Dd;
    const int m0 = blockIdx.y * BM;
    const int tid = threadIdx.x;
    const int tx = tid % 16, ty = tid / 16;
    float acc[TM][TN];
#pragma unroll
    for (int i = 0; i < TM; i++)
#pragma unroll
        for (int j = 0; j < TN; j++) acc[i][j] = 0.f;

    for (int k0 = 0; k0 < Dd; k0 += BK) {
        for (int i = tid; i < BM * BK / 4; i += 256) {
            int m = i / 4, kq = i % 4;
            float4 v = *(const float4*)(A + (long long)(m0 + m) * Dd + k0 + kq * 4);
            As[kq*4+0][m] = v.x; As[kq*4+1][m] = v.y; As[kq*4+2][m] = v.z; As[kq*4+3][m] = v.w;
        }
        for (int i = tid; i < BN * BK / 4; i += 256) {
            int n = i / 4, kq = i % 4;
            float4 v = *(const float4*)(B + (long long)n * Dd + k0 + kq * 4);
            Bs[kq*4+0][n] = v.x; Bs[kq*4+1][n] = v.y; Bs[kq*4+2][n] = v.z; Bs[kq*4+3][n] = v.w;
        }
        __syncthreads();
#pragma unroll
        for (int kk = 0; kk < BK; kk++) {
            float a[TM], b[TN];
#pragma unroll
            for (int i = 0; i < TM; i++) a[i] = As[kk][ty * TM + i];
#pragma unroll
            for (int j = 0; j < TN; j++) b[j] = Bs[kk][tx * TN + j];
#pragma unroll
            for (int i = 0; i < TM; i++)
#pragma unroll
                for (int j = 0; j < TN; j++) acc[i][j] += a[i] * b[j];
        }
        __syncthreads();
    }
    // row softmax: each row's 128 cols live on 16 contiguous lanes (same ty)
#pragma unroll
    for (int i = 0; i < TM; i++) {
        float mx = acc[i][0];
#pragma unroll
        for (int j = 1; j < TN; j++) mx = fmaxf(mx, acc[i][j]);
#pragma unroll
        for (int o = 1; o < 16; o <<= 1) mx = fmaxf(mx, __shfl_xor_sync(0xffffffffu, mx, o));
        float e[TN], s = 0.f;
#pragma unroll
        for (int j = 0; j < TN; j++) { e[j] = expf(acc[i][j] - mx); s += e[j]; }
#pragma unroll
        for (int o = 1; o < 16; o <<= 1) s += __shfl_xor_sync(0xffffffffu, s, o);
        float inv = 1.f / s;
        long long base = OK1 + ((long long)z * Nn + m0 + ty * TM + i) * Ll + tx * 8;
        *(float4*)&g_s[base]     = make_float4(e[0]*inv, e[1]*inv, e[2]*inv, e[3]*inv);
        *(float4*)&g_s[base + 4] = make_float4(e[4]*inv, e[5]*inv, e[6]*inv, e[7]*inv);
    }
}

// ------------------------- tf32 tensor-core GEMM (cp.async 3-stage) ---------
__device__ __forceinline__ float to_tf32(float x) {
    float r; asm("cvt.rna.tf32.f32 %0, %1;" : "=f"(r) : "f"(x)); return r;
}
__device__ __forceinline__ void mma_tf32(float (&d)[4], const float (&a)[4], const float (&b)[2]) {
    asm volatile("mma.sync.aligned.m16n8k8.row.col.f32.tf32.tf32.f32 "
        "{%0,%1,%2,%3}, {%4,%5,%6,%7}, {%8,%9}, {%0,%1,%2,%3};"
        : "+f"(d[0]), "+f"(d[1]), "+f"(d[2]), "+f"(d[3])
        : "r"(__float_as_uint(a[0])), "r"(__float_as_uint(a[1])),
          "r"(__float_as_uint(a[2])), "r"(__float_as_uint(a[3])),
          "r"(__float_as_uint(b[0])), "r"(__float_as_uint(b[1])));
}
__device__ __forceinline__ void cpa16(float* dst, const float* src) {
    unsigned s = (unsigned)__cvta_generic_to_shared(dst);
    asm volatile("cp.async.cg.shared.global [%0], [%1], 16;" :: "r"(s), "l"(src));
}

// BM x (WN*32) x 16 tiles, 8 warps, 3-stage cp.async.
// X3CAP enables the error-compensated 3xTF32 path for warps whose column
// range start is < x3lim (per-warp uniform; 32-col warp tiles align).
template <int BM, int WN, bool X3CAP, class Epi>
__global__ __launch_bounds__(256) void gemm_tf32(
    const float* __restrict__ A, const float* __restrict__ B,
    int K, int lda, int ldb, long long sA1, long long sB1, int x3lim, Epi epi)
{
    constexpr int BN = WN * 32, BK = 16;
    constexpr int LDA_S = BK + 4;
    constexpr int LDB_S = BN + 8;
    constexpr int MF = (BM * WN) / 128;
    __shared__ float As[3][BM * LDA_S];
    __shared__ float Bs[3][BK * LDB_S];
    const int z = blockIdx.z;
    const int m0 = blockIdx.y * BM, n0 = blockIdx.x * BN;
    const float* Ab = A + (long long)z * sA1 + (long long)m0 * lda;
    const float* Bb = B + (long long)z * sB1 + n0;
    const int tid = threadIdx.x, wid = tid >> 5, lane = tid & 31;
    const int wm = (wid / WN) * (16 * MF), wn = (wid % WN) * 32;
    const int g = lane >> 2, t = lane & 3;
    const bool ux3 = X3CAP && (n0 + wn < x3lim);

    float acc[MF][4][4];
#pragma unroll
    for (int i = 0; i < MF; i++)
#pragma unroll
        for (int j = 0; j < 4; j++)
#pragma unroll
            for (int r = 0; r < 4; r++) acc[i][j][r] = 0.f;

    auto stage_load = [&](int s, int k0) {
#pragma unroll
        for (int i = tid; i < BM * 4; i += 256) {
            int m = i >> 2, kq = i & 3;
            cpa16(&As[s][m * LDA_S + kq * 4], Ab + (long long)m * lda + k0 + kq * 4);
        }
#pragma unroll
        for (int i = tid; i < BK * (BN / 4); i += 256) {
            int kk = i / (BN / 4), nq = i % (BN / 4);
            cpa16(&Bs[s][kk * LDB_S + nq * 4], Bb + (long long)(k0 + kk) * ldb + nq * 4);
        }
        asm volatile("cp.async.commit_group;");
    };

    const int KT = K / BK;
    stage_load(0, 0);
    if (KT > 1) stage_load(1, BK);
    for (int kt = 0; kt < KT; kt++) {
        const int s = kt % 3;
        if (kt + 2 < KT) {
            stage_load((kt + 2) % 3, (kt + 2) * BK);
            asm volatile("cp.async.wait_group 2;");
        } else if (kt + 1 < KT) {
            asm volatile("cp.async.wait_group 1;");
        } else {
            asm volatile("cp.async.wait_group 0;");
        }
        __syncthreads();
#pragma unroll
        for (int ks = 0; ks < 2; ks++) {
            const int kb = ks * 8;
            float a[MF][4], b[4][2];
            float al[MF][4], bl[4][2];
#pragma unroll
            for (int mf = 0; mf < MF; mf++) {
                int ml = wm + mf * 16 + g;
                float r0 = As[s][ ml      * LDA_S + kb + t];
                float r1 = As[s][(ml + 8) * LDA_S + kb + t];
                float r2 = As[s][ ml      * LDA_S + kb + t + 4];
                float r3 = As[s][(ml + 8) * LDA_S + kb + t + 4];
                a[mf][0] = to_tf32(r0); a[mf][1] = to_tf32(r1);
                a[mf][2] = to_tf32(r2); a[mf][3] = to_tf32(r3);
                if (ux3) {
                    al[mf][0] = to_tf32(r0 - a[mf][0]); al[mf][1] = to_tf32(r1 - a[mf][1]);
                    al[mf][2] = to_tf32(r2 - a[mf][2]); al[mf][3] = to_tf32(r3 - a[mf][3]);
                }
            }
#pragma unroll
            for (int nf = 0; nf < 4; nf++) {
                int nb = wn + nf * 8 + g;
                float r0 = Bs[s][(kb + t)     * LDB_S + nb];
                float r1 = Bs[s][(kb + t + 4) * LDB_S + nb];
                b[nf][0] = to_tf32(r0); b[nf][1] = to_tf32(r1);
                if (ux3) {
                    bl[nf][0] = to_tf32(r0 - b[nf][0]); bl[nf][1] = to_tf32(r1 - b[nf][1]);
                }
            }
#pragma unroll
            for (int mf = 0; mf < MF; mf++)
#pragma unroll
                for (int nf = 0; nf < 4; nf++) {
                    mma_tf32(acc[mf][nf], a[mf], b[nf]);
                    if (ux3) {
                        mma_tf32(acc[mf][nf], al[mf], b[nf]);
                        mma_tf32(acc[mf][nf], a[mf], bl[nf]);
                    }
                }
        }
        __syncthreads();
    }
#pragma unroll
    for (int mf = 0; mf < MF; mf++) {
        int m = m0 + wm + mf * 16 + g;
#pragma unroll
        for (int nf = 0; nf < 4; nf++) {
            int n = n0 + wn + nf * 8 + 2 * t;
            epi(z, m,     n,     acc[mf][nf][0]);
            epi(z, m,     n + 1, acc[mf][nf][1]);
            epi(z, m + 8, n,     acc[mf][nf][2]);
            epi(z, m + 8, n + 1, acc[mf][nf][3]);
        }
    }
}

// ------------------------- epilogues ----------------------------------------
struct EpiQKV {
    __device__ void operator()(int, int m, int n, float v) const {
        int part = n / Cc, c = n - part * Cc;
        int hh = c >> 6, dd = c & 63;
        int b = m / Nn, nn = m - b * Nn;
        long long idx = (((long long)(b * Hh + hh)) * Nn + nn) * Dd + dd;
        const float sc = 0.35355339059327378f;
        if (part == 0)      g_s[OQ  + idx] = v * sc;
        else if (part == 1) g_s[OKk + idx] = v * sc;
        else                g_s[OV  + idx] = v;
    }
};
struct EpiK2 {
    __device__ void operator()(int z, int m, int n, float v) const {
        int f = n / Pp, p = n - f * Pp;
        g_s[OK2 + (((long long)z * Ll + m) * Ff + f) * PPAD + p] = v;
    }
};
struct EpiX1 {
    __device__ void operator()(int z, int m, int n, float v) const {
        int bh = z >> 4, f = z & 15;
        g_s[OX1 + (((long long)bh * Ll + m) * Ff + f) * Dd + n] = v;
    }
};
struct EpiXO {
    __device__ void operator()(int z, int m, int n, float v) const {
        int b = z / Hh, hh = z - b * Hh;
        int f = n >> 6, dd = n & 63;
        long long base = (long long)(b * Nn + m);
        g_s[OXO + (base * Ff + f) * Cc + hh * Dd + dd] = v;
        if (f == m / Pp) g_s[OXD + base * Cc + hh * Dd + dd] = v;
    }
};
struct EpiQ2 {
    __device__ void operator()(int, int m, int n, float v) const {
        g_s[OQ2 + (long long)m * Cc + n] = v * 0.125f;
    }
};
struct EpiU {     // u[n,h,c]; z = h
    __device__ void operator()(int z, int m, int n, float v) const {
        g_s[OU + ((long long)m * Hh + z) * Cc + n] = v;
    }
};
struct EpiAO {    // ao[m][z*64 + n]; z = h
    __device__ void operator()(int z, int m, int n, float v) const {
        g_s[OAO + (long long)m * Cc + z * 64 + n] = v;
    }
};
struct EpiOut {
    float* out; const float* bias;
    __device__ void operator()(int, int m, int n, float v) const {
        out[(long long)m * Cc + n] = v + bias[n];
    }
};

// ------------------------- small kernels ------------------------------------
__global__ void norm_kernel() {
    long long gw = (long long)blockIdx.x * 8 + (threadIdx.x >> 5);
    int lane = threadIdx.x & 31;
    float2 v = ((const float2*)(g_s + OQ + gw * Dd))[lane];
    float ss = v.x * v.x + v.y * v.y;
#pragma unroll
    for (int o = 16; o; o >>= 1) ss += __shfl_xor_sync(0xffffffffu, ss, o);
    float dnm = fmaxf(sqrtf(ss), 1e-12f);
    int bh = (int)(gw / Nn), n = (int)(gw - (long long)bh * Nn);
    long long base = OQKN + (long long)bh * Nn * Dd;
    g_s[base + (long long)(2 * lane)     * Nn + n] = v.x / dnm;
    g_s[base + (long long)(2 * lane + 1) * Nn + n] = v.y / dnm;
}

__device__ __forceinline__ unsigned ctarank() {
    unsigned r; asm("mov.u32 %0, %%cluster_ctarank;" : "=r"(r)); return r;
}
__device__ __forceinline__ unsigned mapa_u32(unsigned addr, unsigned rank) {
    unsigned r; asm("mapa.shared::cluster.u32 %0, %1, %2;" : "=r"(r) : "r"(addr), "r"(rank));
    return r;
}

__global__ __launch_bounds__(256) __cluster_dims__(FB, 1, 1) void fps_kernel4() {
    extern __shared__ float ssm[];                            // [Dd][NS]
    __shared__ unsigned long long cand[2][FB];
    __shared__ float cur[Dd];
    __shared__ float s_val[8];
    __shared__ int   s_idx[8], s_pick;
    const int b = blockIdx.x / FB;
    const int j = (int)ctarank();
    const int tid = threadIdx.x;
    const float* qkT = g_s + OQKN + (long long)b * Nn * Dd;
    for (int i = tid; i < Dd * NC4; i += 256) {
        int d = i / NC4, c = i % NC4;
        *(float4*)&ssm[d * NS + 4 * c] =
            *(const float4*)(qkT + (long long)d * Nn + j * NS + 4 * c);
    }
    float ms0 = 0.f, ms1 = 0.f, ms2 = 0.f, ms3 = 0.f;
    if (tid == 0) {
        int i0 = jax_idx0(b);
        if (j == 0) g_idx[b * Ll] = i0;
        s_pick = i0;
    }
    __syncthreads();
    int pick = s_pick;
    if (tid < Dd) cur[tid] = qkT[(long long)tid * Nn + pick];
    if (tid < NC4 && tid == (pick >> 2) - j * NC4) {
        switch (pick & 3) { case 0: ms0 = 10.f; break; case 1: ms1 = 10.f; break;
                            case 2: ms2 = 10.f; break; default: ms3 = 10.f; }
    }
    __syncthreads();
    const int lane = tid & 31, wid = tid >> 5;
    const unsigned candBase = (unsigned)__cvta_generic_to_shared(&cand[0][0]);
    for (int step = 1; step < Ll; step++) {
        float bv = 3.4e38f; int bi = 0x7fffffff;
        if (tid < NC4) {
            float ax = 0.f, ay = 0.f, az = 0.f, aw = 0.f;
#pragma unroll
            for (int d = 0; d < Dd; d++) {
                float4 v = *(const float4*)&ssm[d * NS + 4 * tid];
                float c = cur[d];
                ax += v.x * c; ay += v.y * c; az += v.z * c; aw += v.w * c;
            }
            ms0 = fmaxf(ms0, fabsf(ax)); ms1 = fmaxf(ms1, fabsf(ay));
            ms2 = fmaxf(ms2, fabsf(az)); ms3 = fmaxf(ms3, fabsf(aw));
            int nb = j * NS + 4 * tid;
            bv = ms0; bi = nb;
            if (ms1 < bv) { bv = ms1; bi = nb + 1; }
            if (ms2 < bv) { bv = ms2; bi = nb + 2; }
            if (ms3 < bv) { bv = ms3; bi = nb + 3; }
        }
#pragma unroll
        for (int o = 16; o; o >>= 1) {
            float ov = __shfl_down_sync(0xffffffffu, bv, o);
            int   oi = __shfl_down_sync(0xffffffffu, bi, o);
            if (ov < bv || (ov == bv && oi < bi)) { bv = ov; bi = oi; }
        }
        if (lane == 0) { s_val[wid] = bv; s_idx[wid] = bi; }
        __syncthreads();
        const int par = step & 1;
        if (tid == 0) {
#pragma unroll
            for (int w = 0; w < 8; w++) {
                float ov = s_val[w]; int oi = s_idx[w];
                if (w == 0 || ov < bv || (ov == bv && oi < bi)) { bv = ov; bi = oi; }
            }
            unsigned long long packed =
                ((unsigned long long)__float_as_uint(bv) << 32) | (unsigned)bi;
            unsigned slot = candBase + (unsigned)((par * FB + j) * 8);
#pragma unroll
            for (int jj = 0; jj < FB; jj++) {
                unsigned raddr = mapa_u32(slot, (unsigned)jj);
                asm volatile("st.shared::cluster.b64 [%0], %1;" :: "r"(raddr), "l"(packed));
            }
        }
        asm volatile("barrier.cluster.arrive.aligned;" ::: "memory");
        asm volatile("barrier.cluster.wait.aligned;" ::: "memory");
        unsigned long long best = cand[par][0];
#pragma unroll
        for (int jj = 1; jj < FB; jj++) {
            unsigned long long c2 = cand[par][jj];
            if (c2 < best) best = c2;
        }
        pick = (int)(unsigned)(best & 0xffffffffull);
        if (j == 0 && tid == 0) g_idx[b * Ll + step] = pick;
        if (tid < Dd) cur[tid] = qkT[(long long)tid * Nn + pick];
        if (tid < NC4 && tid == (pick >> 2) - j * NC4) {
            switch (pick & 3) { case 0: ms0 = 10.f; break; case 1: ms1 = 10.f; break;
                                case 2: ms2 = 10.f; break; default: ms3 = 10.f; }
        }
        __syncthreads();
    }
}

__global__ void gather_lm() {
    int gw = blockIdx.x * 8 + (threadIdx.x >> 5);
    int lane = threadIdx.x & 31;
    int bh = gw >> 7;
    int idx = g_idx[gw];
    ((float2*)(g_s + OLM + (long long)gw * Dd))[lane] =
        ((const float2*)(g_s + OQ + ((long long)bh * Nn + idx) * Dd))[lane];
}

__global__ void softmax196() {
    long long r = (long long)blockIdx.x * 8 + (threadIdx.x >> 5);
    int lane = threadIdx.x & 31;
    float* row = g_s + OK2 + r * PPAD;
    float v[7], mx = -1e30f;
#pragma unroll
    for (int j = 0; j < 7; j++) { int i = lane + 32*j; v[j] = (i < Pp) ? row[i] : -1e30f; mx = fmaxf(mx, v[j]); }
#pragma unroll
    for (int o = 16; o; o >>= 1) mx = fmaxf(mx, __shfl_xor_sync(0xffffffffu, mx, o));
    float s = 0.f;
#pragma unroll
    for (int j = 0; j < 7; j++) { int i = lane + 32*j; if (i < Pp) { v[j] = expf(v[j] - mx); s += v[j]; } }
#pragma unroll
    for (int o = 16; o; o >>= 1) s += __shfl_xor_sync(0xffffffffu, s, o);
    float inv = 1.f / s;
#pragma unroll
    for (int j = 0; j < 7; j++) { int i = lane + 32*j; if (i < Pp) row[i] = v[j] * inv; }
    if (lane < PPAD - Pp) row[Pp + lane] = 0.f;
}

// transpose k-half of Wpkv: WkT[j][c] = Wpkv[c][j]
__global__ void transpose_wk(const float* __restrict__ W) {
    __shared__ float t[32][33];
    int j0 = blockIdx.x * 32, c0 = blockIdx.y * 32;
    int tx = threadIdx.x, ty = threadIdx.y;
#pragma unroll
    for (int i = 0; i < 32; i += 8)
        t[ty + i][tx] = W[(long long)(c0 + ty + i) * (2 * Cc) + j0 + tx];
    __syncthreads();
#pragma unroll
    for (int i = 0; i < 32; i += 8)
        g_s[OWKT + (long long)(j0 + ty + i) * Cc + c0 + tx] = t[tx][ty + i];
}

// fused: logits[n,h,f] = xo[n,f,:]·u[n,h,:]; softmax over f; attn out;
// xo_w[n,h,:] = sum_f w_f xo[n,f,:].  One block per (b,n), 384 thr = 12 warps (h).
__global__ __launch_bounds__(384) void attn2_kernel(float* outAttn) {
    extern __shared__ float xos[];                 // [Ff][Cc] = 49152 B
    __shared__ float lg[Hh][Ff];
    __shared__ float wts[Hh][Ff];
    const int bn = blockIdx.x;                     // b*Nn + n
    const int tid = threadIdx.x, h = tid >> 5, lane = tid & 31;
    const float* xsrc = g_s + OXO + (long long)bn * Ff * Cc;
    for (int i = tid; i < Ff * Cc / 4; i += 384)
        ((float4*)xos)[i] = ((const float4*)xsrc)[i];
    float ureg[24];
    const float* urow = g_s + OU + ((long long)bn * Hh + h) * Cc;
#pragma unroll
    for (int i = 0; i < 24; i++) ureg[i] = urow[lane + 32 * i];
    __syncthreads();
#pragma unroll
    for (int f = 0; f < Ff; f++) {
        const float* xr = xos + f * Cc;
        float p = 0.f;
#pragma unroll
        for (int i = 0; i < 24; i++) p += ureg[i] * xr[lane + 32 * i];
#pragma unroll
        for (int o = 16; o; o >>= 1) p += __shfl_xor_sync(0xffffffffu, p, o);
        if (lane == 0) lg[h][f] = p;
    }
    __syncwarp();
    float mx = -1e30f;
#pragma unroll
    for (int f = 0; f < Ff; f++) mx = fmaxf(mx, lg[h][f]);
    float s = 0.f;
#pragma unroll
    for (int f = 0; f < Ff; f++) s += expf(lg[h][f] - mx);
    float inv = 1.f / s;
    if (lane < Ff) {
        float w = expf(lg[h][lane] - mx) * inv;
        wts[h][lane] = w;
        int b = bn / Nn, n = bn - b * Nn;
        outAttn[(((long long)(b * Hh + h)) * Nn + n) * Ff + lane] = w;
    }
    __syncwarp();
    float* xw = g_s + OXW + ((long long)bn * Hh + h) * Cc;
#pragma unroll
    for (int i = 0; i < 24; i++) {
        float acc = 0.f;
#pragma unroll
        for (int f = 0; f < Ff; f++) acc += wts[h][f] * xos[f * Cc + lane + 32 * i];
        xw[lane + 32 * i] = acc;
    }
}

// ------------------------- launch -------------------------------------------
extern "C" void kernel_launch(void* const* d_in, const int*, int, void* d_out, int) {
    const float* x     = (const float*)d_in[0];
    const float* Wqkv  = (const float*)d_in[1];
    const float* Wpq   = (const float*)d_in[2];
    const float* Wpkv  = (const float*)d_in[3];
    const float* Wproj = (const float*)d_in[4];
    const float* bproj = (const float*)d_in[5];
    float* out = (float*)d_out;

    float* sc = nullptr;
    cudaGetSymbolAddress((void**)&sc, g_s);

    const int fps_smem = Dd * NS * (int)sizeof(float);       // 200704 B
    cudaFuncSetAttribute(fps_kernel4, cudaFuncAttributeMaxDynamicSharedMemorySize, fps_smem);
    const int at2_smem = Ff * Cc * (int)sizeof(float);       // 49152 B
    cudaFuncSetAttribute(attn2_kernel, cudaFuncAttributeMaxDynamicSharedMemorySize, at2_smem);

    // Wk^T: no dependencies — run first
    transpose_wk<<<dim3(24,24),dim3(32,8)>>>(Wpkv);
    // 1) qkv = x @ W_qkv (3xTF32 on q columns only; k,v plain tf32)
    gemm_tf32<128,4,true,EpiQKV><<<dim3(18,49,1),256>>>(
        x, Wqkv, Cc, Cc, 3*Cc, 0, 0, Cc, EpiQKV{});
    norm_kernel<<<9408,256>>>();
    fps_kernel4<<<BH*FB,256,fps_smem>>>();
    gather_lm<<<384,256>>>();
    // kernel_1 logits + fused row softmax
    k1_softmax_kernel<<<dim3(1,49,BH),256>>>();
    gemm_kernel<128,64,16,8,4,true,EpiK2><<<dim3(49,1,BH),256>>>(
        sc+OLM, sc+OKk, Ll, Nn, Dd, Dd, Dd,
        (long long)Ll*Dd,0, (long long)Nn*Dd,0, 1, EpiK2{});
    softmax196<<<6144,256>>>();
    gemm_kernel<128,64,16,8,4,false,EpiX1><<<dim3(1,1,BH*Ff),256>>>(
        sc+OK2, sc+OV, Ll, Dd, PPAD, Ff*PPAD, Dd,
        (long long)Ll*Ff*PPAD, PPAD, (long long)Nn*Dd, (long long)Pp*Dd, Ff, EpiX1{});
    // xo = kernel_1 @ x1  (tf32)
    gemm_tf32<64,4,false,EpiXO><<<dim3(8,49,BH),256>>>(
        sc+OK1, sc+OX1, Ll, Ll, Ff*Dd,
        (long long)Nn*Ll, (long long)Ll*Ff*Dd, 0, EpiXO{});
    // q2 = xdiag @ W_pq  (tf32, scaled)
    gemm_tf32<128,4,false,EpiQ2><<<dim3(6,49,1),256>>>(
        sc+OXD, Wpq, Cc, Cc, Cc, 0, 0, 0, EpiQ2{});
    // u[n,h,:] = Wk_h^T @ q2[n,h,:]  (batched over h, plain tf32)
    gemm_tf32<128,4,false,EpiU><<<dim3(6,49,Hh),256>>>(
        sc+OQ2, sc+OWKT, Dd, Cc, Cc, 64, (long long)64*Cc, 0, EpiU{});
    // fused logits + softmax + attn-out + weighted xo
    attn2_kernel<<<Bb*Nn,384,at2_smem>>>(out + (long long)Bb*Nn*Cc);
    // ao[n,h-block] = xo_w[n,h,:] @ Wv_h  (batched over h, tf32)
    gemm_tf32<128,2,false,EpiAO><<<dim3(1,49,Hh),256>>>(
        sc+OXW, Wpkv + Cc, Cc, Hh*Cc, 2*Cc, Cc, 64, 0, EpiAO{});
    // out = ao @ W_proj + b  (tf32)
    gemm_tf32<128,4,false,EpiOut><<<dim3(6,49,1),256>>>(
        sc+OAO, Wproj, Cc, Cc, Cc, 0, 0, 0, EpiOut{out, bproj});
}

// round 12
// speedup vs baseline: 1.1108x; 1.1108x over previous
#include <cuda_runtime.h>

#define PRNG_VARIANT 0  // 0 = threefry_partitionable (modern JAX default), 1 = legacy

namespace ta {
constexpr int Bb=2, Hh=12, BH=24, Ff=16, Pp=196, Nn=3136, Cc=768, Dd=64, Ll=128, PPAD=208;
constexpr int FB=4, NS=Nn/FB, NC4=NS/4;
constexpr long long QS = (long long)BH*Nn*Dd;
constexpr long long OQ=0, OKk=OQ+QS, OV=OKk+QS, OQKN=OV+QS, OLM=OQKN+QS;
constexpr long long OK1=OLM+(long long)BH*Ll*Dd;
constexpr long long OK2=OK1+(long long)BH*Nn*Ll;
constexpr long long OX1=OK2+(long long)BH*Ll*Ff*PPAD;
constexpr long long OXO=OX1+(long long)BH*Ll*Ff*Dd;
constexpr long long OXD=OXO+(long long)Bb*Nn*Ff*Cc;
constexpr long long OQ2=OXD+(long long)Bb*Nn*Cc;
constexpr long long OU =OQ2+(long long)Bb*Nn*Cc;                 // u[n,h,c]
constexpr long long OXW=OU +(long long)Bb*Nn*Hh*Cc;              // xo_w[n,h,c]
constexpr long long OWKT=OXW+(long long)Bb*Nn*Hh*Cc;             // Wk^T 768x768
constexpr long long OAO=OWKT+(long long)Cc*Cc;
constexpr long long TOT=OAO+(long long)Bb*Nn*Cc;
}
__device__ float g_s[ta::TOT];
__device__ int   g_idx[ta::BH*ta::Ll];

using namespace ta;

// ------------------------- threefry2x32 (general key) -----------------------
__device__ __forceinline__ void tf(unsigned k0, unsigned k1, unsigned x0, unsigned x1,
                                   unsigned &y0, unsigned &y1) {
    const unsigned k2 = 0x1BD11BDAu ^ k0 ^ k1;
    x0 += k0; x1 += k1;
#define TFR(r) { x0 += x1; x1 = (x1<<(r))|(x1>>(32-(r))); x1 ^= x0; }
    TFR(13) TFR(15) TFR(26) TFR(6)   x0 += k1; x1 += k2 + 1u;
    TFR(17) TFR(29) TFR(16) TFR(24)  x0 += k2; x1 += k0 + 2u;
    TFR(13) TFR(15) TFR(26) TFR(6)   x0 += k0; x1 += k1 + 3u;
    TFR(17) TFR(29) TFR(16) TFR(24)  x0 += k1; x1 += k2 + 4u;
    TFR(13) TFR(15) TFR(26) TFR(6)   x0 += k2; x1 += k0 + 5u;
#undef TFR
    y0 = x0; y1 = x1;
}

__device__ int jax_idx0(int i) {
    const unsigned span = (unsigned)Nn;
    const unsigned mult = 2048u;
    unsigned hi, lo;
#if PRNG_VARIANT == 0
    unsigned a0,a1,b0,b1,y0,y1;
    tf(0u,42u, 0u,0u, a0,a1);
    tf(0u,42u, 0u,1u, b0,b1);
    tf(a0,a1, 0u,(unsigned)i, y0,y1); hi = y0 ^ y1;
    tf(b0,b1, 0u,(unsigned)i, y0,y1); lo = y0 ^ y1;
#else
    unsigned s00,s01,s10,s11,y0,y1;
    tf(0u,42u, 0u,2u, s00,s01);
    tf(0u,42u, 1u,3u, s10,s11);
    unsigned k1a=s00, k1b=s10, k2a=s01, k2b=s11;
    if (i < 12) { tf(k1a,k1b,(unsigned)i,(unsigned)(i+12),y0,y1); hi = y0; }
    else        { tf(k1a,k1b,(unsigned)(i-12),(unsigned)i,y0,y1); hi = y1; }
    if (i < 12) { tf(k2a,k2b,(unsigned)i,(unsigned)(i+12),y0,y1); lo = y0; }
    else        { tf(k2a,k2b,(unsigned)(i-12),(unsigned)i,y0,y1); lo = y1; }
#endif
    return (int)((((hi % span) * mult) + (lo % span)) % span);
}

// ------------------------- generic tiled f32 SIMT GEMM ----------------------
template <int BM, int BN, int BK, int TM, int TN, bool NT, class Epi>
__global__ __launch_bounds__(256) void gemm_kernel(
    const float* __restrict__ A, const float* __restrict__ B,
    int M, int N, int K, int lda, int ldb,
    long long sA1, long long sA2, long long sB1, long long sB2, int zdiv, Epi epi)
{
    __shared__ float As[BK][BM];
    __shared__ float Bs[BK][BN];
    const int z = blockIdx.z, za = z / zdiv, zb = z % zdiv;
    A += za * sA1 + zb * sA2;
    B += za * sB1 + zb * sB2;
    const int m0 = blockIdx.y * BM, n0 = blockIdx.x * BN;
    const int tid = threadIdx.x;
    const int tx = tid % (BN / TN), ty = tid / (BN / TN);
    float acc[TM][TN];
#pragma unroll
    for (int i = 0; i < TM; i++)
#pragma unroll
        for (int j = 0; j < TN; j++) acc[i][j] = 0.f;

    for (int k0 = 0; k0 < K; k0 += BK) {
        for (int i = tid; i < BM * BK / 4; i += 256) {
            int m = i / (BK / 4), kq = i % (BK / 4);
            float4 v = *(const float4*)(A + (long long)(m0 + m) * lda + k0 + kq * 4);
            As[kq*4+0][m] = v.x; As[kq*4+1][m] = v.y; As[kq*4+2][m] = v.z; As[kq*4+3][m] = v.w;
        }
        if (!NT) {
            for (int i = tid; i < BK * BN / 4; i += 256) {
                int kk = i / (BN / 4), nq = i % (BN / 4);
                *(float4*)&Bs[kk][nq*4] = *(const float4*)(B + (long long)(k0 + kk) * ldb + n0 + nq * 4);
            }
        } else {
            for (int i = tid; i < BN * BK / 4; i += 256) {
                int n = i / (BK / 4), kq = i % (BK / 4);
                float4 v = *(const float4*)(B + (long long)(n0 + n) * ldb + k0 + kq * 4);
                Bs[kq*4+0][n] = v.x; Bs[kq*4+1][n] = v.y; Bs[kq*4+2][n] = v.z; Bs[kq*4+3][n] = v.w;
            }
        }
        __syncthreads();
#pragma unroll
        for (int kk = 0; kk < BK; kk++) {
            float a[TM], b[TN];
#pragma unroll
            for (int i = 0; i < TM; i++) a[i] = As[kk][ty * TM + i];
#pragma unroll
            for (int j = 0; j < TN; j++) b[j] = Bs[kk][tx * TN + j];
#pragma unroll
            for (int i = 0; i < TM; i++)
#pragma unroll
                for (int j = 0; j < TN; j++) acc[i][j] += a[i] * b[j];
        }
        __syncthreads();
    }
#pragma unroll
    for (int i = 0; i < TM; i++)
#pragma unroll
        for (int j = 0; j < TN; j++)
            epi(z, m0 + ty * TM + i, n0 + tx * TN + j, acc[i][j]);
}

// ------------------------- tf32 tensor-core GEMM (cp.async 3-stage) ---------
__device__ __forceinline__ float to_tf32(float x) {
    float r; asm("cvt.rna.tf32.f32 %0, %1;" : "=f"(r) : "f"(x)); return r;
}
__device__ __forceinline__ void mma_tf32(float (&d)[4], const float (&a)[4], const float (&b)[2]) {
    asm volatile("mma.sync.aligned.m16n8k8.row.col.f32.tf32.tf32.f32 "
        "{%0,%1,%2,%3}, {%4,%5,%6,%7}, {%8,%9}, {%0,%1,%2,%3};"
        : "+f"(d[0]), "+f"(d[1]), "+f"(d[2]), "+f"(d[3])
        : "r"(__float_as_uint(a[0])), "r"(__float_as_uint(a[1])),
          "r"(__float_as_uint(a[2])), "r"(__float_as_uint(a[3])),
          "r"(__float_as_uint(b[0])), "r"(__float_as_uint(b[1])));
}
__device__ __forceinline__ void cpa16(float* dst, const float* src) {
    unsigned s = (unsigned)__cvta_generic_to_shared(dst);
    asm volatile("cp.async.cg.shared.global [%0], [%1], 16;" :: "r"(s), "l"(src));
}

// BM x (WN*32) x 16 tiles, 8 warps ((8/WN) m-rows x WN n-cols), 3-stage cp.async.
template <int BM, int WN, bool X3, class Epi>
__global__ __launch_bounds__(256) void gemm_tf32(
    const float* __restrict__ A, const float* __restrict__ B,
    int K, int lda, int ldb, long long sA1, long long sB1, Epi epi)
{
    constexpr int BN = WN * 32, BK = 16;
    constexpr int LDA_S = BK + 4;
    constexpr int LDB_S = BN + 8;
    constexpr int MF = (BM * WN) / 128;   // m16 frags per warp
    __shared__ float As[3][BM * LDA_S];
    __shared__ float Bs[3][BK * LDB_S];
    const int z = blockIdx.z;
    const int m0 = blockIdx.y * BM, n0 = blockIdx.x * BN;
    const float* Ab = A + (long long)z * sA1 + (long long)m0 * lda;
    const float* Bb = B + (long long)z * sB1 + n0;
    const int tid = threadIdx.x, wid = tid >> 5, lane = tid & 31;
    const int wm = (wid / WN) * (16 * MF), wn = (wid % WN) * 32;
    const int g = lane >> 2, t = lane & 3;

    float acc[MF][4][4];
#pragma unroll
    for (int i = 0; i < MF; i++)
#pragma unroll
        for (int j = 0; j < 4; j++)
#pragma unroll
            for (int r = 0; r < 4; r++) acc[i][j][r] = 0.f;

    auto stage_load = [&](int s, int k0) {
#pragma unroll
        for (int i = tid; i < BM * 4; i += 256) {
            int m = i >> 2, kq = i & 3;
            cpa16(&As[s][m * LDA_S + kq * 4], Ab + (long long)m * lda + k0 + kq * 4);
        }
#pragma unroll
        for (int i = tid; i < BK * (BN / 4); i += 256) {
            int kk = i / (BN / 4), nq = i % (BN / 4);
            cpa16(&Bs[s][kk * LDB_S + nq * 4], Bb + (long long)(k0 + kk) * ldb + nq * 4);
        }
        asm volatile("cp.async.commit_group;");
    };

    const int KT = K / BK;
    stage_load(0, 0);
    if (KT > 1) stage_load(1, BK);
    for (int kt = 0; kt < KT; kt++) {
        const int s = kt % 3;
        if (kt + 2 < KT) {
            stage_load((kt + 2) % 3, (kt + 2) * BK);
            asm volatile("cp.async.wait_group 2;");
        } else if (kt + 1 < KT) {
            asm volatile("cp.async.wait_group 1;");
        } else {
            asm volatile("cp.async.wait_group 0;");
        }
        __syncthreads();
#pragma unroll
        for (int ks = 0; ks < 2; ks++) {
            const int kb = ks * 8;
            float a[MF][4], b[4][2];
            float al[MF][4], bl[4][2];
#pragma unroll
            for (int mf = 0; mf < MF; mf++) {
                int ml = wm + mf * 16 + g;
                float r0 = As[s][ ml      * LDA_S + kb + t];
                float r1 = As[s][(ml + 8) * LDA_S + kb + t];
                float r2 = As[s][ ml      * LDA_S + kb + t + 4];
                float r3 = As[s][(ml + 8) * LDA_S + kb + t + 4];
                a[mf][0] = to_tf32(r0); a[mf][1] = to_tf32(r1);
                a[mf][2] = to_tf32(r2); a[mf][3] = to_tf32(r3);
                if (X3) {
                    al[mf][0] = to_tf32(r0 - a[mf][0]); al[mf][1] = to_tf32(r1 - a[mf][1]);
                    al[mf][2] = to_tf32(r2 - a[mf][2]); al[mf][3] = to_tf32(r3 - a[mf][3]);
                }
            }
#pragma unroll
            for (int nf = 0; nf < 4; nf++) {
                int nb = wn + nf * 8 + g;
                float r0 = Bs[s][(kb + t)     * LDB_S + nb];
                float r1 = Bs[s][(kb + t + 4) * LDB_S + nb];
                b[nf][0] = to_tf32(r0); b[nf][1] = to_tf32(r1);
                if (X3) {
                    bl[nf][0] = to_tf32(r0 - b[nf][0]); bl[nf][1] = to_tf32(r1 - b[nf][1]);
                }
            }
#pragma unroll
            for (int mf = 0; mf < MF; mf++)
#pragma unroll
                for (int nf = 0; nf < 4; nf++) {
                    mma_tf32(acc[mf][nf], a[mf], b[nf]);
                    if (X3) {
                        mma_tf32(acc[mf][nf], al[mf], b[nf]);
                        mma_tf32(acc[mf][nf], a[mf], bl[nf]);
                    }
                }
        }
        __syncthreads();
    }
#pragma unroll
    for (int mf = 0; mf < MF; mf++) {
        int m = m0 + wm + mf * 16 + g;
#pragma unroll
        for (int nf = 0; nf < 4; nf++) {
            int n = n0 + wn + nf * 8 + 2 * t;
            epi(z, m,     n,     acc[mf][nf][0]);
            epi(z, m,     n + 1, acc[mf][nf][1]);
            epi(z, m + 8, n,     acc[mf][nf][2]);
            epi(z, m + 8, n + 1, acc[mf][nf][3]);
        }
    }
}

// ------------------------- epilogues ----------------------------------------
struct EpiQKV {
    __device__ void operator()(int, int m, int n, float v) const {
        int part = n / Cc, c = n - part * Cc;
        int hh = c >> 6, dd = c & 63;
        int b = m / Nn, nn = m - b * Nn;
        long long idx = (((long long)(b * Hh + hh)) * Nn + nn) * Dd + dd;
        const float sc = 0.35355339059327378f;
        if (part == 0)      g_s[OQ  + idx] = v * sc;
        else if (part == 1) g_s[OKk + idx] = v * sc;
        else                g_s[OV  + idx] = v;
    }
};
struct EpiK1 {
    __device__ void operator()(int z, int m, int n, float v) const {
        g_s[OK1 + ((long long)z * Nn + m) * Ll + n] = v;
    }
};
struct EpiK2 {
    __device__ void operator()(int z, int m, int n, float v) const {
        int f = n / Pp, p = n - f * Pp;
        g_s[OK2 + (((long long)z * Ll + m) * Ff + f) * PPAD + p] = v;
    }
};
struct EpiX1 {
    __device__ void operator()(int z, int m, int n, float v) const {
        int bh = z >> 4, f = z & 15;
        g_s[OX1 + (((long long)bh * Ll + m) * Ff + f) * Dd + n] = v;
    }
};
struct EpiXO {
    __device__ void operator()(int z, int m, int n, float v) const {
        int b = z / Hh, hh = z - b * Hh;
        int f = n >> 6, dd = n & 63;
        long long base = (long long)(b * Nn + m);
        g_s[OXO + (base * Ff + f) * Cc + hh * Dd + dd] = v;
        if (f == m / Pp) g_s[OXD + base * Cc + hh * Dd + dd] = v;
    }
};
struct EpiQ2 {
    __device__ void operator()(int, int m, int n, float v) const {
        g_s[OQ2 + (long long)m * Cc + n] = v * 0.125f;
    }
};
struct EpiU {     // u[n,h,c]; z = h
    __device__ void operator()(int z, int m, int n, float v) const {
        g_s[OU + ((long long)m * Hh + z) * Cc + n] = v;
    }
};
struct EpiAO {    // ao[m][z*64 + n]; z = h
    __device__ void operator()(int z, int m, int n, float v) const {
        g_s[OAO + (long long)m * Cc + z * 64 + n] = v;
    }
};
struct EpiOut {
    float* out; const float* bias;
    __device__ void operator()(int, int m, int n, float v) const {
        out[(long long)m * Cc + n] = v + bias[n];
    }
};

// ------------------------- small kernels ------------------------------------
__global__ void norm_kernel() {
    long long gw = (long long)blockIdx.x * 8 + (threadIdx.x >> 5);
    int lane = threadIdx.x & 31;
    float2 v = ((const float2*)(g_s + OQ + gw * Dd))[lane];
    float ss = v.x * v.x + v.y * v.y;
#pragma unroll
    for (int o = 16; o; o >>= 1) ss += __shfl_xor_sync(0xffffffffu, ss, o);
    float dnm = fmaxf(sqrtf(ss), 1e-12f);
    int bh = (int)(gw / Nn), n = (int)(gw - (long long)bh * Nn);
    long long base = OQKN + (long long)bh * Nn * Dd;
    g_s[base + (long long)(2 * lane)     * Nn + n] = v.x / dnm;
    g_s[base + (long long)(2 * lane + 1) * Nn + n] = v.y / dnm;
}

__device__ __forceinline__ unsigned ctarank() {
    unsigned r; asm("mov.u32 %0, %%cluster_ctarank;" : "=r"(r)); return r;
}
__device__ __forceinline__ unsigned mapa_u32(unsigned addr, unsigned rank) {
    unsigned r; asm("mapa.shared::cluster.u32 %0, %1, %2;" : "=r"(r) : "r"(addr), "r"(rank));
    return r;
}

__global__ __launch_bounds__(256) __cluster_dims__(FB, 1, 1) void fps_kernel4() {
    extern __shared__ float ssm[];                            // [Dd][NS]
    __shared__ unsigned long long cand[2][FB];
    __shared__ float cur[Dd];
    __shared__ float s_val[8];
    __shared__ int   s_idx[8], s_pick;
    const int b = blockIdx.x / FB;
    const int j = (int)ctarank();
    const int tid = threadIdx.x;
    const float* qkT = g_s + OQKN + (long long)b * Nn * Dd;
    for (int i = tid; i < Dd * NC4; i += 256) {
        int d = i / NC4, c = i % NC4;
        *(float4*)&ssm[d * NS + 4 * c] =
            *(const float4*)(qkT + (long long)d * Nn + j * NS + 4 * c);
    }
    float ms0 = 0.f, ms1 = 0.f, ms2 = 0.f, ms3 = 0.f;
    if (tid == 0) {
        int i0 = jax_idx0(b);
        if (j == 0) g_idx[b * Ll] = i0;
        s_pick = i0;
    }
    __syncthreads();
    int pick = s_pick;
    if (tid < Dd) cur[tid] = qkT[(long long)tid * Nn + pick];
    if (tid < NC4 && tid == (pick >> 2) - j * NC4) {
        switch (pick & 3) { case 0: ms0 = 10.f; break; case 1: ms1 = 10.f; break;
                            case 2: ms2 = 10.f; break; default: ms3 = 10.f; }
    }
    __syncthreads();
    const int lane = tid & 31, wid = tid >> 5;
    const unsigned candBase = (unsigned)__cvta_generic_to_shared(&cand[0][0]);
    for (int step = 1; step < Ll; step++) {
        float bv = 3.4e38f; int bi = 0x7fffffff;
        if (tid < NC4) {
            float ax = 0.f, ay = 0.f, az = 0.f, aw = 0.f;
#pragma unroll
            for (int d = 0; d < Dd; d++) {
                float4 v = *(const float4*)&ssm[d * NS + 4 * tid];
                float c = cur[d];
                ax += v.x * c; ay += v.y * c; az += v.z * c; aw += v.w * c;
            }
            ms0 = fmaxf(ms0, fabsf(ax)); ms1 = fmaxf(ms1, fabsf(ay));
            ms2 = fmaxf(ms2, fabsf(az)); ms3 = fmaxf(ms3, fabsf(aw));
            int nb = j * NS + 4 * tid;
            bv = ms0; bi = nb;
            if (ms1 < bv) { bv = ms1; bi = nb + 1; }
            if (ms2 < bv) { bv = ms2; bi = nb + 2; }
            if (ms3 < bv) { bv = ms3; bi = nb + 3; }
        }
#pragma unroll
        for (int o = 16; o; o >>= 1) {
            float ov = __shfl_down_sync(0xffffffffu, bv, o);
            int   oi = __shfl_down_sync(0xffffffffu, bi, o);
            if (ov < bv || (ov == bv && oi < bi)) { bv = ov; bi = oi; }
        }
        if (lane == 0) { s_val[wid] = bv; s_idx[wid] = bi; }
        __syncthreads();
        const int par = step & 1;
        if (tid == 0) {
#pragma unroll
            for (int w = 0; w < 8; w++) {
                float ov = s_val[w]; int oi = s_idx[w];
                if (w == 0 || ov < bv || (ov == bv && oi < bi)) { bv = ov; bi = oi; }
            }
            unsigned long long packed =
                ((unsigned long long)__float_as_uint(bv) << 32) | (unsigned)bi;
            unsigned slot = candBase + (unsigned)((par * FB + j) * 8);
#pragma unroll
            for (int jj = 0; jj < FB; jj++) {
                unsigned raddr = mapa_u32(slot, (unsigned)jj);
                asm volatile("st.shared::cluster.b64 [%0], %1;" :: "r"(raddr), "l"(packed));
            }
        }
        asm volatile("barrier.cluster.arrive.aligned;" ::: "memory");
        asm volatile("barrier.cluster.wait.aligned;" ::: "memory");
        unsigned long long best = cand[par][0];
#pragma unroll
        for (int jj = 1; jj < FB; jj++) {
            unsigned long long c2 = cand[par][jj];
            if (c2 < best) best = c2;
        }
        pick = (int)(unsigned)(best & 0xffffffffull);
        if (j == 0 && tid == 0) g_idx[b * Ll + step] = pick;
        if (tid < Dd) cur[tid] = qkT[(long long)tid * Nn + pick];
        if (tid < NC4 && tid == (pick >> 2) - j * NC4) {
            switch (pick & 3) { case 0: ms0 = 10.f; break; case 1: ms1 = 10.f; break;
                                case 2: ms2 = 10.f; break; default: ms3 = 10.f; }
        }
        __syncthreads();
    }
}

__global__ void gather_lm() {
    int gw = blockIdx.x * 8 + (threadIdx.x >> 5);
    int lane = threadIdx.x & 31;
    int bh = gw >> 7;
    int idx = g_idx[gw];
    ((float2*)(g_s + OLM + (long long)gw * Dd))[lane] =
        ((const float2*)(g_s + OQ + ((long long)bh * Nn + idx) * Dd))[lane];
}

__global__ void softmax128() {
    long long r = (long long)blockIdx.x * 8 + (threadIdx.x >> 5);
    int lane = threadIdx.x & 31;
    float4* row = (float4*)(g_s + OK1 + r * Ll);
    float4 v = row[lane];
    float mx = fmaxf(fmaxf(v.x, v.y), fmaxf(v.z, v.w));
#pragma unroll
    for (int o = 16; o; o >>= 1) mx = fmaxf(mx, __shfl_xor_sync(0xffffffffu, mx, o));
    v.x = expf(v.x - mx); v.y = expf(v.y - mx); v.z = expf(v.z - mx); v.w = expf(v.w - mx);
    float s = v.x + v.y + v.z + v.w;
#pragma unroll
    for (int o = 16; o; o >>= 1) s += __shfl_xor_sync(0xffffffffu, s, o);
    float inv = 1.f / s;
    v.x *= inv; v.y *= inv; v.z *= inv; v.w *= inv;
    row[lane] = v;
}

__global__ void softmax196() {
    long long r = (long long)blockIdx.x * 8 + (threadIdx.x >> 5);
    int lane = threadIdx.x & 31;
    float* row = g_s + OK2 + r * PPAD;
    float v[7], mx = -1e30f;
#pragma unroll
    for (int j = 0; j < 7; j++) { int i = lane + 32*j; v[j] = (i < Pp) ? row[i] : -1e30f; mx = fmaxf(mx, v[j]); }
#pragma unroll
    for (int o = 16; o; o >>= 1) mx = fmaxf(mx, __shfl_xor_sync(0xffffffffu, mx, o));
    float s = 0.f;
#pragma unroll
    for (int j = 0; j < 7; j++) { int i = lane + 32*j; if (i < Pp) { v[j] = expf(v[j] - mx); s += v[j]; } }
#pragma unroll
    for (int o = 16; o; o >>= 1) s += __shfl_xor_sync(0xffffffffu, s, o);
    float inv = 1.f / s;
#pragma unroll
    for (int j = 0; j < 7; j++) { int i = lane + 32*j; if (i < Pp) row[i] = v[j] * inv; }
    if (lane < PPAD - Pp) row[Pp + lane] = 0.f;
}

// transpose k-half of Wpkv: WkT[j][c] = Wpkv[c][j]
__global__ void transpose_wk(const float* __restrict__ W) {
    __shared__ float t[32][33];
    int j0 = blockIdx.x * 32, c0 = blockIdx.y * 32;
    int tx = threadIdx.x, ty = threadIdx.y;
#pragma unroll
    for (int i = 0; i < 32; i += 8)
        t[ty + i][tx] = W[(long long)(c0 + ty + i) * (2 * Cc) + j0 + tx];
    __syncthreads();
#pragma unroll
    for (int i = 0; i < 32; i += 8)
        g_s[OWKT + (long long)(j0 + ty + i) * Cc + c0 + tx] = t[tx][ty + i];
}

// fused: logits[n,h,f] = xo[n,f,:]·u[n,h,:]; softmax over f; attn out;
// xo_w[n,h,:] = sum_f w_f xo[n,f,:].  One block per (b,n), 384 thr = 12 warps (h).
__global__ __launch_bounds__(384) void attn2_kernel(float* outAttn) {
    extern __shared__ float xos[];                 // [Ff][Cc] = 49152 B
    __shared__ float lg[Hh][Ff];
    __shared__ float wts[Hh][Ff];
    const int bn = blockIdx.x;                     // b*Nn + n
    const int tid = threadIdx.x, h = tid >> 5, lane = tid & 31;
    const float* xsrc = g_s + OXO + (long long)bn * Ff * Cc;
    for (int i = tid; i < Ff * Cc / 4; i += 384)
        ((float4*)xos)[i] = ((const float4*)xsrc)[i];
    float ureg[24];
    const float* urow = g_s + OU + ((long long)bn * Hh + h) * Cc;
#pragma unroll
    for (int i = 0; i < 24; i++) ureg[i] = urow[lane + 32 * i];
    __syncthreads();
#pragma unroll
    for (int f = 0; f < Ff; f++) {
        const float* xr = xos + f * Cc;
        float p = 0.f;
#pragma unroll
        for (int i = 0; i < 24; i++) p += ureg[i] * xr[lane + 32 * i];
#pragma unroll
        for (int o = 16; o; o >>= 1) p += __shfl_xor_sync(0xffffffffu, p, o);
        if (lane == 0) lg[h][f] = p;
    }
    __syncwarp();
    float mx = -1e30f;
#pragma unroll
    for (int f = 0; f < Ff; f++) mx = fmaxf(mx, lg[h][f]);
    float s = 0.f;
#pragma unroll
    for (int f = 0; f < Ff; f++) s += expf(lg[h][f] - mx);
    float inv = 1.f / s;
    if (lane < Ff) {
        float w = expf(lg[h][lane] - mx) * inv;
        wts[h][lane] = w;
        int b = bn / Nn, n = bn - b * Nn;
        outAttn[(((long long)(b * Hh + h)) * Nn + n) * Ff + lane] = w;
    }
    __syncwarp();
    float* xw = g_s + OXW + ((long long)bn * Hh + h) * Cc;
#pragma unroll
    for (int i = 0; i < 24; i++) {
        float acc = 0.f;
#pragma unroll
        for (int f = 0; f < Ff; f++) acc += wts[h][f] * xos[f * Cc + lane + 32 * i];
        xw[lane + 32 * i] = acc;
    }
}

// ------------------------- launch -------------------------------------------
extern "C" void kernel_launch(void* const* d_in, const int*, int, void* d_out, int) {
    const float* x     = (const float*)d_in[0];
    const float* Wqkv  = (const float*)d_in[1];
    const float* Wpq   = (const float*)d_in[2];
    const float* Wpkv  = (const float*)d_in[3];
    const float* Wproj = (const float*)d_in[4];
    const float* bproj = (const float*)d_in[5];
    float* out = (float*)d_out;

    float* sc = nullptr;
    cudaGetSymbolAddress((void**)&sc, g_s);

    const int fps_smem = Dd * NS * (int)sizeof(float);       // 200704 B
    cudaFuncSetAttribute(fps_kernel4, cudaFuncAttributeMaxDynamicSharedMemorySize, fps_smem);
    const int at2_smem = Ff * Cc * (int)sizeof(float);       // 49152 B
    cudaFuncSetAttribute(attn2_kernel, cudaFuncAttributeMaxDynamicSharedMemorySize, at2_smem);

    // 1) qkv = x @ W_qkv (3xTF32)
    gemm_tf32<128,4,true,EpiQKV><<<dim3(18,49,1),256>>>(
        x, Wqkv, Cc, Cc, 3*Cc, 0, 0, EpiQKV{});
    norm_kernel<<<9408,256>>>();
    fps_kernel4<<<BH*FB,256,fps_smem>>>();
    gather_lm<<<384,256>>>();
    gemm_kernel<64,128,16,4,8,true,EpiK1><<<dim3(1,49,BH),256>>>(
        sc+OQ, sc+OLM, Nn, Ll, Dd, Dd, Dd,
        (long long)Nn*Dd,0, (long long)Ll*Dd,0, 1, EpiK1{});
    softmax128<<<9408,256>>>();
    gemm_kernel<128,64,16,8,4,true,EpiK2><<<dim3(49,1,BH),256>>>(
        sc+OLM, sc+OKk, Ll, Nn, Dd, Dd, Dd,
        (long long)Ll*Dd,0, (long long)Nn*Dd,0, 1, EpiK2{});
    softmax196<<<6144,256>>>();
    gemm_kernel<128,64,16,8,4,false,EpiX1><<<dim3(1,1,BH*Ff),256>>>(
        sc+OK2, sc+OV, Ll, Dd, PPAD, Ff*PPAD, Dd,
        (long long)Ll*Ff*PPAD, PPAD, (long long)Nn*Dd, (long long)Pp*Dd, Ff, EpiX1{});
    // xo = kernel_1 @ x1  (tf32)
    gemm_tf32<64,4,false,EpiXO><<<dim3(8,49,BH),256>>>(
        sc+OK1, sc+OX1, Ll, Ll, Ff*Dd,
        (long long)Nn*Ll, (long long)Ll*Ff*Dd, EpiXO{});
    // q2 = xdiag @ W_pq  (tf32, scaled)
    gemm_tf32<128,4,false,EpiQ2><<<dim3(6,49,1),256>>>(
        sc+OXD, Wpq, Cc, Cc, Cc, 0, 0, EpiQ2{});
    // Wk^T for the U GEMM
    transpose_wk<<<dim3(24,24),dim3(32,8)>>>(Wpkv);
    // u[n,h,:] = Wk_h^T @ q2[n,h,:]  (batched over h, plain tf32 — the ONE change vs round 9)
    gemm_tf32<128,4,false,EpiU><<<dim3(6,49,Hh),256>>>(
        sc+OQ2, sc+OWKT, Dd, Cc, Cc, 64, (long long)64*Cc, EpiU{});
    // fused logits + softmax + attn-out + weighted xo
    attn2_kernel<<<Bb*Nn,384,at2_smem>>>(out + (long long)Bb*Nn*Cc);
    // ao[n,h-block] = xo_w[n,h,:] @ Wv_h  (batched over h, tf32)
    gemm_tf32<128,2,false,EpiAO><<<dim3(1,49,Hh),256>>>(
        sc+OXW, Wpkv + Cc, Cc, Hh*Cc, 2*Cc, Cc, 64, EpiAO{});
    // out = ao @ W_proj + b  (tf32)
    gemm_tf32<128,4,false,EpiOut><<<dim3(6,49,1),256>>>(
        sc+OAO, Wproj, Cc, Cc, Cc, 0, 0, EpiOut{out, bproj});
}

// round 13
// speedup vs baseline: 1.1262x; 1.0139x over previous
#include <cuda_runtime.h>

#define PRNG_VARIANT 0  // 0 = threefry_partitionable (modern JAX default), 1 = legacy

namespace ta {
constexpr int Bb=2, Hh=12, BH=24, Ff=16, Pp=196, Nn=3136, Cc=768, Dd=64, Ll=128, PPAD=208;
constexpr int FB=8, NS=Nn/FB, NC2=NS/2, NCF=NS/4;   // FPS: 8 blocks/bh, 392 cols, 196 f2, 98 f4
constexpr long long QS = (long long)BH*Nn*Dd;
constexpr long long OQ=0, OKk=OQ+QS, OV=OKk+QS, OQKN=OV+QS, OLM=OQKN+QS;
constexpr long long OK1=OLM+(long long)BH*Ll*Dd;
constexpr long long OK2=OK1+(long long)BH*Nn*Ll;
constexpr long long OX1=OK2+(long long)BH*Ll*Ff*PPAD;
constexpr long long OXO=OX1+(long long)BH*Ll*Ff*Dd;
constexpr long long OXD=OXO+(long long)Bb*Nn*Ff*Cc;
constexpr long long OQ2=OXD+(long long)Bb*Nn*Cc;
constexpr long long OU =OQ2+(long long)Bb*Nn*Cc;                 // u[n,h,c]
constexpr long long OXW=OU +(long long)Bb*Nn*Hh*Cc;              // xo_w[n,h,c]
constexpr long long OWKT=OXW+(long long)Bb*Nn*Hh*Cc;             // Wk^T 768x768
constexpr long long OAO=OWKT+(long long)Cc*Cc;
constexpr long long TOT=OAO+(long long)Bb*Nn*Cc;
}
__device__ float g_s[ta::TOT];
__device__ int   g_idx[ta::BH*ta::Ll];

using namespace ta;

// ------------------------- threefry2x32 (general key) -----------------------
__device__ __forceinline__ void tf(unsigned k0, unsigned k1, unsigned x0, unsigned x1,
                                   unsigned &y0, unsigned &y1) {
    const unsigned k2 = 0x1BD11BDAu ^ k0 ^ k1;
    x0 += k0; x1 += k1;
#define TFR(r) { x0 += x1; x1 = (x1<<(r))|(x1>>(32-(r))); x1 ^= x0; }
    TFR(13) TFR(15) TFR(26) TFR(6)   x0 += k1; x1 += k2 + 1u;
    TFR(17) TFR(29) TFR(16) TFR(24)  x0 += k2; x1 += k0 + 2u;
    TFR(13) TFR(15) TFR(26) TFR(6)   x0 += k0; x1 += k1 + 3u;
    TFR(17) TFR(29) TFR(16) TFR(24)  x0 += k1; x1 += k2 + 4u;
    TFR(13) TFR(15) TFR(26) TFR(6)   x0 += k2; x1 += k0 + 5u;
#undef TFR
    y0 = x0; y1 = x1;
}

__device__ int jax_idx0(int i) {
    const unsigned span = (unsigned)Nn;
    const unsigned mult = 2048u;
    unsigned hi, lo;
#if PRNG_VARIANT == 0
    unsigned a0,a1,b0,b1,y0,y1;
    tf(0u,42u, 0u,0u, a0,a1);
    tf(0u,42u, 0u,1u, b0,b1);
    tf(a0,a1, 0u,(unsigned)i, y0,y1); hi = y0 ^ y1;
    tf(b0,b1, 0u,(unsigned)i, y0,y1); lo = y0 ^ y1;
#else
    unsigned s00,s01,s10,s11,y0,y1;
    tf(0u,42u, 0u,2u, s00,s01);
    tf(0u,42u, 1u,3u, s10,s11);
    unsigned k1a=s00, k1b=s10, k2a=s01, k2b=s11;
    if (i < 12) { tf(k1a,k1b,(unsigned)i,(unsigned)(i+12),y0,y1); hi = y0; }
    else        { tf(k1a,k1b,(unsigned)(i-12),(unsigned)i,y0,y1); hi = y1; }
    if (i < 12) { tf(k2a,k2b,(unsigned)i,(unsigned)(i+12),y0,y1); lo = y0; }
    else        { tf(k2a,k2b,(unsigned)(i-12),(unsigned)i,y0,y1); lo = y1; }
#endif
    return (int)((((hi % span) * mult) + (lo % span)) % span);
}

// ------------------------- generic tiled f32 SIMT GEMM ----------------------
template <int BM, int BN, int BK, int TM, int TN, bool NT, class Epi>
__global__ __launch_bounds__(256) void gemm_kernel(
    const float* __restrict__ A, const float* __restrict__ B,
    int M, int N, int K, int lda, int ldb,
    long long sA1, long long sA2, long long sB1, long long sB2, int zdiv, Epi epi)
{
    __shared__ float As[BK][BM];
    __shared__ float Bs[BK][BN];
    const int z = blockIdx.z, za = z / zdiv, zb = z % zdiv;
    A += za * sA1 + zb * sA2;
    B += za * sB1 + zb * sB2;
    const int m0 = blockIdx.y * BM, n0 = blockIdx.x * BN;
    const int tid = threadIdx.x;
    const int tx = tid % (BN / TN), ty = tid / (BN / TN);
    float acc[TM][TN];
#pragma unroll
    for (int i = 0; i < TM; i++)
#pragma unroll
        for (int j = 0; j < TN; j++) acc[i][j] = 0.f;

    for (int k0 = 0; k0 < K; k0 += BK) {
        for (int i = tid; i < BM * BK / 4; i += 256) {
            int m = i / (BK / 4), kq = i % (BK / 4);
            float4 v = *(const float4*)(A + (long long)(m0 + m) * lda + k0 + kq * 4);
            As[kq*4+0][m] = v.x; As[kq*4+1][m] = v.y; As[kq*4+2][m] = v.z; As[kq*4+3][m] = v.w;
        }
        if (!NT) {
            for (int i = tid; i < BK * BN / 4; i += 256) {
                int kk = i / (BN / 4), nq = i % (BN / 4);
                *(float4*)&Bs[kk][nq*4] = *(const float4*)(B + (long long)(k0 + kk) * ldb + n0 + nq * 4);
            }
        } else {
            for (int i = tid; i < BN * BK / 4; i += 256) {
                int n = i / (BK / 4), kq = i % (BK / 4);
                float4 v = *(const float4*)(B + (long long)(n0 + n) * ldb + k0 + kq * 4);
                Bs[kq*4+0][n] = v.x; Bs[kq*4+1][n] = v.y; Bs[kq*4+2][n] = v.z; Bs[kq*4+3][n] = v.w;
            }
        }
        __syncthreads();
#pragma unroll
        for (int kk = 0; kk < BK; kk++) {
            float a[TM], b[TN];
#pragma unroll
            for (int i = 0; i < TM; i++) a[i] = As[kk][ty * TM + i];
#pragma unroll
            for (int j = 0; j < TN; j++) b[j] = Bs[kk][tx * TN + j];
#pragma unroll
            for (int i = 0; i < TM; i++)
#pragma unroll
                for (int j = 0; j < TN; j++) acc[i][j] += a[i] * b[j];
        }
        __syncthreads();
    }
#pragma unroll
    for (int i = 0; i < TM; i++)
#pragma unroll
        for (int j = 0; j < TN; j++)
            epi(z, m0 + ty * TM + i, n0 + tx * TN + j, acc[i][j]);
}

// --------- K1 logits GEMM with fused row softmax (BN=128 = full L row) ------
__global__ __launch_bounds__(256) void k1_softmax_kernel() {
    constexpr int BM = 64, BN = 128, BK = 16, TM = 4, TN = 8;
    __shared__ float As[BK][BM];
    __shared__ float Bs[BK][BN];
    const int z = blockIdx.z;
    const float* A = g_s + OQ  + (long long)z * Nn * Dd;
    const float* B = g_s + OLM + (long long)z * Ll * Dd;
    const int m0 = blockIdx.y * BM;
    const int tid = threadIdx.x;
    const int tx = tid % 16, ty = tid / 16;
    float acc[TM][TN];
#pragma unroll
    for (int i = 0; i < TM; i++)
#pragma unroll
        for (int j = 0; j < TN; j++) acc[i][j] = 0.f;

    for (int k0 = 0; k0 < Dd; k0 += BK) {
        for (int i = tid; i < BM * BK / 4; i += 256) {
            int m = i / 4, kq = i % 4;
            float4 v = *(const float4*)(A + (long long)(m0 + m) * Dd + k0 + kq * 4);
            As[kq*4+0][m] = v.x; As[kq*4+1][m] = v.y; As[kq*4+2][m] = v.z; As[kq*4+3][m] = v.w;
        }
        for (int i = tid; i < BN * BK / 4; i += 256) {
            int n = i / 4, kq = i % 4;
            float4 v = *(const float4*)(B + (long long)n * Dd + k0 + kq * 4);
            Bs[kq*4+0][n] = v.x; Bs[kq*4+1][n] = v.y; Bs[kq*4+2][n] = v.z; Bs[kq*4+3][n] = v.w;
        }
        __syncthreads();
#pragma unroll
        for (int kk = 0; kk < BK; kk++) {
            float a[TM], b[TN];
#pragma unroll
            for (int i = 0; i < TM; i++) a[i] = As[kk][ty * TM + i];
#pragma unroll
            for (int j = 0; j < TN; j++) b[j] = Bs[kk][tx * TN + j];
#pragma unroll
            for (int i = 0; i < TM; i++)
#pragma unroll
                for (int j = 0; j < TN; j++) acc[i][j] += a[i] * b[j];
        }
        __syncthreads();
    }
    // row softmax: each row's 128 cols live on the 16 lanes sharing ty
#pragma unroll
    for (int i = 0; i < TM; i++) {
        float mx = acc[i][0];
#pragma unroll
        for (int j = 1; j < TN; j++) mx = fmaxf(mx, acc[i][j]);
#pragma unroll
        for (int o = 1; o < 16; o <<= 1) mx = fmaxf(mx, __shfl_xor_sync(0xffffffffu, mx, o));
        float e[TN], s = 0.f;
#pragma unroll
        for (int j = 0; j < TN; j++) { e[j] = expf(acc[i][j] - mx); s += e[j]; }
#pragma unroll
        for (int o = 1; o < 16; o <<= 1) s += __shfl_xor_sync(0xffffffffu, s, o);
        float inv = 1.f / s;
        long long base = OK1 + ((long long)z * Nn + m0 + ty * TM + i) * Ll + tx * 8;
        *(float4*)&g_s[base]     = make_float4(e[0]*inv, e[1]*inv, e[2]*inv, e[3]*inv);
        *(float4*)&g_s[base + 4] = make_float4(e[4]*inv, e[5]*inv, e[6]*inv, e[7]*inv);
    }
}

// ------------------------- tf32 tensor-core GEMM (cp.async 3-stage) ---------
__device__ __forceinline__ float to_tf32(float x) {
    float r; asm("cvt.rna.tf32.f32 %0, %1;" : "=f"(r) : "f"(x)); return r;
}
__device__ __forceinline__ void mma_tf32(float (&d)[4], const float (&a)[4], const float (&b)[2]) {
    asm volatile("mma.sync.aligned.m16n8k8.row.col.f32.tf32.tf32.f32 "
        "{%0,%1,%2,%3}, {%4,%5,%6,%7}, {%8,%9}, {%0,%1,%2,%3};"
        : "+f"(d[0]), "+f"(d[1]), "+f"(d[2]), "+f"(d[3])
        : "r"(__float_as_uint(a[0])), "r"(__float_as_uint(a[1])),
          "r"(__float_as_uint(a[2])), "r"(__float_as_uint(a[3])),
          "r"(__float_as_uint(b[0])), "r"(__float_as_uint(b[1])));
}
__device__ __forceinline__ void cpa16(float* dst, const float* src) {
    unsigned s = (unsigned)__cvta_generic_to_shared(dst);
    asm volatile("cp.async.cg.shared.global [%0], [%1], 16;" :: "r"(s), "l"(src));
}

template <int BM, int WN, bool X3, class Epi>
__global__ __launch_bounds__(256) void gemm_tf32(
    const float* __restrict__ A, const float* __restrict__ B,
    int K, int lda, int ldb, long long sA1, long long sB1, Epi epi)
{
    constexpr int BN = WN * 32, BK = 16;
    constexpr int LDA_S = BK + 4;
    constexpr int LDB_S = BN + 8;
    constexpr int MF = (BM * WN) / 128;
    __shared__ float As[3][BM * LDA_S];
    __shared__ float Bs[3][BK * LDB_S];
    const int z = blockIdx.z;
    const int m0 = blockIdx.y * BM, n0 = blockIdx.x * BN;
    const float* Ab = A + (long long)z * sA1 + (long long)m0 * lda;
    const float* Bb = B + (long long)z * sB1 + n0;
    const int tid = threadIdx.x, wid = tid >> 5, lane = tid & 31;
    const int wm = (wid / WN) * (16 * MF), wn = (wid % WN) * 32;
    const int g = lane >> 2, t = lane & 3;

    float acc[MF][4][4];
#pragma unroll
    for (int i = 0; i < MF; i++)
#pragma unroll
        for (int j = 0; j < 4; j++)
#pragma unroll
            for (int r = 0; r < 4; r++) acc[i][j][r] = 0.f;

    auto stage_load = [&](int s, int k0) {
#pragma unroll
        for (int i = tid; i < BM * 4; i += 256) {
            int m = i >> 2, kq = i & 3;
            cpa16(&As[s][m * LDA_S + kq * 4], Ab + (long long)m * lda + k0 + kq * 4);
        }
#pragma unroll
        for (int i = tid; i < BK * (BN / 4); i += 256) {
            int kk = i / (BN / 4), nq = i % (BN / 4);
            cpa16(&Bs[s][kk * LDB_S + nq * 4], Bb + (long long)(k0 + kk) * ldb + nq * 4);
        }
        asm volatile("cp.async.commit_group;");
    };

    const int KT = K / BK;
    stage_load(0, 0);
    if (KT > 1) stage_load(1, BK);
    for (int kt = 0; kt < KT; kt++) {
        const int s = kt % 3;
        if (kt + 2 < KT) {
            stage_load((kt + 2) % 3, (kt + 2) * BK);
            asm volatile("cp.async.wait_group 2;");
        } else if (kt + 1 < KT) {
            asm volatile("cp.async.wait_group 1;");
        } else {
            asm volatile("cp.async.wait_group 0;");
        }
        __syncthreads();
#pragma unroll
        for (int ks = 0; ks < 2; ks++) {
            const int kb = ks * 8;
            float a[MF][4], b[4][2];
            float al[MF][4], bl[4][2];
#pragma unroll
            for (int mf = 0; mf < MF; mf++) {
                int ml = wm + mf * 16 + g;
                float r0 = As[s][ ml      * LDA_S + kb + t];
                float r1 = As[s][(ml + 8) * LDA_S + kb + t];
                float r2 = As[s][ ml      * LDA_S + kb + t + 4];
                float r3 = As[s][(ml + 8) * LDA_S + kb + t + 4];
                a[mf][0] = to_tf32(r0); a[mf][1] = to_tf32(r1);
                a[mf][2] = to_tf32(r2); a[mf][3] = to_tf32(r3);
                if (X3) {
                    al[mf][0] = to_tf32(r0 - a[mf][0]); al[mf][1] = to_tf32(r1 - a[mf][1]);
                    al[mf][2] = to_tf32(r2 - a[mf][2]); al[mf][3] = to_tf32(r3 - a[mf][3]);
                }
            }
#pragma unroll
            for (int nf = 0; nf < 4; nf++) {
                int nb = wn + nf * 8 + g;
                float r0 = Bs[s][(kb + t)     * LDB_S + nb];
                float r1 = Bs[s][(kb + t + 4) * LDB_S + nb];
                b[nf][0] = to_tf32(r0); b[nf][1] = to_tf32(r1);
                if (X3) {
                    bl[nf][0] = to_tf32(r0 - b[nf][0]); bl[nf][1] = to_tf32(r1 - b[nf][1]);
                }
            }
#pragma unroll
            for (int mf = 0; mf < MF; mf++)
#pragma unroll
                for (int nf = 0; nf < 4; nf++) {
                    mma_tf32(acc[mf][nf], a[mf], b[nf]);
                    if (X3) {
                        mma_tf32(acc[mf][nf], al[mf], b[nf]);
                        mma_tf32(acc[mf][nf], a[mf], bl[nf]);
                    }
                }
        }
        __syncthreads();
    }
#pragma unroll
    for (int mf = 0; mf < MF; mf++) {
        int m = m0 + wm + mf * 16 + g;
#pragma unroll
        for (int nf = 0; nf < 4; nf++) {
            int n = n0 + wn + nf * 8 + 2 * t;
            epi(z, m,     n,     acc[mf][nf][0]);
            epi(z, m,     n + 1, acc[mf][nf][1]);
            epi(z, m + 8, n,     acc[mf][nf][2]);
            epi(z, m + 8, n + 1, acc[mf][nf][3]);
        }
    }
}

// ------------------------- epilogues ----------------------------------------
struct EpiQKV {
    __device__ void operator()(int, int m, int n, float v) const {
        int part = n / Cc, c = n - part * Cc;
        int hh = c >> 6, dd = c & 63;
        int b = m / Nn, nn = m - b * Nn;
        long long idx = (((long long)(b * Hh + hh)) * Nn + nn) * Dd + dd;
        const float sc = 0.35355339059327378f;
        if (part == 0)      g_s[OQ  + idx] = v * sc;
        else if (part == 1) g_s[OKk + idx] = v * sc;
        else                g_s[OV  + idx] = v;
    }
};
struct EpiK2 {
    __device__ void operator()(int z, int m, int n, float v) const {
        int f = n / Pp, p = n - f * Pp;
        g_s[OK2 + (((long long)z * Ll + m) * Ff + f) * PPAD + p] = v;
    }
};
struct EpiX1 {
    __device__ void operator()(int z, int m, int n, float v) const {
        int bh = z >> 4, f = z & 15;
        g_s[OX1 + (((long long)bh * Ll + m) * Ff + f) * Dd + n] = v;
    }
};
struct EpiXO {
    __device__ void operator()(int z, int m, int n, float v) const {
        int b = z / Hh, hh = z - b * Hh;
        int f = n >> 6, dd = n & 63;
        long long base = (long long)(b * Nn + m);
        g_s[OXO + (base * Ff + f) * Cc + hh * Dd + dd] = v;
        if (f == m / Pp) g_s[OXD + base * Cc + hh * Dd + dd] = v;
    }
};
struct EpiQ2 {
    __device__ void operator()(int, int m, int n, float v) const {
        g_s[OQ2 + (long long)m * Cc + n] = v * 0.125f;
    }
};
struct EpiU {
    __device__ void operator()(int z, int m, int n, float v) const {
        g_s[OU + ((long long)m * Hh + z) * Cc + n] = v;
    }
};
struct EpiAO {
    __device__ void operator()(int z, int m, int n, float v) const {
        g_s[OAO + (long long)m * Cc + z * 64 + n] = v;
    }
};
struct EpiOut {
    float* out; const float* bias;
    __device__ void operator()(int, int m, int n, float v) const {
        out[(long long)m * Cc + n] = v + bias[n];
    }
};

// ------------------------- small kernels ------------------------------------
__global__ void norm_kernel() {
    long long gw = (long long)blockIdx.x * 8 + (threadIdx.x >> 5);
    int lane = threadIdx.x & 31;
    float2 v = ((const float2*)(g_s + OQ + gw * Dd))[lane];
    float ss = v.x * v.x + v.y * v.y;
#pragma unroll
    for (int o = 16; o; o >>= 1) ss += __shfl_xor_sync(0xffffffffu, ss, o);
    float dnm = fmaxf(sqrtf(ss), 1e-12f);
    int bh = (int)(gw / Nn), n = (int)(gw - (long long)bh * Nn);
    long long base = OQKN + (long long)bh * Nn * Dd;
    g_s[base + (long long)(2 * lane)     * Nn + n] = v.x / dnm;
    g_s[base + (long long)(2 * lane + 1) * Nn + n] = v.y / dnm;
}

__device__ __forceinline__ unsigned ctarank() {
    unsigned r; asm("mov.u32 %0, %%cluster_ctarank;" : "=r"(r)); return r;
}
__device__ __forceinline__ unsigned mapa_u32(unsigned addr, unsigned rank) {
    unsigned r; asm("mapa.shared::cluster.u32 %0, %1, %2;" : "=r"(r) : "r"(addr), "r"(rank));
    return r;
}

// FPS: FB=8 blocks per head = one CGA cluster; slice (100 KB) in dynamic smem.
// Each thread owns 2 consecutive columns; per-column dot order over d and the
// lowest-index tie-break are identical to prior rounds (bit-exact picks).
__global__ __launch_bounds__(256) __cluster_dims__(FB, 1, 1) void fps_kernel5() {
    extern __shared__ float ssm[];                            // [Dd][NS]
    __shared__ unsigned long long cand[2][FB];
    __shared__ float cur[Dd];
    __shared__ float s_val[8];
    __shared__ int   s_idx[8], s_pick;
    const int b = blockIdx.x / FB;
    const int j = (int)ctarank();
    const int tid = threadIdx.x;
    const float* qkT = g_s + OQKN + (long long)b * Nn * Dd;
    for (int i = tid; i < Dd * NCF; i += 256) {
        int d = i / NCF, c = i % NCF;
        *(float4*)&ssm[d * NS + 4 * c] =
            *(const float4*)(qkT + (long long)d * Nn + j * NS + 4 * c);
    }
    float ms0 = 0.f, ms1 = 0.f;
    if (tid == 0) {
        int i0 = jax_idx0(b);
        if (j == 0) g_idx[b * Ll] = i0;
        s_pick = i0;
    }
    __syncthreads();
    int pick = s_pick;
    if (tid < Dd) cur[tid] = qkT[(long long)tid * Nn + pick];
    if (tid == (pick >> 1) - j * NC2) {
        if (pick & 1) ms1 = 10.f; else ms0 = 10.f;
    }
    __syncthreads();
    const int lane = tid & 31, wid = tid >> 5;
    const unsigned candBase = (unsigned)__cvta_generic_to_shared(&cand[0][0]);
    for (int step = 1; step < Ll; step++) {
        float bv = 3.4e38f; int bi = 0x7fffffff;
        if (tid < NC2) {
            float ax = 0.f, ay = 0.f;
#pragma unroll
            for (int d = 0; d < Dd; d++) {
                float2 v = *(const float2*)&ssm[d * NS + 2 * tid];
                float c = cur[d];
                ax += v.x * c; ay += v.y * c;
            }
            ms0 = fmaxf(ms0, fabsf(ax)); ms1 = fmaxf(ms1, fabsf(ay));
            int nb = j * NS + 2 * tid;
            bv = ms0; bi = nb;
            if (ms1 < bv) { bv = ms1; bi = nb + 1; }
        }
#pragma unroll
        for (int o = 16; o; o >>= 1) {
            float ov = __shfl_down_sync(0xffffffffu, bv, o);
            int   oi = __shfl_down_sync(0xffffffffu, bi, o);
            if (ov < bv || (ov == bv && oi < bi)) { bv = ov; bi = oi; }
        }
        if (lane == 0) { s_val[wid] = bv; s_idx[wid] = bi; }
        __syncthreads();
        const int par = step & 1;
        if (tid == 0) {
#pragma unroll
            for (int w = 0; w < 8; w++) {
                float ov = s_val[w]; int oi = s_idx[w];
                if (w == 0 || ov < bv || (ov == bv && oi < bi)) { bv = ov; bi = oi; }
            }
            unsigned long long packed =
                ((unsigned long long)__float_as_uint(bv) << 32) | (unsigned)bi;
            unsigned slot = candBase + (unsigned)((par * FB + j) * 8);
#pragma unroll
            for (int jj = 0; jj < FB; jj++) {
                unsigned raddr = mapa_u32(slot, (unsigned)jj);
                asm volatile("st.shared::cluster.b64 [%0], %1;" :: "r"(raddr), "l"(packed));
            }
        }
        asm volatile("barrier.cluster.arrive.aligned;" ::: "memory");
        asm volatile("barrier.cluster.wait.aligned;" ::: "memory");
        unsigned long long best = cand[par][0];
#pragma unroll
        for (int jj = 1; jj < FB; jj++) {
            unsigned long long c2 = cand[par][jj];
            if (c2 < best) best = c2;
        }
        pick = (int)(unsigned)(best & 0xffffffffull);
        if (j == 0 && tid == 0) g_idx[b * Ll + step] = pick;
        if (tid < Dd) cur[tid] = qkT[(long long)tid * Nn + pick];
        if (tid == (pick >> 1) - j * NC2) {
            if (pick & 1) ms1 = 10.f; else ms0 = 10.f;
        }
        __syncthreads();
    }
}

__global__ void gather_lm() {
    int gw = blockIdx.x * 8 + (threadIdx.x >> 5);
    int lane = threadIdx.x & 31;
    int bh = gw >> 7;
    int idx = g_idx[gw];
    ((float2*)(g_s + OLM + (long long)gw * Dd))[lane] =
        ((const float2*)(g_s + OQ + ((long long)bh * Nn + idx) * Dd))[lane];
}

__global__ void softmax196() {
    long long r = (long long)blockIdx.x * 8 + (threadIdx.x >> 5);
    int lane = threadIdx.x & 31;
    float* row = g_s + OK2 + r * PPAD;
    float v[7], mx = -1e30f;
#pragma unroll
    for (int j = 0; j < 7; j++) { int i = lane + 32*j; v[j] = (i < Pp) ? row[i] : -1e30f; mx = fmaxf(mx, v[j]); }
#pragma unroll
    for (int o = 16; o; o >>= 1) mx = fmaxf(mx, __shfl_xor_sync(0xffffffffu, mx, o));
    float s = 0.f;
#pragma unroll
    for (int j = 0; j < 7; j++) { int i = lane + 32*j; if (i < Pp) { v[j] = expf(v[j] - mx); s += v[j]; } }
#pragma unroll
    for (int o = 16; o; o >>= 1) s += __shfl_xor_sync(0xffffffffu, s, o);
    float inv = 1.f / s;
#pragma unroll
    for (int j = 0; j < 7; j++) { int i = lane + 32*j; if (i < Pp) row[i] = v[j] * inv; }
    if (lane < PPAD - Pp) row[Pp + lane] = 0.f;
}

// transpose k-half of Wpkv: WkT[j][c] = Wpkv[c][j]
__global__ void transpose_wk(const float* __restrict__ W) {
    __shared__ float t[32][33];
    int j0 = blockIdx.x * 32, c0 = blockIdx.y * 32;
    int tx = threadIdx.x, ty = threadIdx.y;
#pragma unroll
    for (int i = 0; i < 32; i += 8)
        t[ty + i][tx] = W[(long long)(c0 + ty + i) * (2 * Cc) + j0 + tx];
    __syncthreads();
#pragma unroll
    for (int i = 0; i < 32; i += 8)
        g_s[OWKT + (long long)(j0 + ty + i) * Cc + c0 + tx] = t[tx][ty + i];
}

// fused: logits[n,h,f] = xo[n,f,:]·u[n,h,:]; softmax over f; attn out;
// xo_w[n,h,:] = sum_f w_f xo[n,f,:].  One block per (b,n), 384 thr = 12 warps (h).
__global__ __launch_bounds__(384) void attn2_kernel(float* outAttn) {
    extern __shared__ float xos[];                 // [Ff][Cc] = 49152 B
    __shared__ float lg[Hh][Ff];
    __shared__ float wts[Hh][Ff];
    const int bn = blockIdx.x;
    const int tid = threadIdx.x, h = tid >> 5, lane = tid & 31;
    const float* xsrc = g_s + OXO + (long long)bn * Ff * Cc;
    for (int i = tid; i < Ff * Cc / 4; i += 384)
        ((float4*)xos)[i] = ((const float4*)xsrc)[i];
    float ureg[24];
    const float* urow = g_s + OU + ((long long)bn * Hh + h) * Cc;
#pragma unroll
    for (int i = 0; i < 24; i++) ureg[i] = urow[lane + 32 * i];
    __syncthreads();
#pragma unroll
    for (int f = 0; f < Ff; f++) {
        const float* xr = xos + f * Cc;
        float p = 0.f;
#pragma unroll
        for (int i = 0; i < 24; i++) p += ureg[i] * xr[lane + 32 * i];
#pragma unroll
        for (int o = 16; o; o >>= 1) p += __shfl_xor_sync(0xffffffffu, p, o);
        if (lane == 0) lg[h][f] = p;
    }
    __syncwarp();
    float mx = -1e30f;
#pragma unroll
    for (int f = 0; f < Ff; f++) mx = fmaxf(mx, lg[h][f]);
    float s = 0.f;
#pragma unroll
    for (int f = 0; f < Ff; f++) s += expf(lg[h][f] - mx);
    float inv = 1.f / s;
    if (lane < Ff) {
        float w = expf(lg[h][lane] - mx) * inv;
        wts[h][lane] = w;
        int b = bn / Nn, n = bn - b * Nn;
        outAttn[(((long long)(b * Hh + h)) * Nn + n) * Ff + lane] = w;
    }
    __syncwarp();
    float* xw = g_s + OXW + ((long long)bn * Hh + h) * Cc;
#pragma unroll
    for (int i = 0; i < 24; i++) {
        float acc = 0.f;
#pragma unroll
        for (int f = 0; f < Ff; f++) acc += wts[h][f] * xos[f * Cc + lane + 32 * i];
        xw[lane + 32 * i] = acc;
    }
}

// ------------------------- launch -------------------------------------------
extern "C" void kernel_launch(void* const* d_in, const int*, int, void* d_out, int) {
    const float* x     = (const float*)d_in[0];
    const float* Wqkv  = (const float*)d_in[1];
    const float* Wpq   = (const float*)d_in[2];
    const float* Wpkv  = (const float*)d_in[3];
    const float* Wproj = (const float*)d_in[4];
    const float* bproj = (const float*)d_in[5];
    float* out = (float*)d_out;

    float* sc = nullptr;
    cudaGetSymbolAddress((void**)&sc, g_s);

    const int fps_smem = Dd * NS * (int)sizeof(float);       // 100352 B
    cudaFuncSetAttribute(fps_kernel5, cudaFuncAttributeMaxDynamicSharedMemorySize, fps_smem);
    const int at2_smem = Ff * Cc * (int)sizeof(float);       // 49152 B
    cudaFuncSetAttribute(attn2_kernel, cudaFuncAttributeMaxDynamicSharedMemorySize, at2_smem);

    // 1) qkv = x @ W_qkv (3xTF32)
    gemm_tf32<128,4,true,EpiQKV><<<dim3(18,49,1),256>>>(
        x, Wqkv, Cc, Cc, 3*Cc, 0, 0, EpiQKV{});
    norm_kernel<<<9408,256>>>();
    fps_kernel5<<<BH*FB,256,fps_smem>>>();
    gather_lm<<<384,256>>>();
    // kernel_1 logits + fused row softmax
    k1_softmax_kernel<<<dim3(1,49,BH),256>>>();
    gemm_kernel<128,64,16,8,4,true,EpiK2><<<dim3(49,1,BH),256>>>(
        sc+OLM, sc+OKk, Ll, Nn, Dd, Dd, Dd,
        (long long)Ll*Dd,0, (long long)Nn*Dd,0, 1, EpiK2{});
    softmax196<<<6144,256>>>();
    gemm_kernel<128,64,16,8,4,false,EpiX1><<<dim3(1,1,BH*Ff),256>>>(
        sc+OK2, sc+OV, Ll, Dd, PPAD, Ff*PPAD, Dd,
        (long long)Ll*Ff*PPAD, PPAD, (long long)Nn*Dd, (long long)Pp*Dd, Ff, EpiX1{});
    // xo = kernel_1 @ x1  (tf32)
    gemm_tf32<64,4,false,EpiXO><<<dim3(8,49,BH),256>>>(
        sc+OK1, sc+OX1, Ll, Ll, Ff*Dd,
        (long long)Nn*Ll, (long long)Ll*Ff*Dd, EpiXO{});
    // q2 = xdiag @ W_pq  (tf32, scaled)
    gemm_tf32<128,4,false,EpiQ2><<<dim3(6,49,1),256>>>(
        sc+OXD, Wpq, Cc, Cc, Cc, 0, 0, EpiQ2{});
    // Wk^T for the U GEMM
    transpose_wk<<<dim3(24,24),dim3(32,8)>>>(Wpkv);
    // u[n,h,:] = Wk_h^T @ q2[n,h,:]  (batched over h, plain tf32)
    gemm_tf32<128,4,false,EpiU><<<dim3(6,49,Hh),256>>>(
        sc+OQ2, sc+OWKT, Dd, Cc, Cc, 64, (long long)64*Cc, EpiU{});
    // fused logits + softmax + attn-out + weighted xo
    attn2_kernel<<<Bb*Nn,384,at2_smem>>>(out + (long long)Bb*Nn*Cc);
    // ao[n,h-block] = xo_w[n,h,:] @ Wv_h  (batched over h, tf32)
    gemm_tf32<128,2,false,EpiAO><<<dim3(1,49,Hh),256>>>(
        sc+OXW, Wpkv + Cc, Cc, Hh*Cc, 2*Cc, Cc, 64, EpiAO{});
    // out = ao @ W_proj + b  (tf32)
    gemm_tf32<128,4,false,EpiOut><<<dim3(6,49,1),256>>>(
        sc+OAO, Wproj, Cc, Cc, Cc, 0, 0, EpiOut{out, bproj});
}

// round 14
// speedup vs baseline: 1.1943x; 1.0605x over previous
#include <cuda_runtime.h>

#define PRNG_VARIANT 0  // 0 = threefry_partitionable (modern JAX default), 1 = legacy

namespace ta {
constexpr int Bb=2, Hh=12, BH=24, Ff=16, Pp=196, Nn=3136, Cc=768, Dd=64, Ll=128, PPAD=208;
constexpr int FB=8, NS=Nn/FB, NC2=NS/2, NCF=NS/4;
constexpr long long QS = (long long)BH*Nn*Dd;
constexpr long long OQ=0, OKk=OQ+QS, OV=OKk+QS, OQKN=OV+QS, OLM=OQKN+QS;
constexpr long long OK1=OLM+(long long)BH*Ll*Dd;
constexpr long long OK2=OK1+(long long)BH*Nn*Ll;
constexpr long long OX1=OK2+(long long)BH*Ll*Ff*PPAD;
constexpr long long OXO=OX1+(long long)BH*Ll*Ff*Dd;
constexpr long long OXD=OXO+(long long)Bb*Nn*Ff*Cc;
constexpr long long OQ2=OXD+(long long)Bb*Nn*Cc;
constexpr long long OU =OQ2+(long long)Bb*Nn*Cc;
constexpr long long OXW=OU +(long long)Bb*Nn*Hh*Cc;
constexpr long long OWKT=OXW+(long long)Bb*Nn*Hh*Cc;
constexpr long long OAO=OWKT+(long long)Cc*Cc;
constexpr long long TOT=OAO+(long long)Bb*Nn*Cc;
}
__device__ float g_s[ta::TOT];
__device__ int   g_idx[ta::BH*ta::Ll];

using namespace ta;

// ------------------------- threefry2x32 (general key) -----------------------
__device__ __forceinline__ void tf(unsigned k0, unsigned k1, unsigned x0, unsigned x1,
                                   unsigned &y0, unsigned &y1) {
    const unsigned k2 = 0x1BD11BDAu ^ k0 ^ k1;
    x0 += k0; x1 += k1;
#define TFR(r) { x0 += x1; x1 = (x1<<(r))|(x1>>(32-(r))); x1 ^= x0; }
    TFR(13) TFR(15) TFR(26) TFR(6)   x0 += k1; x1 += k2 + 1u;
    TFR(17) TFR(29) TFR(16) TFR(24)  x0 += k2; x1 += k0 + 2u;
    TFR(13) TFR(15) TFR(26) TFR(6)   x0 += k0; x1 += k1 + 3u;
    TFR(17) TFR(29) TFR(16) TFR(24)  x0 += k1; x1 += k2 + 4u;
    TFR(13) TFR(15) TFR(26) TFR(6)   x0 += k2; x1 += k0 + 5u;
#undef TFR
    y0 = x0; y1 = x1;
}

__device__ int jax_idx0(int i) {
    const unsigned span = (unsigned)Nn;
    const unsigned mult = 2048u;
    unsigned hi, lo;
#if PRNG_VARIANT == 0
    unsigned a0,a1,b0,b1,y0,y1;
    tf(0u,42u, 0u,0u, a0,a1);
    tf(0u,42u, 0u,1u, b0,b1);
    tf(a0,a1, 0u,(unsigned)i, y0,y1); hi = y0 ^ y1;
    tf(b0,b1, 0u,(unsigned)i, y0,y1); lo = y0 ^ y1;
#else
    unsigned s00,s01,s10,s11,y0,y1;
    tf(0u,42u, 0u,2u, s00,s01);
    tf(0u,42u, 1u,3u, s10,s11);
    unsigned k1a=s00, k1b=s10, k2a=s01, k2b=s11;
    if (i < 12) { tf(k1a,k1b,(unsigned)i,(unsigned)(i+12),y0,y1); hi = y0; }
    else        { tf(k1a,k1b,(unsigned)(i-12),(unsigned)i,y0,y1); hi = y1; }
    if (i < 12) { tf(k2a,k2b,(unsigned)i,(unsigned)(i+12),y0,y1); lo = y0; }
    else        { tf(k2a,k2b,(unsigned)(i-12),(unsigned)i,y0,y1); lo = y1; }
#endif
    return (int)((((hi % span) * mult) + (lo % span)) % span);
}

// ------------------------- generic tiled f32 SIMT GEMM ----------------------
template <int BM, int BN, int BK, int TM, int TN, bool NT, class Epi>
__global__ __launch_bounds__(256) void gemm_kernel(
    const float* __restrict__ A, const float* __restrict__ B,
    int M, int N, int K, int lda, int ldb,
    long long sA1, long long sA2, long long sB1, long long sB2, int zdiv, Epi epi)
{
    __shared__ float As[BK][BM];
    __shared__ float Bs[BK][BN];
    const int z = blockIdx.z, za = z / zdiv, zb = z % zdiv;
    A += za * sA1 + zb * sA2;
    B += za * sB1 + zb * sB2;
    const int m0 = blockIdx.y * BM, n0 = blockIdx.x * BN;
    const int tid = threadIdx.x;
    const int tx = tid % (BN / TN), ty = tid / (BN / TN);
    float acc[TM][TN];
#pragma unroll
    for (int i = 0; i < TM; i++)
#pragma unroll
        for (int j = 0; j < TN; j++) acc[i][j] = 0.f;

    for (int k0 = 0; k0 < K; k0 += BK) {
        for (int i = tid; i < BM * BK / 4; i += 256) {
            int m = i / (BK / 4), kq = i % (BK / 4);
            float4 v = *(const float4*)(A + (long long)(m0 + m) * lda + k0 + kq * 4);
            As[kq*4+0][m] = v.x; As[kq*4+1][m] = v.y; As[kq*4+2][m] = v.z; As[kq*4+3][m] = v.w;
        }
        if (!NT) {
            for (int i = tid; i < BK * BN / 4; i += 256) {
                int kk = i / (BN / 4), nq = i % (BN / 4);
                *(float4*)&Bs[kk][nq*4] = *(const float4*)(B + (long long)(k0 + kk) * ldb + n0 + nq * 4);
            }
        } else {
            for (int i = tid; i < BN * BK / 4; i += 256) {
                int n = i / (BK / 4), kq = i % (BK / 4);
                float4 v = *(const float4*)(B + (long long)(n0 + n) * ldb + k0 + kq * 4);
                Bs[kq*4+0][n] = v.x; Bs[kq*4+1][n] = v.y; Bs[kq*4+2][n] = v.z; Bs[kq*4+3][n] = v.w;
            }
        }
        __syncthreads();
#pragma unroll
        for (int kk = 0; kk < BK; kk++) {
            float a[TM], b[TN];
#pragma unroll
            for (int i = 0; i < TM; i++) a[i] = As[kk][ty * TM + i];
#pragma unroll
            for (int j = 0; j < TN; j++) b[j] = Bs[kk][tx * TN + j];
#pragma unroll
            for (int i = 0; i < TM; i++)
#pragma unroll
                for (int j = 0; j < TN; j++) acc[i][j] += a[i] * b[j];
        }
        __syncthreads();
    }
#pragma unroll
    for (int i = 0; i < TM; i++)
#pragma unroll
        for (int j = 0; j < TN; j++)
            epi(z, m0 + ty * TM + i, n0 + tx * TN + j, acc[i][j]);
}

// --------- K1 logits GEMM with fused row softmax (BN=128 = full L row) ------
__global__ __launch_bounds__(256) void k1_softmax_kernel() {
    constexpr int BM = 64, BK = 16, TM = 4, TN = 8;
    __shared__ float As[BK][BM];
    __shared__ float Bs[BK][128];
    const int z = blockIdx.z;
    const float* A = g_s + OQ  + (long long)z * Nn * Dd;
    const float* B = g_s + OLM + (long long)z * Ll * Dd;
    const int m0 = blockIdx.y * BM;
    const int tid = threadIdx.x;
    const int tx = tid % 16, ty = tid / 16;
    float acc[TM][TN];
#pragma unroll
    for (int i = 0; i < TM; i++)
#pragma unroll
        for (int j = 0; j < TN; j++) acc[i][j] = 0.f;

    for (int k0 = 0; k0 < Dd; k0 += BK) {
        for (int i = tid; i < BM * BK / 4; i += 256) {
            int m = i / 4, kq = i % 4;
            float4 v = *(const float4*)(A + (long long)(m0 + m) * Dd + k0 + kq * 4);
            As[kq*4+0][m] = v.x; As[kq*4+1][m] = v.y; As[kq*4+2][m] = v.z; As[kq*4+3][m] = v.w;
        }
        for (int i = tid; i < 128 * BK / 4; i += 256) {
            int n = i / 4, kq = i % 4;
            float4 v = *(const float4*)(B + (long long)n * Dd + k0 + kq * 4);
            Bs[kq*4+0][n] = v.x; Bs[kq*4+1][n] = v.y; Bs[kq*4+2][n] = v.z; Bs[kq*4+3][n] = v.w;
        }
        __syncthreads();
#pragma unroll
        for (int kk = 0; kk < BK; kk++) {
            float a[TM], b[TN];
#pragma unroll
            for (int i = 0; i < TM; i++) a[i] = As[kk][ty * TM + i];
#pragma unroll
            for (int j = 0; j < TN; j++) b[j] = Bs[kk][tx * TN + j];
#pragma unroll
            for (int i = 0; i < TM; i++)
#pragma unroll
                for (int j = 0; j < TN; j++) acc[i][j] += a[i] * b[j];
        }
        __syncthreads();
    }
#pragma unroll
    for (int i = 0; i < TM; i++) {
        float mx = acc[i][0];
#pragma unroll
        for (int j = 1; j < TN; j++) mx = fmaxf(mx, acc[i][j]);
#pragma unroll
        for (int o = 1; o < 16; o <<= 1) mx = fmaxf(mx, __shfl_xor_sync(0xffffffffu, mx, o));
        float e[TN], s = 0.f;
#pragma unroll
        for (int j = 0; j < TN; j++) { e[j] = expf(acc[i][j] - mx); s += e[j]; }
#pragma unroll
        for (int o = 1; o < 16; o <<= 1) s += __shfl_xor_sync(0xffffffffu, s, o);
        float inv = 1.f / s;
        long long base = OK1 + ((long long)z * Nn + m0 + ty * TM + i) * Ll + tx * 8;
        *(float4*)&g_s[base]     = make_float4(e[0]*inv, e[1]*inv, e[2]*inv, e[3]*inv);
        *(float4*)&g_s[base + 4] = make_float4(e[4]*inv, e[5]*inv, e[6]*inv, e[7]*inv);
    }
}

// ------------------------- tf32 tensor-core GEMM (cp.async 3-stage) ---------
__device__ __forceinline__ float to_tf32(float x) {
    float r; asm("cvt.rna.tf32.f32 %0, %1;" : "=f"(r) : "f"(x)); return r;
}
__device__ __forceinline__ void mma_tf32(float (&d)[4], const float (&a)[4], const float (&b)[2]) {
    asm volatile("mma.sync.aligned.m16n8k8.row.col.f32.tf32.tf32.f32 "
        "{%0,%1,%2,%3}, {%4,%5,%6,%7}, {%8,%9}, {%0,%1,%2,%3};"
        : "+f"(d[0]), "+f"(d[1]), "+f"(d[2]), "+f"(d[3])
        : "r"(__float_as_uint(a[0])), "r"(__float_as_uint(a[1])),
          "r"(__float_as_uint(a[2])), "r"(__float_as_uint(a[3])),
          "r"(__float_as_uint(b[0])), "r"(__float_as_uint(b[1])));
}
__device__ __forceinline__ void cpa16(float* dst, const float* src) {
    unsigned s = (unsigned)__cvta_generic_to_shared(dst);
    asm volatile("cp.async.cg.shared.global [%0], [%1], 16;" :: "r"(s), "l"(src));
}

template <int BM, int WN, bool X3, class Epi>
__global__ __launch_bounds__(256) void gemm_tf32(
    const float* __restrict__ A, const float* __restrict__ B,
    int K, int lda, int ldb, long long sA1, long long sB1, Epi epi)
{
    constexpr int BN = WN * 32, BK = 16;
    constexpr int LDA_S = BK + 4;
    constexpr int LDB_S = BN + 8;
    constexpr int MF = (BM * WN) / 128;
    __shared__ float As[3][BM * LDA_S];
    __shared__ float Bs[3][BK * LDB_S];
    const int z = blockIdx.z;
    const int m0 = blockIdx.y * BM, n0 = blockIdx.x * BN;
    const float* Ab = A + (long long)z * sA1 + (long long)m0 * lda;
    const float* Bb = B + (long long)z * sB1 + n0;
    const int tid = threadIdx.x, wid = tid >> 5, lane = tid & 31;
    const int wm = (wid / WN) * (16 * MF), wn = (wid % WN) * 32;
    const int g = lane >> 2, t = lane & 3;

    float acc[MF][4][4];
#pragma unroll
    for (int i = 0; i < MF; i++)
#pragma unroll
        for (int j = 0; j < 4; j++)
#pragma unroll
            for (int r = 0; r < 4; r++) acc[i][j][r] = 0.f;

    auto stage_load = [&](int s, int k0) {
#pragma unroll
        for (int i = tid; i < BM * 4; i += 256) {
            int m = i >> 2, kq = i & 3;
            cpa16(&As[s][m * LDA_S + kq * 4], Ab + (long long)m * lda + k0 + kq * 4);
        }
#pragma unroll
        for (int i = tid; i < BK * (BN / 4); i += 256) {
            int kk = i / (BN / 4), nq = i % (BN / 4);
            cpa16(&Bs[s][kk * LDB_S + nq * 4], Bb + (long long)(k0 + kk) * ldb + nq * 4);
        }
        asm volatile("cp.async.commit_group;");
    };

    const int KT = K / BK;
    stage_load(0, 0);
    if (KT > 1) stage_load(1, BK);
    for (int kt = 0; kt < KT; kt++) {
        const int s = kt % 3;
        if (kt + 2 < KT) {
            stage_load((kt + 2) % 3, (kt + 2) * BK);
            asm volatile("cp.async.wait_group 2;");
        } else if (kt + 1 < KT) {
            asm volatile("cp.async.wait_group 1;");
        } else {
            asm volatile("cp.async.wait_group 0;");
        }
        __syncthreads();
#pragma unroll
        for (int ks = 0; ks < 2; ks++) {
            const int kb = ks * 8;
            float a[MF][4], b[4][2];
            float al[MF][4], bl[4][2];
#pragma unroll
            for (int mf = 0; mf < MF; mf++) {
                int ml = wm + mf * 16 + g;
                float r0 = As[s][ ml      * LDA_S + kb + t];
                float r1 = As[s][(ml + 8) * LDA_S + kb + t];
                float r2 = As[s][ ml      * LDA_S + kb + t + 4];
                float r3 = As[s][(ml + 8) * LDA_S + kb + t + 4];
                a[mf][0] = to_tf32(r0); a[mf][1] = to_tf32(r1);
                a[mf][2] = to_tf32(r2); a[mf][3] = to_tf32(r3);
                if (X3) {
                    al[mf][0] = to_tf32(r0 - a[mf][0]); al[mf][1] = to_tf32(r1 - a[mf][1]);
                    al[mf][2] = to_tf32(r2 - a[mf][2]); al[mf][3] = to_tf32(r3 - a[mf][3]);
                }
            }
#pragma unroll
            for (int nf = 0; nf < 4; nf++) {
                int nb = wn + nf * 8 + g;
                float r0 = Bs[s][(kb + t)     * LDB_S + nb];
                float r1 = Bs[s][(kb + t + 4) * LDB_S + nb];
                b[nf][0] = to_tf32(r0); b[nf][1] = to_tf32(r1);
                if (X3) {
                    bl[nf][0] = to_tf32(r0 - b[nf][0]); bl[nf][1] = to_tf32(r1 - b[nf][1]);
                }
            }
#pragma unroll
            for (int mf = 0; mf < MF; mf++)
#pragma unroll
                for (int nf = 0; nf < 4; nf++) {
                    mma_tf32(acc[mf][nf], a[mf], b[nf]);
                    if (X3) {
                        mma_tf32(acc[mf][nf], al[mf], b[nf]);
                        mma_tf32(acc[mf][nf], a[mf], bl[nf]);
                    }
                }
        }
        __syncthreads();
    }
#pragma unroll
    for (int mf = 0; mf < MF; mf++) {
        int m = m0 + wm + mf * 16 + g;
#pragma unroll
        for (int nf = 0; nf < 4; nf++) {
            int n = n0 + wn + nf * 8 + 2 * t;
            epi(z, m,     n,     acc[mf][nf][0]);
            epi(z, m,     n + 1, acc[mf][nf][1]);
            epi(z, m + 8, n,     acc[mf][nf][2]);
            epi(z, m + 8, n + 1, acc[mf][nf][3]);
        }
    }
}

// ------------------------- epilogues ----------------------------------------
struct EpiQ {     // q columns only (N = 0..767), scaled
    __device__ void operator()(int, int m, int n, float v) const {
        int hh = n >> 6, dd = n & 63;
        int b = m / Nn, nn = m - b * Nn;
        g_s[OQ + (((long long)(b * Hh + hh)) * Nn + nn) * Dd + dd]
            = v * 0.35355339059327378f;
    }
};
struct EpiKV {    // k,v columns (n = 0..1535 relative to Wqkv col 768)
    __device__ void operator()(int, int m, int n, float v) const {
        int part = n >> 9 >> 1;          // n/1024? no — part = n / Cc
        part = n / Cc; int c = n - part * Cc;
        int hh = c >> 6, dd = c & 63;
        int b = m / Nn, nn = m - b * Nn;
        long long idx = (((long long)(b * Hh + hh)) * Nn + nn) * Dd + dd;
        if (part == 0) g_s[OKk + idx] = v * 0.35355339059327378f;
        else           g_s[OV  + idx] = v;
    }
};
struct EpiK2 {
    __device__ void operator()(int z, int m, int n, float v) const {
        int f = n / Pp, p = n - f * Pp;
        g_s[OK2 + (((long long)z * Ll + m) * Ff + f) * PPAD + p] = v;
    }
};
struct EpiX1 {
    __device__ void operator()(int z, int m, int n, float v) const {
        int bh = z >> 4, f = z & 15;
        g_s[OX1 + (((long long)bh * Ll + m) * Ff + f) * Dd + n] = v;
    }
};
struct EpiXO {
    __device__ void operator()(int z, int m, int n, float v) const {
        int b = z / Hh, hh = z - b * Hh;
        int f = n >> 6, dd = n & 63;
        long long base = (long long)(b * Nn + m);
        g_s[OXO + (base * Ff + f) * Cc + hh * Dd + dd] = v;
        if (f == m / Pp) g_s[OXD + base * Cc + hh * Dd + dd] = v;
    }
};
struct EpiQ2 {
    __device__ void operator()(int, int m, int n, float v) const {
        g_s[OQ2 + (long long)m * Cc + n] = v * 0.125f;
    }
};
struct EpiU {
    __device__ void operator()(int z, int m, int n, float v) const {
        g_s[OU + ((long long)m * Hh + z) * Cc + n] = v;
    }
};
struct EpiAO {
    __device__ void operator()(int z, int m, int n, float v) const {
        g_s[OAO + (long long)m * Cc + z * 64 + n] = v;
    }
};
struct EpiOut {
    float* out; const float* bias;
    __device__ void operator()(int, int m, int n, float v) const {
        out[(long long)m * Cc + n] = v + bias[n];
    }
};

// ------------------------- small kernels ------------------------------------
__global__ void norm_kernel() {
    long long gw = (long long)blockIdx.x * 8 + (threadIdx.x >> 5);
    int lane = threadIdx.x & 31;
    float2 v = ((const float2*)(g_s + OQ + gw * Dd))[lane];
    float ss = v.x * v.x + v.y * v.y;
#pragma unroll
    for (int o = 16; o; o >>= 1) ss += __shfl_xor_sync(0xffffffffu, ss, o);
    float dnm = fmaxf(sqrtf(ss), 1e-12f);
    int bh = (int)(gw / Nn), n = (int)(gw - (long long)bh * Nn);
    long long base = OQKN + (long long)bh * Nn * Dd;
    g_s[base + (long long)(2 * lane)     * Nn + n] = v.x / dnm;
    g_s[base + (long long)(2 * lane + 1) * Nn + n] = v.y / dnm;
}

__device__ __forceinline__ unsigned ctarank() {
    unsigned r; asm("mov.u32 %0, %%cluster_ctarank;" : "=r"(r)); return r;
}
__device__ __forceinline__ unsigned mapa_u32(unsigned addr, unsigned rank) {
    unsigned r; asm("mapa.shared::cluster.u32 %0, %1, %2;" : "=r"(r) : "r"(addr), "r"(rank));
    return r;
}

__global__ __launch_bounds__(256) __cluster_dims__(FB, 1, 1) void fps_kernel5() {
    extern __shared__ float ssm[];                            // [Dd][NS]
    __shared__ unsigned long long cand[2][FB];
    __shared__ float cur[Dd];
    __shared__ float s_val[8];
    __shared__ int   s_idx[8], s_pick;
    const int b = blockIdx.x / FB;
    const int j = (int)ctarank();
    const int tid = threadIdx.x;
    const float* qkT = g_s + OQKN + (long long)b * Nn * Dd;
    for (int i = tid; i < Dd * NCF; i += 256) {
        int d = i / NCF, c = i % NCF;
        *(float4*)&ssm[d * NS + 4 * c] =
            *(const float4*)(qkT + (long long)d * Nn + j * NS + 4 * c);
    }
    float ms0 = 0.f, ms1 = 0.f;
    if (tid == 0) {
        int i0 = jax_idx0(b);
        if (j == 0) g_idx[b * Ll] = i0;
        s_pick = i0;
    }
    __syncthreads();
    int pick = s_pick;
    if (tid < Dd) cur[tid] = qkT[(long long)tid * Nn + pick];
    if (tid == (pick >> 1) - j * NC2) {
        if (pick & 1) ms1 = 10.f; else ms0 = 10.f;
    }
    __syncthreads();
    const int lane = tid & 31, wid = tid >> 5;
    const unsigned candBase = (unsigned)__cvta_generic_to_shared(&cand[0][0]);
    for (int step = 1; step < Ll; step++) {
        float bv = 3.4e38f; int bi = 0x7fffffff;
        if (tid < NC2) {
            float ax = 0.f, ay = 0.f;
#pragma unroll
            for (int d = 0; d < Dd; d++) {
                float2 v = *(const float2*)&ssm[d * NS + 2 * tid];
                float c = cur[d];
                ax += v.x * c; ay += v.y * c;
            }
            ms0 = fmaxf(ms0, fabsf(ax)); ms1 = fmaxf(ms1, fabsf(ay));
            int nb = j * NS + 2 * tid;
            bv = ms0; bi = nb;
            if (ms1 < bv) { bv = ms1; bi = nb + 1; }
        }
#pragma unroll
        for (int o = 16; o; o >>= 1) {
            float ov = __shfl_down_sync(0xffffffffu, bv, o);
            int   oi = __shfl_down_sync(0xffffffffu, bi, o);
            if (ov < bv || (ov == bv && oi < bi)) { bv = ov; bi = oi; }
        }
        if (lane == 0) { s_val[wid] = bv; s_idx[wid] = bi; }
        __syncthreads();
        const int par = step & 1;
        if (tid == 0) {
#pragma unroll
            for (int w = 0; w < 8; w++) {
                float ov = s_val[w]; int oi = s_idx[w];
                if (w == 0 || ov < bv || (ov == bv && oi < bi)) { bv = ov; bi = oi; }
            }
            unsigned long long packed =
                ((unsigned long long)__float_as_uint(bv) << 32) | (unsigned)bi;
            unsigned slot = candBase + (unsigned)((par * FB + j) * 8);
#pragma unroll
            for (int jj = 0; jj < FB; jj++) {
                unsigned raddr = mapa_u32(slot, (unsigned)jj);
                asm volatile("st.shared::cluster.b64 [%0], %1;" :: "r"(raddr), "l"(packed));
            }
        }
        asm volatile("barrier.cluster.arrive.aligned;" ::: "memory");
        asm volatile("barrier.cluster.wait.aligned;" ::: "memory");
        unsigned long long best = cand[par][0];
#pragma unroll
        for (int jj = 1; jj < FB; jj++) {
            unsigned long long c2 = cand[par][jj];
            if (c2 < best) best = c2;
        }
        pick = (int)(unsigned)(best & 0xffffffffull);
        if (j == 0 && tid == 0) g_idx[b * Ll + step] = pick;
        if (tid < Dd) cur[tid] = qkT[(long long)tid * Nn + pick];
        if (tid == (pick >> 1) - j * NC2) {
            if (pick & 1) ms1 = 10.f; else ms0 = 10.f;
        }
        __syncthreads();
    }
}

__global__ void gather_lm() {
    int gw = blockIdx.x * 8 + (threadIdx.x >> 5);
    int lane = threadIdx.x & 31;
    int bh = gw >> 7;
    int idx = g_idx[gw];
    ((float2*)(g_s + OLM + (long long)gw * Dd))[lane] =
        ((const float2*)(g_s + OQ + ((long long)bh * Nn + idx) * Dd))[lane];
}

__global__ void softmax196() {
    long long r = (long long)blockIdx.x * 8 + (threadIdx.x >> 5);
    int lane = threadIdx.x & 31;
    float* row = g_s + OK2 + r * PPAD;
    float v[7], mx = -1e30f;
#pragma unroll
    for (int j = 0; j < 7; j++) { int i = lane + 32*j; v[j] = (i < Pp) ? row[i] : -1e30f; mx = fmaxf(mx, v[j]); }
#pragma unroll
    for (int o = 16; o; o >>= 1) mx = fmaxf(mx, __shfl_xor_sync(0xffffffffu, mx, o));
    float s = 0.f;
#pragma unroll
    for (int j = 0; j < 7; j++) { int i = lane + 32*j; if (i < Pp) { v[j] = expf(v[j] - mx); s += v[j]; } }
#pragma unroll
    for (int o = 16; o; o >>= 1) s += __shfl_xor_sync(0xffffffffu, s, o);
    float inv = 1.f / s;
#pragma unroll
    for (int j = 0; j < 7; j++) { int i = lane + 32*j; if (i < Pp) row[i] = v[j] * inv; }
    if (lane < PPAD - Pp) row[Pp + lane] = 0.f;
}

__global__ void transpose_wk(const float* __restrict__ W) {
    __shared__ float t[32][33];
    int j0 = blockIdx.x * 32, c0 = blockIdx.y * 32;
    int tx = threadIdx.x, ty = threadIdx.y;
#pragma unroll
    for (int i = 0; i < 32; i += 8)
        t[ty + i][tx] = W[(long long)(c0 + ty + i) * (2 * Cc) + j0 + tx];
    __syncthreads();
#pragma unroll
    for (int i = 0; i < 32; i += 8)
        g_s[OWKT + (long long)(j0 + ty + i) * Cc + c0 + tx] = t[tx][ty + i];
}

__global__ __launch_bounds__(384) void attn2_kernel(float* outAttn) {
    extern __shared__ float xos[];                 // [Ff][Cc] = 49152 B
    __shared__ float lg[Hh][Ff];
    __shared__ float wts[Hh][Ff];
    const int bn = blockIdx.x;
    const int tid = threadIdx.x, h = tid >> 5, lane = tid & 31;
    const float* xsrc = g_s + OXO + (long long)bn * Ff * Cc;
    for (int i = tid; i < Ff * Cc / 4; i += 384)
        ((float4*)xos)[i] = ((const float4*)xsrc)[i];
    float ureg[24];
    const float* urow = g_s + OU + ((long long)bn * Hh + h) * Cc;
#pragma unroll
    for (int i = 0; i < 24; i++) ureg[i] = urow[lane + 32 * i];
    __syncthreads();
#pragma unroll
    for (int f = 0; f < Ff; f++) {
        const float* xr = xos + f * Cc;
        float p = 0.f;
#pragma unroll
        for (int i = 0; i < 24; i++) p += ureg[i] * xr[lane + 32 * i];
#pragma unroll
        for (int o = 16; o; o >>= 1) p += __shfl_xor_sync(0xffffffffu, p, o);
        if (lane == 0) lg[h][f] = p;
    }
    __syncwarp();
    float mx = -1e30f;
#pragma unroll
    for (int f = 0; f < Ff; f++) mx = fmaxf(mx, lg[h][f]);
    float s = 0.f;
#pragma unroll
    for (int f = 0; f < Ff; f++) s += expf(lg[h][f] - mx);
    float inv = 1.f / s;
    if (lane < Ff) {
        float w = expf(lg[h][lane] - mx) * inv;
        wts[h][lane] = w;
        int b = bn / Nn, n = bn - b * Nn;
        outAttn[(((long long)(b * Hh + h)) * Nn + n) * Ff + lane] = w;
    }
    __syncwarp();
    float* xw = g_s + OXW + ((long long)bn * Hh + h) * Cc;
#pragma unroll
    for (int i = 0; i < 24; i++) {
        float acc = 0.f;
#pragma unroll
        for (int f = 0; f < Ff; f++) acc += wts[h][f] * xos[f * Cc + lane + 32 * i];
        xw[lane + 32 * i] = acc;
    }
}

// ------------------------- launch -------------------------------------------
extern "C" void kernel_launch(void* const* d_in, const int*, int, void* d_out, int) {
    const float* x     = (const float*)d_in[0];
    const float* Wqkv  = (const float*)d_in[1];
    const float* Wpq   = (const float*)d_in[2];
    const float* Wpkv  = (const float*)d_in[3];
    const float* Wproj = (const float*)d_in[4];
    const float* bproj = (const float*)d_in[5];
    float* out = (float*)d_out;

    float* sc = nullptr;
    cudaGetSymbolAddress((void**)&sc, g_s);

    const int fps_smem = Dd * NS * (int)sizeof(float);       // 100352 B
    cudaFuncSetAttribute(fps_kernel5, cudaFuncAttributeMaxDynamicSharedMemorySize, fps_smem);
    const int at2_smem = Ff * Cc * (int)sizeof(float);       // 49152 B
    cudaFuncSetAttribute(attn2_kernel, cudaFuncAttributeMaxDynamicSharedMemorySize, at2_smem);

    // 1a) q = x @ Wqkv[:, 0:768]  (3xTF32 — FPS needs near-fp32 q)
    gemm_tf32<128,4,true,EpiQ><<<dim3(6,49,1),256>>>(
        x, Wqkv, Cc, Cc, 3*Cc, 0, 0, EpiQ{});
    // 1b) k,v = x @ Wqkv[:, 768:2304]  (plain tf32 — feeds softmaxed logits / x1)
    gemm_tf32<128,4,false,EpiKV><<<dim3(12,49,1),256>>>(
        x, Wqkv + Cc, Cc, Cc, 3*Cc, 0, 0, EpiKV{});
    norm_kernel<<<9408,256>>>();
    fps_kernel5<<<BH*FB,256,fps_smem>>>();
    gather_lm<<<384,256>>>();
    // kernel_1 logits + fused row softmax
    k1_softmax_kernel<<<dim3(1,49,BH),256>>>();
    gemm_kernel<128,64,16,8,4,true,EpiK2><<<dim3(49,1,BH),256>>>(
        sc+OLM, sc+OKk, Ll, Nn, Dd, Dd, Dd,
        (long long)Ll*Dd,0, (long long)Nn*Dd,0, 1, EpiK2{});
    softmax196<<<6144,256>>>();
    gemm_kernel<128,64,16,8,4,false,EpiX1><<<dim3(1,1,BH*Ff),256>>>(
        sc+OK2, sc+OV, Ll, Dd, PPAD, Ff*PPAD, Dd,
        (long long)Ll*Ff*PPAD, PPAD, (long long)Nn*Dd, (long long)Pp*Dd, Ff, EpiX1{});
    // xo = kernel_1 @ x1  (tf32)
    gemm_tf32<64,4,false,EpiXO><<<dim3(8,49,BH),256>>>(
        sc+OK1, sc+OX1, Ll, Ll, Ff*Dd,
        (long long)Nn*Ll, (long long)Ll*Ff*Dd, EpiXO{});
    // q2 = xdiag @ W_pq  (tf32, scaled)
    gemm_tf32<128,4,false,EpiQ2><<<dim3(6,49,1),256>>>(
        sc+OXD, Wpq, Cc, Cc, Cc, 0, 0, EpiQ2{});
    // Wk^T for the U GEMM
    transpose_wk<<<dim3(24,24),dim3(32,8)>>>(Wpkv);
    // u[n,h,:] = Wk_h^T @ q2[n,h,:]  (batched over h, plain tf32)
    gemm_tf32<128,4,false,EpiU><<<dim3(6,49,Hh),256>>>(
        sc+OQ2, sc+OWKT, Dd, Cc, Cc, 64, (long long)64*Cc, EpiU{});
    // fused logits + softmax + attn-out + weighted xo
    attn2_kernel<<<Bb*Nn,384,at2_smem>>>(out + (long long)Bb*Nn*Cc);
    // ao = xo_w @ Wv_h  (batched over h, tf32)
    gemm_tf32<128,2,false,EpiAO><<<dim3(1,49,Hh),256>>>(
        sc+OXW, Wpkv + Cc, Cc, Hh*Cc, 2*Cc, Cc, 64, EpiAO{});
    // out = ao @ W_proj + b  (tf32)
    gemm_tf32<128,4,false,EpiOut><<<dim3(6,49,1),256>>>(
        sc+OAO, Wproj, Cc, Cc, Cc, 0, 0, EpiOut{out, bproj});
}

// round 15
// speedup vs baseline: 1.2503x; 1.0469x over previous
#include <cuda_runtime.h>

#define PRNG_VARIANT 0  // 0 = threefry_partitionable (modern JAX default), 1 = legacy

namespace ta {
constexpr int Bb=2, Hh=12, BH=24, Ff=16, Pp=196, Nn=3136, Cc=768, Dd=64, Ll=128, PPAD=208;
constexpr int FB=8, NS=Nn/FB, NC2=NS/2, NCF=NS/4;
constexpr int KVT=588, TRT=576;                       // kv tiles, transpose tiles
constexpr int GRID_MEGA=((BH*FB+KVT+TRT+FB-1)/FB)*FB; // 1360
constexpr long long QS = (long long)BH*Nn*Dd;
constexpr long long OQ=0, OKk=OQ+QS, OV=OKk+QS, OQKN=OV+QS, OLM=OQKN+QS;
constexpr long long OK1=OLM+(long long)BH*Ll*Dd;
constexpr long long OK2=OK1+(long long)BH*Nn*Ll;
constexpr long long OX1=OK2+(long long)BH*Ll*Ff*PPAD;
constexpr long long OXO=OX1+(long long)BH*Ll*Ff*Dd;
constexpr long long OXD=OXO+(long long)Bb*Nn*Ff*Cc;
constexpr long long OQ2=OXD+(long long)Bb*Nn*Cc;
constexpr long long OU =OQ2+(long long)Bb*Nn*Cc;
constexpr long long OXW=OU +(long long)Bb*Nn*Hh*Cc;
constexpr long long OWKT=OXW+(long long)Bb*Nn*Hh*Cc;
constexpr long long OAO=OWKT+(long long)Cc*Cc;
constexpr long long TOT=OAO+(long long)Bb*Nn*Cc;
}
__device__ float g_s[ta::TOT];
__device__ int   g_idx[ta::BH*ta::Ll];

using namespace ta;

// ------------------------- threefry2x32 (general key) -----------------------
__device__ __forceinline__ void tf(unsigned k0, unsigned k1, unsigned x0, unsigned x1,
                                   unsigned &y0, unsigned &y1) {
    const unsigned k2 = 0x1BD11BDAu ^ k0 ^ k1;
    x0 += k0; x1 += k1;
#define TFR(r) { x0 += x1; x1 = (x1<<(r))|(x1>>(32-(r))); x1 ^= x0; }
    TFR(13) TFR(15) TFR(26) TFR(6)   x0 += k1; x1 += k2 + 1u;
    TFR(17) TFR(29) TFR(16) TFR(24)  x0 += k2; x1 += k0 + 2u;
    TFR(13) TFR(15) TFR(26) TFR(6)   x0 += k0; x1 += k1 + 3u;
    TFR(17) TFR(29) TFR(16) TFR(24)  x0 += k1; x1 += k2 + 4u;
    TFR(13) TFR(15) TFR(26) TFR(6)   x0 += k2; x1 += k0 + 5u;
#undef TFR
    y0 = x0; y1 = x1;
}

__device__ int jax_idx0(int i) {
    const unsigned span = (unsigned)Nn;
    const unsigned mult = 2048u;
    unsigned hi, lo;
#if PRNG_VARIANT == 0
    unsigned a0,a1,b0,b1,y0,y1;
    tf(0u,42u, 0u,0u, a0,a1);
    tf(0u,42u, 0u,1u, b0,b1);
    tf(a0,a1, 0u,(unsigned)i, y0,y1); hi = y0 ^ y1;
    tf(b0,b1, 0u,(unsigned)i, y0,y1); lo = y0 ^ y1;
#else
    unsigned s00,s01,s10,s11,y0,y1;
    tf(0u,42u, 0u,2u, s00,s01);
    tf(0u,42u, 1u,3u, s10,s11);
    unsigned k1a=s00, k1b=s10, k2a=s01, k2b=s11;
    if (i < 12) { tf(k1a,k1b,(unsigned)i,(unsigned)(i+12),y0,y1); hi = y0; }
    else        { tf(k1a,k1b,(unsigned)(i-12),(unsigned)i,y0,y1); hi = y1; }
    if (i < 12) { tf(k2a,k2b,(unsigned)i,(unsigned)(i+12),y0,y1); lo = y0; }
    else        { tf(k2a,k2b,(unsigned)(i-12),(unsigned)i,y0,y1); lo = y1; }
#endif
    return (int)((((hi % span) * mult) + (lo % span)) % span);
}

// ------------------------- generic tiled f32 SIMT GEMM ----------------------
template <int BM, int BN, int BK, int TM, int TN, bool NT, class Epi>
__global__ __launch_bounds__(256) void gemm_kernel(
    const float* __restrict__ A, const float* __restrict__ B,
    int M, int N, int K, int lda, int ldb,
    long long sA1, long long sA2, long long sB1, long long sB2, int zdiv, Epi epi)
{
    __shared__ float As[BK][BM];
    __shared__ float Bs[BK][BN];
    const int z = blockIdx.z, za = z / zdiv, zb = z % zdiv;
    A += za * sA1 + zb * sA2;
    B += za * sB1 + zb * sB2;
    const int m0 = blockIdx.y * BM, n0 = blockIdx.x * BN;
    const int tid = threadIdx.x;
    const int tx = tid % (BN / TN), ty = tid / (BN / TN);
    float acc[TM][TN];
#pragma unroll
    for (int i = 0; i < TM; i++)
#pragma unroll
        for (int j = 0; j < TN; j++) acc[i][j] = 0.f;

    for (int k0 = 0; k0 < K; k0 += BK) {
        for (int i = tid; i < BM * BK / 4; i += 256) {
            int m = i / (BK / 4), kq = i % (BK / 4);
            float4 v = *(const float4*)(A + (long long)(m0 + m) * lda + k0 + kq * 4);
            As[kq*4+0][m] = v.x; As[kq*4+1][m] = v.y; As[kq*4+2][m] = v.z; As[kq*4+3][m] = v.w;
        }
        if (!NT) {
            for (int i = tid; i < BK * BN / 4; i += 256) {
                int kk = i / (BN / 4), nq = i % (BN / 4);
                *(float4*)&Bs[kk][nq*4] = *(const float4*)(B + (long long)(k0 + kk) * ldb + n0 + nq * 4);
            }
        } else {
            for (int i = tid; i < BN * BK / 4; i += 256) {
                int n = i / (BK / 4), kq = i % (BK / 4);
                float4 v = *(const float4*)(B + (long long)(n0 + n) * ldb + k0 + kq * 4);
                Bs[kq*4+0][n] = v.x; Bs[kq*4+1][n] = v.y; Bs[kq*4+2][n] = v.z; Bs[kq*4+3][n] = v.w;
            }
        }
        __syncthreads();
#pragma unroll
        for (int kk = 0; kk < BK; kk++) {
            float a[TM], b[TN];
#pragma unroll
            for (int i = 0; i < TM; i++) a[i] = As[kk][ty * TM + i];
#pragma unroll
            for (int j = 0; j < TN; j++) b[j] = Bs[kk][tx * TN + j];
#pragma unroll
            for (int i = 0; i < TM; i++)
#pragma unroll
                for (int j = 0; j < TN; j++) acc[i][j] += a[i] * b[j];
        }
        __syncthreads();
    }
#pragma unroll
    for (int i = 0; i < TM; i++)
#pragma unroll
        for (int j = 0; j < TN; j++)
            epi(z, m0 + ty * TM + i, n0 + tx * TN + j, acc[i][j]);
}

// --------- K1 logits GEMM with fused row softmax ----------------------------
__global__ __launch_bounds__(256) void k1_softmax_kernel() {
    constexpr int BM = 64, BK = 16, TM = 4, TN = 8;
    __shared__ float As[BK][BM];
    __shared__ float Bs[BK][128];
    const int z = blockIdx.z;
    const float* A = g_s + OQ  + (long long)z * Nn * Dd;
    const float* B = g_s + OLM + (long long)z * Ll * Dd;
    const int m0 = blockIdx.y * BM;
    const int tid = threadIdx.x;
    const int tx = tid % 16, ty = tid / 16;
    float acc[TM][TN];
#pragma unroll
    for (int i = 0; i < TM; i++)
#pragma unroll
        for (int j = 0; j < TN; j++) acc[i][j] = 0.f;

    for (int k0 = 0; k0 < Dd; k0 += BK) {
        for (int i = tid; i < BM * BK / 4; i += 256) {
            int m = i / 4, kq = i % 4;
            float4 v = *(const float4*)(A + (long long)(m0 + m) * Dd + k0 + kq * 4);
            As[kq*4+0][m] = v.x; As[kq*4+1][m] = v.y; As[kq*4+2][m] = v.z; As[kq*4+3][m] = v.w;
        }
        for (int i = tid; i < 128 * BK / 4; i += 256) {
            int n = i / 4, kq = i % 4;
            float4 v = *(const float4*)(B + (long long)n * Dd + k0 + kq * 4);
            Bs[kq*4+0][n] = v.x; Bs[kq*4+1][n] = v.y; Bs[kq*4+2][n] = v.z; Bs[kq*4+3][n] = v.w;
        }
        __syncthreads();
#pragma unroll
        for (int kk = 0; kk < BK; kk++) {
            float a[TM], b[TN];
#pragma unroll
            for (int i = 0; i < TM; i++) a[i] = As[kk][ty * TM + i];
#pragma unroll
            for (int j = 0; j < TN; j++) b[j] = Bs[kk][tx * TN + j];
#pragma unroll
            for (int i = 0; i < TM; i++)
#pragma unroll
                for (int j = 0; j < TN; j++) acc[i][j] += a[i] * b[j];
        }
        __syncthreads();
    }
#pragma unroll
    for (int i = 0; i < TM; i++) {
        float mx = acc[i][0];
#pragma unroll
        for (int j = 1; j < TN; j++) mx = fmaxf(mx, acc[i][j]);
#pragma unroll
        for (int o = 1; o < 16; o <<= 1) mx = fmaxf(mx, __shfl_xor_sync(0xffffffffu, mx, o));
        float e[TN], s = 0.f;
#pragma unroll
        for (int j = 0; j < TN; j++) { e[j] = expf(acc[i][j] - mx); s += e[j]; }
#pragma unroll
        for (int o = 1; o < 16; o <<= 1) s += __shfl_xor_sync(0xffffffffu, s, o);
        float inv = 1.f / s;
        long long base = OK1 + ((long long)z * Nn + m0 + ty * TM + i) * Ll + tx * 8;
        *(float4*)&g_s[base]     = make_float4(e[0]*inv, e[1]*inv, e[2]*inv, e[3]*inv);
        *(float4*)&g_s[base + 4] = make_float4(e[4]*inv, e[5]*inv, e[6]*inv, e[7]*inv);
    }
}

// ------------------------- tf32 tensor-core GEMM (cp.async 3-stage) ---------
__device__ __forceinline__ float to_tf32(float x) {
    float r; asm("cvt.rna.tf32.f32 %0, %1;" : "=f"(r) : "f"(x)); return r;
}
__device__ __forceinline__ void mma_tf32(float (&d)[4], const float (&a)[4], const float (&b)[2]) {
    asm volatile("mma.sync.aligned.m16n8k8.row.col.f32.tf32.tf32.f32 "
        "{%0,%1,%2,%3}, {%4,%5,%6,%7}, {%8,%9}, {%0,%1,%2,%3};"
        : "+f"(d[0]), "+f"(d[1]), "+f"(d[2]), "+f"(d[3])
        : "r"(__float_as_uint(a[0])), "r"(__float_as_uint(a[1])),
          "r"(__float_as_uint(a[2])), "r"(__float_as_uint(a[3])),
          "r"(__float_as_uint(b[0])), "r"(__float_as_uint(b[1])));
}
__device__ __forceinline__ void cpa16(float* dst, const float* src) {
    unsigned s = (unsigned)__cvta_generic_to_shared(dst);
    asm volatile("cp.async.cg.shared.global [%0], [%1], 16;" :: "r"(s), "l"(src));
}

template <int BM, int WN, bool X3, class Epi>
__global__ __launch_bounds__(256) void gemm_tf32(
    const float* __restrict__ A, const float* __restrict__ B,
    int K, int lda, int ldb, long long sA1, long long sB1, Epi epi)
{
    constexpr int BN = WN * 32, BK = 16;
    constexpr int LDA_S = BK + 4;
    constexpr int LDB_S = BN + 8;
    constexpr int MF = (BM * WN) / 128;
    __shared__ float As[3][BM * LDA_S];
    __shared__ float Bs[3][BK * LDB_S];
    const int z = blockIdx.z;
    const int m0 = blockIdx.y * BM, n0 = blockIdx.x * BN;
    const float* Ab = A + (long long)z * sA1 + (long long)m0 * lda;
    const float* Bb = B + (long long)z * sB1 + n0;
    const int tid = threadIdx.x, wid = tid >> 5, lane = tid & 31;
    const int wm = (wid / WN) * (16 * MF), wn = (wid % WN) * 32;
    const int g = lane >> 2, t = lane & 3;

    float acc[MF][4][4];
#pragma unroll
    for (int i = 0; i < MF; i++)
#pragma unroll
        for (int j = 0; j < 4; j++)
#pragma unroll
            for (int r = 0; r < 4; r++) acc[i][j][r] = 0.f;

    auto stage_load = [&](int s, int k0) {
#pragma unroll
        for (int i = tid; i < BM * 4; i += 256) {
            int m = i >> 2, kq = i & 3;
            cpa16(&As[s][m * LDA_S + kq * 4], Ab + (long long)m * lda + k0 + kq * 4);
        }
#pragma unroll
        for (int i = tid; i < BK * (BN / 4); i += 256) {
            int kk = i / (BN / 4), nq = i % (BN / 4);
            cpa16(&Bs[s][kk * LDB_S + nq * 4], Bb + (long long)(k0 + kk) * ldb + nq * 4);
        }
        asm volatile("cp.async.commit_group;");
    };

    const int KT = K / BK;
    stage_load(0, 0);
    if (KT > 1) stage_load(1, BK);
    for (int kt = 0; kt < KT; kt++) {
        const int s = kt % 3;
        if (kt + 2 < KT) {
            stage_load((kt + 2) % 3, (kt + 2) * BK);
            asm volatile("cp.async.wait_group 2;");
        } else if (kt + 1 < KT) {
            asm volatile("cp.async.wait_group 1;");
        } else {
            asm volatile("cp.async.wait_group 0;");
        }
        __syncthreads();
#pragma unroll
        for (int ks = 0; ks < 2; ks++) {
            const int kb = ks * 8;
            float a[MF][4], b[4][2];
            float al[MF][4], bl[4][2];
#pragma unroll
            for (int mf = 0; mf < MF; mf++) {
                int ml = wm + mf * 16 + g;
                float r0 = As[s][ ml      * LDA_S + kb + t];
                float r1 = As[s][(ml + 8) * LDA_S + kb + t];
                float r2 = As[s][ ml      * LDA_S + kb + t + 4];
                float r3 = As[s][(ml + 8) * LDA_S + kb + t + 4];
                a[mf][0] = to_tf32(r0); a[mf][1] = to_tf32(r1);
                a[mf][2] = to_tf32(r2); a[mf][3] = to_tf32(r3);
                if (X3) {
                    al[mf][0] = to_tf32(r0 - a[mf][0]); al[mf][1] = to_tf32(r1 - a[mf][1]);
                    al[mf][2] = to_tf32(r2 - a[mf][2]); al[mf][3] = to_tf32(r3 - a[mf][3]);
                }
            }
#pragma unroll
            for (int nf = 0; nf < 4; nf++) {
                int nb = wn + nf * 8 + g;
                float r0 = Bs[s][(kb + t)     * LDB_S + nb];
                float r1 = Bs[s][(kb + t + 4) * LDB_S + nb];
                b[nf][0] = to_tf32(r0); b[nf][1] = to_tf32(r1);
                if (X3) {
                    bl[nf][0] = to_tf32(r0 - b[nf][0]); bl[nf][1] = to_tf32(r1 - b[nf][1]);
                }
            }
#pragma unroll
            for (int mf = 0; mf < MF; mf++)
#pragma unroll
                for (int nf = 0; nf < 4; nf++) {
                    mma_tf32(acc[mf][nf], a[mf], b[nf]);
                    if (X3) {
                        mma_tf32(acc[mf][nf], al[mf], b[nf]);
                        mma_tf32(acc[mf][nf], a[mf], bl[nf]);
                    }
                }
        }
        __syncthreads();
    }
#pragma unroll
    for (int mf = 0; mf < MF; mf++) {
        int m = m0 + wm + mf * 16 + g;
#pragma unroll
        for (int nf = 0; nf < 4; nf++) {
            int n = n0 + wn + nf * 8 + 2 * t;
            epi(z, m,     n,     acc[mf][nf][0]);
            epi(z, m,     n + 1, acc[mf][nf][1]);
            epi(z, m + 8, n,     acc[mf][nf][2]);
            epi(z, m + 8, n + 1, acc[mf][nf][3]);
        }
    }
}

// ------------------------- epilogues ----------------------------------------
struct EpiQ {
    __device__ void operator()(int, int m, int n, float v) const {
        int hh = n >> 6, dd = n & 63;
        int b = m / Nn, nn = m - b * Nn;
        g_s[OQ + (((long long)(b * Hh + hh)) * Nn + nn) * Dd + dd]
            = v * 0.35355339059327378f;
    }
};
struct EpiKV {
    __device__ void operator()(int, int m, int n, float v) const {
        int part = n / Cc, c = n - part * Cc;
        int hh = c >> 6, dd = c & 63;
        int b = m / Nn, nn = m - b * Nn;
        long long idx = (((long long)(b * Hh + hh)) * Nn + nn) * Dd + dd;
        if (part == 0) g_s[OKk + idx] = v * 0.35355339059327378f;
        else           g_s[OV  + idx] = v;
    }
};
struct EpiK2 {
    __device__ void operator()(int z, int m, int n, float v) const {
        int f = n / Pp, p = n - f * Pp;
        g_s[OK2 + (((long long)z * Ll + m) * Ff + f) * PPAD + p] = v;
    }
};
struct EpiX1 {
    __device__ void operator()(int z, int m, int n, float v) const {
        int bh = z >> 4, f = z & 15;
        g_s[OX1 + (((long long)bh * Ll + m) * Ff + f) * Dd + n] = v;
    }
};
struct EpiXO {
    __device__ void operator()(int z, int m, int n, float v) const {
        int b = z / Hh, hh = z - b * Hh;
        int f = n >> 6, dd = n & 63;
        long long base = (long long)(b * Nn + m);
        g_s[OXO + (base * Ff + f) * Cc + hh * Dd + dd] = v;
        if (f == m / Pp) g_s[OXD + base * Cc + hh * Dd + dd] = v;
    }
};
struct EpiQ2 {
    __device__ void operator()(int, int m, int n, float v) const {
        g_s[OQ2 + (long long)m * Cc + n] = v * 0.125f;
    }
};
struct EpiU {
    __device__ void operator()(int z, int m, int n, float v) const {
        g_s[OU + ((long long)m * Hh + z) * Cc + n] = v;
    }
};
struct EpiAO {
    __device__ void operator()(int z, int m, int n, float v) const {
        g_s[OAO + (long long)m * Cc + z * 64 + n] = v;
    }
};
struct EpiOut {
    float* out; const float* bias;
    __device__ void operator()(int, int m, int n, float v) const {
        out[(long long)m * Cc + n] = v + bias[n];
    }
};

// ------------------------- small kernels ------------------------------------
__global__ void norm_kernel() {
    long long gw = (long long)blockIdx.x * 8 + (threadIdx.x >> 5);
    int lane = threadIdx.x & 31;
    float2 v = ((const float2*)(g_s + OQ + gw * Dd))[lane];
    float ss = v.x * v.x + v.y * v.y;
#pragma unroll
    for (int o = 16; o; o >>= 1) ss += __shfl_xor_sync(0xffffffffu, ss, o);
    float dnm = fmaxf(sqrtf(ss), 1e-12f);
    int bh = (int)(gw / Nn), n = (int)(gw - (long long)bh * Nn);
    long long base = OQKN + (long long)bh * Nn * Dd;
    g_s[base + (long long)(2 * lane)     * Nn + n] = v.x / dnm;
    g_s[base + (long long)(2 * lane + 1) * Nn + n] = v.y / dnm;
}

__device__ __forceinline__ unsigned ctarank() {
    unsigned r; asm("mov.u32 %0, %%cluster_ctarank;" : "=r"(r)); return r;
}
__device__ __forceinline__ unsigned mapa_u32(unsigned addr, unsigned rank) {
    unsigned r; asm("mapa.shared::cluster.u32 %0, %1, %2;" : "=r"(r) : "r"(addr), "r"(rank));
    return r;
}

// ---- MEGA kernel: FPS clusters + kv-GEMM tiles + Wk transpose tiles --------
// blocks [0,192): FPS (identical to fps_kernel5); [192,780): kv tf32 tiles
// (same mapping as the standalone launch); [780,1356): transpose tiles.
__global__ __launch_bounds__(256) __cluster_dims__(FB, 1, 1) void mega_kernel(
    const float* __restrict__ x, const float* __restrict__ Wqkv,
    const float* __restrict__ Wpkv)
{
    extern __shared__ float ssm[];
    const int bx = blockIdx.x;
    const int tid = threadIdx.x;

    if (bx < BH * FB) {
        // ======================= FPS path =======================
        __shared__ unsigned long long cand[2][FB];
        __shared__ float cur[Dd];
        __shared__ float s_val[8];
        __shared__ int   s_idx[8], s_pick;
        const int b = bx / FB;
        const int j = (int)ctarank();
        const float* qkT = g_s + OQKN + (long long)b * Nn * Dd;
        for (int i = tid; i < Dd * NCF; i += 256) {
            int d = i / NCF, c = i % NCF;
            *(float4*)&ssm[d * NS + 4 * c] =
                *(const float4*)(qkT + (long long)d * Nn + j * NS + 4 * c);
        }
        float ms0 = 0.f, ms1 = 0.f;
        if (tid == 0) {
            int i0 = jax_idx0(b);
            if (j == 0) g_idx[b * Ll] = i0;
            s_pick = i0;
        }
        __syncthreads();
        int pick = s_pick;
        if (tid < Dd) cur[tid] = qkT[(long long)tid * Nn + pick];
        if (tid == (pick >> 1) - j * NC2) {
            if (pick & 1) ms1 = 10.f; else ms0 = 10.f;
        }
        __syncthreads();
        const int lane = tid & 31, wid = tid >> 5;
        const unsigned candBase = (unsigned)__cvta_generic_to_shared(&cand[0][0]);
        for (int step = 1; step < Ll; step++) {
            float bv = 3.4e38f; int bi = 0x7fffffff;
            if (tid < NC2) {
                float ax = 0.f, ay = 0.f;
#pragma unroll
                for (int d = 0; d < Dd; d++) {
                    float2 v = *(const float2*)&ssm[d * NS + 2 * tid];
                    float c = cur[d];
                    ax += v.x * c; ay += v.y * c;
                }
                ms0 = fmaxf(ms0, fabsf(ax)); ms1 = fmaxf(ms1, fabsf(ay));
                int nb = j * NS + 2 * tid;
                bv = ms0; bi = nb;
                if (ms1 < bv) { bv = ms1; bi = nb + 1; }
            }
#pragma unroll
            for (int o = 16; o; o >>= 1) {
                float ov = __shfl_down_sync(0xffffffffu, bv, o);
                int   oi = __shfl_down_sync(0xffffffffu, bi, o);
                if (ov < bv || (ov == bv && oi < bi)) { bv = ov; bi = oi; }
            }
            if (lane == 0) { s_val[wid] = bv; s_idx[wid] = bi; }
            __syncthreads();
            const int par = step & 1;
            if (tid == 0) {
#pragma unroll
                for (int w = 0; w < 8; w++) {
                    float ov = s_val[w]; int oi = s_idx[w];
                    if (w == 0 || ov < bv || (ov == bv && oi < bi)) { bv = ov; bi = oi; }
                }
                unsigned long long packed =
                    ((unsigned long long)__float_as_uint(bv) << 32) | (unsigned)bi;
                unsigned slot = candBase + (unsigned)((par * FB + j) * 8);
#pragma unroll
                for (int jj = 0; jj < FB; jj++) {
                    unsigned raddr = mapa_u32(slot, (unsigned)jj);
                    asm volatile("st.shared::cluster.b64 [%0], %1;" :: "r"(raddr), "l"(packed));
                }
            }
            asm volatile("barrier.cluster.arrive.aligned;" ::: "memory");
            asm volatile("barrier.cluster.wait.aligned;" ::: "memory");
            unsigned long long best = cand[par][0];
#pragma unroll
            for (int jj = 1; jj < FB; jj++) {
                unsigned long long c2 = cand[par][jj];
                if (c2 < best) best = c2;
            }
            pick = (int)(unsigned)(best & 0xffffffffull);
            if (j == 0 && tid == 0) g_idx[b * Ll + step] = pick;
            if (tid < Dd) cur[tid] = qkT[(long long)tid * Nn + pick];
            if (tid == (pick >> 1) - j * NC2) {
                if (pick & 1) ms1 = 10.f; else ms0 = 10.f;
            }
            __syncthreads();
        }
    } else if (bx < BH * FB + KVT) {
        // ======================= kv tf32 GEMM tile =======================
        constexpr int BMk = 128, BNk = 128, BKk = 16;
        constexpr int LDAk = BKk + 4, LDBk = BNk + 8;
        const int t0 = bx - BH * FB;
        const int m0 = (t0 / 12) * BMk;
        const int n0 = (t0 % 12) * BNk;
        float* As = ssm;                       // [3][128*20]
        float* Bs = ssm + 3 * BMk * LDAk;      // [3][16*136]
        const float* Ab = x + (long long)m0 * Cc;
        const float* Bb = Wqkv + Cc + n0;      // k,v columns (offset 768)
        const int wid = tid >> 5, lane = tid & 31;
        const int wm = (wid >> 2) * 64, wn = (wid & 3) * 32;
        const int g = lane >> 2, tt = lane & 3;
        EpiKV epi{};

        float acc[4][4][4];
#pragma unroll
        for (int i = 0; i < 4; i++)
#pragma unroll
            for (int j2 = 0; j2 < 4; j2++)
#pragma unroll
                for (int r = 0; r < 4; r++) acc[i][j2][r] = 0.f;

        auto stage_load = [&](int s, int k0) {
#pragma unroll
            for (int i = tid; i < BMk * 4; i += 256) {
                int m = i >> 2, kq = i & 3;
                cpa16(&As[s * BMk * LDAk + m * LDAk + kq * 4],
                      Ab + (long long)m * Cc + k0 + kq * 4);
            }
#pragma unroll
            for (int i = tid; i < BKk * (BNk / 4); i += 256) {
                int kk = i / (BNk / 4), nq = i % (BNk / 4);
                cpa16(&Bs[s * BKk * LDBk + kk * LDBk + nq * 4],
                      Bb + (long long)(k0 + kk) * (3 * Cc) + nq * 4);
            }
            asm volatile("cp.async.commit_group;");
        };

        const int KT2 = Cc / BKk;   // 48
        stage_load(0, 0);
        stage_load(1, BKk);
        for (int kt = 0; kt < KT2; kt++) {
            const int s = kt % 3;
            if (kt + 2 < KT2) {
                stage_load((kt + 2) % 3, (kt + 2) * BKk);
                asm volatile("cp.async.wait_group 2;");
            } else if (kt + 1 < KT2) {
                asm volatile("cp.async.wait_group 1;");
            } else {
                asm volatile("cp.async.wait_group 0;");
            }
            __syncthreads();
#pragma unroll
            for (int ks = 0; ks < 2; ks++) {
                const int kb = ks * 8;
                float a[4][4], b[4][2];
#pragma unroll
                for (int mf = 0; mf < 4; mf++) {
                    int ml = wm + mf * 16 + g;
                    a[mf][0] = to_tf32(As[s * BMk * LDAk +  ml      * LDAk + kb + tt]);
                    a[mf][1] = to_tf32(As[s * BMk * LDAk + (ml + 8) * LDAk + kb + tt]);
                    a[mf][2] = to_tf32(As[s * BMk * LDAk +  ml      * LDAk + kb + tt + 4]);
                    a[mf][3] = to_tf32(As[s * BMk * LDAk + (ml + 8) * LDAk + kb + tt + 4]);
                }
#pragma unroll
                for (int nf = 0; nf < 4; nf++) {
                    int nb = wn + nf * 8 + g;
                    b[nf][0] = to_tf32(Bs[s * BKk * LDBk + (kb + tt)     * LDBk + nb]);
                    b[nf][1] = to_tf32(Bs[s * BKk * LDBk + (kb + tt + 4) * LDBk + nb]);
                }
#pragma unroll
                for (int mf = 0; mf < 4; mf++)
#pragma unroll
                    for (int nf = 0; nf < 4; nf++)
                        mma_tf32(acc[mf][nf], a[mf], b[nf]);
            }
            __syncthreads();
        }
#pragma unroll
        for (int mf = 0; mf < 4; mf++) {
            int m = m0 + wm + mf * 16 + g;
#pragma unroll
            for (int nf = 0; nf < 4; nf++) {
                int n = n0 + wn + nf * 8 + 2 * tt;
                epi(0, m,     n,     acc[mf][nf][0]);
                epi(0, m,     n + 1, acc[mf][nf][1]);
                epi(0, m + 8, n,     acc[mf][nf][2]);
                epi(0, m + 8, n + 1, acc[mf][nf][3]);
            }
        }
    } else if (bx < BH * FB + KVT + TRT) {
        // ======================= Wk transpose tile =======================
        __shared__ float tsm[32][33];
        const int t2 = bx - (BH * FB + KVT);
        int j0 = (t2 % 24) * 32, c0 = (t2 / 24) * 32;
        int tx = tid & 31, ty = tid >> 5;
#pragma unroll
        for (int i = 0; i < 32; i += 8)
            tsm[ty + i][tx] = Wpkv[(long long)(c0 + ty + i) * (2 * Cc) + j0 + tx];
        __syncthreads();
#pragma unroll
        for (int i = 0; i < 32; i += 8)
            g_s[OWKT + (long long)(j0 + ty + i) * Cc + c0 + tx] = tsm[tx][ty + i];
    }
}

__global__ void gather_lm() {
    int gw = blockIdx.x * 8 + (threadIdx.x >> 5);
    int lane = threadIdx.x & 31;
    int bh = gw >> 7;
    int idx = g_idx[gw];
    ((float2*)(g_s + OLM + (long long)gw * Dd))[lane] =
        ((const float2*)(g_s + OQ + ((long long)bh * Nn + idx) * Dd))[lane];
}

__global__ void softmax196() {
    long long r = (long long)blockIdx.x * 8 + (threadIdx.x >> 5);
    int lane = threadIdx.x & 31;
    float* row = g_s + OK2 + r * PPAD;
    float v[7], mx = -1e30f;
#pragma unroll
    for (int j = 0; j < 7; j++) { int i = lane + 32*j; v[j] = (i < Pp) ? row[i] : -1e30f; mx = fmaxf(mx, v[j]); }
#pragma unroll
    for (int o = 16; o; o >>= 1) mx = fmaxf(mx, __shfl_xor_sync(0xffffffffu, mx, o));
    float s = 0.f;
#pragma unroll
    for (int j = 0; j < 7; j++) { int i = lane + 32*j; if (i < Pp) { v[j] = expf(v[j] - mx); s += v[j]; } }
#pragma unroll
    for (int o = 16; o; o >>= 1) s += __shfl_xor_sync(0xffffffffu, s, o);
    float inv = 1.f / s;
#pragma unroll
    for (int j = 0; j < 7; j++) { int i = lane + 32*j; if (i < Pp) row[i] = v[j] * inv; }
    if (lane < PPAD - Pp) row[Pp + lane] = 0.f;
}

__global__ __launch_bounds__(384) void attn2_kernel(float* outAttn) {
    extern __shared__ float xos[];
    __shared__ float lg[Hh][Ff];
    __shared__ float wts[Hh][Ff];
    const int bn = blockIdx.x;
    const int tid = threadIdx.x, h = tid >> 5, lane = tid & 31;
    const float* xsrc = g_s + OXO + (long long)bn * Ff * Cc;
    for (int i = tid; i < Ff * Cc / 4; i += 384)
        ((float4*)xos)[i] = ((const float4*)xsrc)[i];
    float ureg[24];
    const float* urow = g_s + OU + ((long long)bn * Hh + h) * Cc;
#pragma unroll
    for (int i = 0; i < 24; i++) ureg[i] = urow[lane + 32 * i];
    __syncthreads();
#pragma unroll
    for (int f = 0; f < Ff; f++) {
        const float* xr = xos + f * Cc;
        float p = 0.f;
#pragma unroll
        for (int i = 0; i < 24; i++) p += ureg[i] * xr[lane + 32 * i];
#pragma unroll
        for (int o = 16; o; o >>= 1) p += __shfl_xor_sync(0xffffffffu, p, o);
        if (lane == 0) lg[h][f] = p;
    }
    __syncwarp();
    float mx = -1e30f;
#pragma unroll
    for (int f = 0; f < Ff; f++) mx = fmaxf(mx, lg[h][f]);
    float s = 0.f;
#pragma unroll
    for (int f = 0; f < Ff; f++) s += expf(lg[h][f] - mx);
    float inv = 1.f / s;
    if (lane < Ff) {
        float w = expf(lg[h][lane] - mx) * inv;
        wts[h][lane] = w;
        int b = bn / Nn, n = bn - b * Nn;
        outAttn[(((long long)(b * Hh + h)) * Nn + n) * Ff + lane] = w;
    }
    __syncwarp();
    float* xw = g_s + OXW + ((long long)bn * Hh + h) * Cc;
#pragma unroll
    for (int i = 0; i < 24; i++) {
        float acc = 0.f;
#pragma unroll
        for (int f = 0; f < Ff; f++) acc += wts[h][f] * xos[f * Cc + lane + 32 * i];
        xw[lane + 32 * i] = acc;
    }
}

// ------------------------- launch -------------------------------------------
extern "C" void kernel_launch(void* const* d_in, const int*, int, void* d_out, int) {
    const float* x     = (const float*)d_in[0];
    const float* Wqkv  = (const float*)d_in[1];
    const float* Wpq   = (const float*)d_in[2];
    const float* Wpkv  = (const float*)d_in[3];
    const float* Wproj = (const float*)d_in[4];
    const float* bproj = (const float*)d_in[5];
    float* out = (float*)d_out;

    float* sc = nullptr;
    cudaGetSymbolAddress((void**)&sc, g_s);

    const int fps_smem = Dd * NS * (int)sizeof(float);       // 100352 B
    cudaFuncSetAttribute(mega_kernel, cudaFuncAttributeMaxDynamicSharedMemorySize, fps_smem);
    const int at2_smem = Ff * Cc * (int)sizeof(float);       // 49152 B
    cudaFuncSetAttribute(attn2_kernel, cudaFuncAttributeMaxDynamicSharedMemorySize, at2_smem);

    // 1) q = x @ Wqkv[:, 0:768]  (3xTF32 — FPS needs near-fp32 q)
    gemm_tf32<128,4,true,EpiQ><<<dim3(6,49,1),256>>>(
        x, Wqkv, Cc, Cc, 3*Cc, 0, 0, EpiQ{});
    norm_kernel<<<9408,256>>>();
    // 2) MEGA: FPS clusters + kv GEMM tiles + Wk^T tiles (kv/trans hide under FPS)
    mega_kernel<<<GRID_MEGA,256,fps_smem>>>(x, Wqkv, Wpkv);
    gather_lm<<<384,256>>>();
    k1_softmax_kernel<<<dim3(1,49,BH),256>>>();
    gemm_kernel<128,64,16,8,4,true,EpiK2><<<dim3(49,1,BH),256>>>(
        sc+OLM, sc+OKk, Ll, Nn, Dd, Dd, Dd,
        (long long)Ll*Dd,0, (long long)Nn*Dd,0, 1, EpiK2{});
    softmax196<<<6144,256>>>();
    gemm_kernel<128,64,16,8,4,false,EpiX1><<<dim3(1,1,BH*Ff),256>>>(
        sc+OK2, sc+OV, Ll, Dd, PPAD, Ff*PPAD, Dd,
        (long long)Ll*Ff*PPAD, PPAD, (long long)Nn*Dd, (long long)Pp*Dd, Ff, EpiX1{});
    gemm_tf32<64,4,false,EpiXO><<<dim3(8,49,BH),256>>>(
        sc+OK1, sc+OX1, Ll, Ll, Ff*Dd,
        (long long)Nn*Ll, (long long)Ll*Ff*Dd, EpiXO{});
    gemm_tf32<128,4,false,EpiQ2><<<dim3(6,49,1),256>>>(
        sc+OXD, Wpq, Cc, Cc, Cc, 0, 0, EpiQ2{});
    gemm_tf32<128,4,false,EpiU><<<dim3(6,49,Hh),256>>>(
        sc+OQ2, sc+OWKT, Dd, Cc, Cc, 64, (long long)64*Cc, EpiU{});
    attn2_kernel<<<Bb*Nn,384,at2_smem>>>(out + (long long)Bb*Nn*Cc);
    gemm_tf32<128,2,false,EpiAO><<<dim3(1,49,Hh),256>>>(
        sc+OXW, Wpkv + Cc, Cc, Hh*Cc, 2*Cc, Cc, 64, EpiAO{});
    gemm_tf32<128,4,false,EpiOut><<<dim3(6,49,1),256>>>(
        sc+OAO, Wproj, Cc, Cc, Cc, 0, 0, EpiOut{out, bproj});
}

// round 16
// speedup vs baseline: 1.3131x; 1.0502x over previous
#include <cuda_runtime.h>

#define PRNG_VARIANT 0  // 0 = threefry_partitionable (modern JAX default), 1 = legacy

namespace ta {
constexpr int Bb=2, Hh=12, BH=24, Ff=16, Pp=196, Nn=3136, Cc=768, Dd=64, Ll=128, PPAD=208;
constexpr int FB=8, NS=Nn/FB, NC2=NS/2, NCF=NS/4;
constexpr int KVT=588, TRT=576;
constexpr int GRID_MEGA=((BH*FB+KVT+TRT+FB-1)/FB)*FB;
constexpr long long QS = (long long)BH*Nn*Dd;
constexpr long long OQ=0, OKk=OQ+QS, OV=OKk+QS, OQKN=OV+QS, OLM=OQKN+QS;
constexpr long long OLMT=OLM+(long long)BH*Ll*Dd;                // lm^T [bh][d][l]
constexpr long long OK1=OLMT+(long long)BH*Dd*Ll;
constexpr long long OK2=OK1+(long long)BH*Nn*Ll;
constexpr long long OX1=OK2+(long long)BH*Ll*Ff*PPAD;
constexpr long long OXO=OX1+(long long)BH*Ll*Ff*Dd;
constexpr long long OXD=OXO+(long long)Bb*Nn*Ff*Cc;
constexpr long long OQ2=OXD+(long long)Bb*Nn*Cc;
constexpr long long OU =OQ2+(long long)Bb*Nn*Cc;
constexpr long long OXW=OU +(long long)Bb*Nn*Hh*Cc;
constexpr long long OWKT=OXW+(long long)Bb*Nn*Hh*Cc;
constexpr long long OAO=OWKT+(long long)Cc*Cc;
constexpr long long TOT=OAO+(long long)Bb*Nn*Cc;
}
__device__ float g_s[ta::TOT];
__device__ int   g_idx[ta::BH*ta::Ll];

using namespace ta;

// ------------------------- threefry2x32 (general key) -----------------------
__device__ __forceinline__ void tf(unsigned k0, unsigned k1, unsigned x0, unsigned x1,
                                   unsigned &y0, unsigned &y1) {
    const unsigned k2 = 0x1BD11BDAu ^ k0 ^ k1;
    x0 += k0; x1 += k1;
#define TFR(r) { x0 += x1; x1 = (x1<<(r))|(x1>>(32-(r))); x1 ^= x0; }
    TFR(13) TFR(15) TFR(26) TFR(6)   x0 += k1; x1 += k2 + 1u;
    TFR(17) TFR(29) TFR(16) TFR(24)  x0 += k2; x1 += k0 + 2u;
    TFR(13) TFR(15) TFR(26) TFR(6)   x0 += k0; x1 += k1 + 3u;
    TFR(17) TFR(29) TFR(16) TFR(24)  x0 += k1; x1 += k2 + 4u;
    TFR(13) TFR(15) TFR(26) TFR(6)   x0 += k2; x1 += k0 + 5u;
#undef TFR
    y0 = x0; y1 = x1;
}

__device__ int jax_idx0(int i) {
    const unsigned span = (unsigned)Nn;
    const unsigned mult = 2048u;
    unsigned hi, lo;
#if PRNG_VARIANT == 0
    unsigned a0,a1,b0,b1,y0,y1;
    tf(0u,42u, 0u,0u, a0,a1);
    tf(0u,42u, 0u,1u, b0,b1);
    tf(a0,a1, 0u,(unsigned)i, y0,y1); hi = y0 ^ y1;
    tf(b0,b1, 0u,(unsigned)i, y0,y1); lo = y0 ^ y1;
#else
    unsigned s00,s01,s10,s11,y0,y1;
    tf(0u,42u, 0u,2u, s00,s01);
    tf(0u,42u, 1u,3u, s10,s11);
    unsigned k1a=s00, k1b=s10, k2a=s01, k2b=s11;
    if (i < 12) { tf(k1a,k1b,(unsigned)i,(unsigned)(i+12),y0,y1); hi = y0; }
    else        { tf(k1a,k1b,(unsigned)(i-12),(unsigned)i,y0,y1); hi = y1; }
    if (i < 12) { tf(k2a,k2b,(unsigned)i,(unsigned)(i+12),y0,y1); lo = y0; }
    else        { tf(k2a,k2b,(unsigned)(i-12),(unsigned)i,y0,y1); lo = y1; }
#endif
    return (int)((((hi % span) * mult) + (lo % span)) % span);
}

// ------------------------- tf32 tensor-core GEMM (cp.async 3-stage) ---------
__device__ __forceinline__ float to_tf32(float x) {
    float r; asm("cvt.rna.tf32.f32 %0, %1;" : "=f"(r) : "f"(x)); return r;
}
__device__ __forceinline__ void mma_tf32(float (&d)[4], const float (&a)[4], const float (&b)[2]) {
    asm volatile("mma.sync.aligned.m16n8k8.row.col.f32.tf32.tf32.f32 "
        "{%0,%1,%2,%3}, {%4,%5,%6,%7}, {%8,%9}, {%0,%1,%2,%3};"
        : "+f"(d[0]), "+f"(d[1]), "+f"(d[2]), "+f"(d[3])
        : "r"(__float_as_uint(a[0])), "r"(__float_as_uint(a[1])),
          "r"(__float_as_uint(a[2])), "r"(__float_as_uint(a[3])),
          "r"(__float_as_uint(b[0])), "r"(__float_as_uint(b[1])));
}
__device__ __forceinline__ void cpa16(float* dst, const float* src) {
    unsigned s = (unsigned)__cvta_generic_to_shared(dst);
    asm volatile("cp.async.cg.shared.global [%0], [%1], 16;" :: "r"(s), "l"(src));
}

// BM x (WN*32) x 16 tiles, 8 warps, 3-stage cp.async.
// Batch via z: za=z/zdiv, zb=z%zdiv; offsets za*s?1 + zb*s?2.
template <int BM, int WN, bool X3, class Epi>
__global__ __launch_bounds__(256) void gemm_tf32(
    const float* __restrict__ A, const float* __restrict__ B,
    int K, int lda, int ldb,
    long long sA1, long long sA2, long long sB1, long long sB2, int zdiv, Epi epi)
{
    constexpr int BN = WN * 32, BK = 16;
    constexpr int LDA_S = BK + 4;
    constexpr int LDB_S = BN + 8;
    constexpr int MF = (BM * WN) / 128;
    __shared__ float As[3][BM * LDA_S];
    __shared__ float Bs[3][BK * LDB_S];
    const int z = blockIdx.z, za = z / zdiv, zb = z % zdiv;
    const int m0 = blockIdx.y * BM, n0 = blockIdx.x * BN;
    const float* Ab = A + za * sA1 + zb * sA2 + (long long)m0 * lda;
    const float* Bb = B + za * sB1 + zb * sB2 + n0;
    const int tid = threadIdx.x, wid = tid >> 5, lane = tid & 31;
    const int wm = (wid / WN) * (16 * MF), wn = (wid % WN) * 32;
    const int g = lane >> 2, t = lane & 3;

    float acc[MF][4][4];
#pragma unroll
    for (int i = 0; i < MF; i++)
#pragma unroll
        for (int j = 0; j < 4; j++)
#pragma unroll
            for (int r = 0; r < 4; r++) acc[i][j][r] = 0.f;

    auto stage_load = [&](int s, int k0) {
#pragma unroll
        for (int i = tid; i < BM * 4; i += 256) {
            int m = i >> 2, kq = i & 3;
            cpa16(&As[s][m * LDA_S + kq * 4], Ab + (long long)m * lda + k0 + kq * 4);
        }
#pragma unroll
        for (int i = tid; i < BK * (BN / 4); i += 256) {
            int kk = i / (BN / 4), nq = i % (BN / 4);
            cpa16(&Bs[s][kk * LDB_S + nq * 4], Bb + (long long)(k0 + kk) * ldb + nq * 4);
        }
        asm volatile("cp.async.commit_group;");
    };

    const int KT = K / BK;
    stage_load(0, 0);
    if (KT > 1) stage_load(1, BK);
    for (int kt = 0; kt < KT; kt++) {
        const int s = kt % 3;
        if (kt + 2 < KT) {
            stage_load((kt + 2) % 3, (kt + 2) * BK);
            asm volatile("cp.async.wait_group 2;");
        } else if (kt + 1 < KT) {
            asm volatile("cp.async.wait_group 1;");
        } else {
            asm volatile("cp.async.wait_group 0;");
        }
        __syncthreads();
#pragma unroll
        for (int ks = 0; ks < 2; ks++) {
            const int kb = ks * 8;
            float a[MF][4], b[4][2];
            float al[MF][4], bl[4][2];
#pragma unroll
            for (int mf = 0; mf < MF; mf++) {
                int ml = wm + mf * 16 + g;
                float r0 = As[s][ ml      * LDA_S + kb + t];
                float r1 = As[s][(ml + 8) * LDA_S + kb + t];
                float r2 = As[s][ ml      * LDA_S + kb + t + 4];
                float r3 = As[s][(ml + 8) * LDA_S + kb + t + 4];
                a[mf][0] = to_tf32(r0); a[mf][1] = to_tf32(r1);
                a[mf][2] = to_tf32(r2); a[mf][3] = to_tf32(r3);
                if (X3) {
                    al[mf][0] = to_tf32(r0 - a[mf][0]); al[mf][1] = to_tf32(r1 - a[mf][1]);
                    al[mf][2] = to_tf32(r2 - a[mf][2]); al[mf][3] = to_tf32(r3 - a[mf][3]);
                }
            }
#pragma unroll
            for (int nf = 0; nf < 4; nf++) {
                int nb = wn + nf * 8 + g;
                float r0 = Bs[s][(kb + t)     * LDB_S + nb];
                float r1 = Bs[s][(kb + t + 4) * LDB_S + nb];
                b[nf][0] = to_tf32(r0); b[nf][1] = to_tf32(r1);
                if (X3) {
                    bl[nf][0] = to_tf32(r0 - b[nf][0]); bl[nf][1] = to_tf32(r1 - b[nf][1]);
                }
            }
#pragma unroll
            for (int mf = 0; mf < MF; mf++)
#pragma unroll
                for (int nf = 0; nf < 4; nf++) {
                    mma_tf32(acc[mf][nf], a[mf], b[nf]);
                    if (X3) {
                        mma_tf32(acc[mf][nf], al[mf], b[nf]);
                        mma_tf32(acc[mf][nf], a[mf], bl[nf]);
                    }
                }
        }
        __syncthreads();
    }
#pragma unroll
    for (int mf = 0; mf < MF; mf++) {
        int m = m0 + wm + mf * 16 + g;
#pragma unroll
        for (int nf = 0; nf < 4; nf++) {
            int n = n0 + wn + nf * 8 + 2 * t;
            epi(z, m,     n,     acc[mf][nf][0]);
            epi(z, m,     n + 1, acc[mf][nf][1]);
            epi(z, m + 8, n,     acc[mf][nf][2]);
            epi(z, m + 8, n + 1, acc[mf][nf][3]);
        }
    }
}

// ------------------------- epilogues ----------------------------------------
struct EpiQ {
    __device__ void operator()(int, int m, int n, float v) const {
        int hh = n >> 6, dd = n & 63;
        int b = m / Nn, nn = m - b * Nn;
        g_s[OQ + (((long long)(b * Hh + hh)) * Nn + nn) * Dd + dd]
            = v * 0.35355339059327378f;
    }
};
struct EpiKV {    // k -> kT[bh][d][n] (scaled); v -> (BH,N,D)
    __device__ void operator()(int, int m, int n, float v) const {
        int part = n / Cc, c = n - part * Cc;
        int hh = c >> 6, dd = c & 63;
        int b = m / Nn, nn = m - b * Nn;
        if (part == 0)
            g_s[OKk + (((long long)(b * Hh + hh)) * Dd + dd) * Nn + nn]
                = v * 0.35355339059327378f;
        else
            g_s[OV + (((long long)(b * Hh + hh)) * Nn + nn) * Dd + dd] = v;
    }
};
struct EpiK1 {    // logits1 (BH,N,L); z=bh
    __device__ void operator()(int z, int m, int n, float v) const {
        g_s[OK1 + ((long long)z * Nn + m) * Ll + n] = v;
    }
};
struct EpiK2 {
    __device__ void operator()(int z, int m, int n, float v) const {
        int f = n / Pp, p = n - f * Pp;
        g_s[OK2 + (((long long)z * Ll + m) * Ff + f) * PPAD + p] = v;
    }
};
struct EpiX1 {
    __device__ void operator()(int z, int m, int n, float v) const {
        int bh = z >> 4, f = z & 15;
        g_s[OX1 + (((long long)bh * Ll + m) * Ff + f) * Dd + n] = v;
    }
};
struct EpiXO {
    __device__ void operator()(int z, int m, int n, float v) const {
        int b = z / Hh, hh = z - b * Hh;
        int f = n >> 6, dd = n & 63;
        long long base = (long long)(b * Nn + m);
        g_s[OXO + (base * Ff + f) * Cc + hh * Dd + dd] = v;
        if (f == m / Pp) g_s[OXD + base * Cc + hh * Dd + dd] = v;
    }
};
struct EpiQ2 {
    __device__ void operator()(int, int m, int n, float v) const {
        g_s[OQ2 + (long long)m * Cc + n] = v * 0.125f;
    }
};
struct EpiU {
    __device__ void operator()(int z, int m, int n, float v) const {
        g_s[OU + ((long long)m * Hh + z) * Cc + n] = v;
    }
};
struct EpiAO {
    __device__ void operator()(int z, int m, int n, float v) const {
        g_s[OAO + (long long)m * Cc + z * 64 + n] = v;
    }
};
struct EpiOut {
    float* out; const float* bias;
    __device__ void operator()(int, int m, int n, float v) const {
        out[(long long)m * Cc + n] = v + bias[n];
    }
};

// ------------------------- small kernels ------------------------------------
__global__ void norm_kernel() {
    long long gw = (long long)blockIdx.x * 8 + (threadIdx.x >> 5);
    int lane = threadIdx.x & 31;
    float2 v = ((const float2*)(g_s + OQ + gw * Dd))[lane];
    float ss = v.x * v.x + v.y * v.y;
#pragma unroll
    for (int o = 16; o; o >>= 1) ss += __shfl_xor_sync(0xffffffffu, ss, o);
    float dnm = fmaxf(sqrtf(ss), 1e-12f);
    int bh = (int)(gw / Nn), n = (int)(gw - (long long)bh * Nn);
    long long base = OQKN + (long long)bh * Nn * Dd;
    g_s[base + (long long)(2 * lane)     * Nn + n] = v.x / dnm;
    g_s[base + (long long)(2 * lane + 1) * Nn + n] = v.y / dnm;
}

__device__ __forceinline__ unsigned ctarank() {
    unsigned r; asm("mov.u32 %0, %%cluster_ctarank;" : "=r"(r)); return r;
}
__device__ __forceinline__ unsigned mapa_u32(unsigned addr, unsigned rank) {
    unsigned r; asm("mapa.shared::cluster.u32 %0, %1, %2;" : "=r"(r) : "r"(addr), "r"(rank));
    return r;
}

// ---- MEGA kernel: FPS clusters + kv-GEMM tiles + Wk transpose tiles --------
__global__ __launch_bounds__(256) __cluster_dims__(FB, 1, 1) void mega_kernel(
    const float* __restrict__ x, const float* __restrict__ Wqkv,
    const float* __restrict__ Wpkv)
{
    extern __shared__ float ssm[];
    const int bx = blockIdx.x;
    const int tid = threadIdx.x;

    if (bx < BH * FB) {
        // ======================= FPS path =======================
        __shared__ unsigned long long cand[2][FB];
        __shared__ float cur[Dd];
        __shared__ float s_val[8];
        __shared__ int   s_idx[8], s_pick;
        const int b = bx / FB;
        const int j = (int)ctarank();
        const float* qkT = g_s + OQKN + (long long)b * Nn * Dd;
        for (int i = tid; i < Dd * NCF; i += 256) {
            int d = i / NCF, c = i % NCF;
            *(float4*)&ssm[d * NS + 4 * c] =
                *(const float4*)(qkT + (long long)d * Nn + j * NS + 4 * c);
        }
        float ms0 = 0.f, ms1 = 0.f;
        if (tid == 0) {
            int i0 = jax_idx0(b);
            if (j == 0) g_idx[b * Ll] = i0;
            s_pick = i0;
        }
        __syncthreads();
        int pick = s_pick;
        if (tid < Dd) cur[tid] = qkT[(long long)tid * Nn + pick];
        if (tid == (pick >> 1) - j * NC2) {
            if (pick & 1) ms1 = 10.f; else ms0 = 10.f;
        }
        __syncthreads();
        const int lane = tid & 31, wid = tid >> 5;
        const unsigned candBase = (unsigned)__cvta_generic_to_shared(&cand[0][0]);
        for (int step = 1; step < Ll; step++) {
            float bv = 3.4e38f; int bi = 0x7fffffff;
            if (tid < NC2) {
                float ax = 0.f, ay = 0.f;
#pragma unroll
                for (int d = 0; d < Dd; d++) {
                    float2 v = *(const float2*)&ssm[d * NS + 2 * tid];
                    float c = cur[d];
                    ax += v.x * c; ay += v.y * c;
                }
                ms0 = fmaxf(ms0, fabsf(ax)); ms1 = fmaxf(ms1, fabsf(ay));
                int nb = j * NS + 2 * tid;
                bv = ms0; bi = nb;
                if (ms1 < bv) { bv = ms1; bi = nb + 1; }
            }
#pragma unroll
            for (int o = 16; o; o >>= 1) {
                float ov = __shfl_down_sync(0xffffffffu, bv, o);
                int   oi = __shfl_down_sync(0xffffffffu, bi, o);
                if (ov < bv || (ov == bv && oi < bi)) { bv = ov; bi = oi; }
            }
            if (lane == 0) { s_val[wid] = bv; s_idx[wid] = bi; }
            __syncthreads();
            const int par = step & 1;
            if (tid == 0) {
#pragma unroll
                for (int w = 0; w < 8; w++) {
                    float ov = s_val[w]; int oi = s_idx[w];
                    if (w == 0 || ov < bv || (ov == bv && oi < bi)) { bv = ov; bi = oi; }
                }
                unsigned long long packed =
                    ((unsigned long long)__float_as_uint(bv) << 32) | (unsigned)bi;
                unsigned slot = candBase + (unsigned)((par * FB + j) * 8);
#pragma unroll
                for (int jj = 0; jj < FB; jj++) {
                    unsigned raddr = mapa_u32(slot, (unsigned)jj);
                    asm volatile("st.shared::cluster.b64 [%0], %1;" :: "r"(raddr), "l"(packed));
                }
            }
            asm volatile("barrier.cluster.arrive.aligned;" ::: "memory");
            asm volatile("barrier.cluster.wait.aligned;" ::: "memory");
            unsigned long long best = cand[par][0];
#pragma unroll
            for (int jj = 1; jj < FB; jj++) {
                unsigned long long c2 = cand[par][jj];
                if (c2 < best) best = c2;
            }
            pick = (int)(unsigned)(best & 0xffffffffull);
            if (j == 0 && tid == 0) g_idx[b * Ll + step] = pick;
            if (tid < Dd) cur[tid] = qkT[(long long)tid * Nn + pick];
            if (tid == (pick >> 1) - j * NC2) {
                if (pick & 1) ms1 = 10.f; else ms0 = 10.f;
            }
            __syncthreads();
        }
    } else if (bx < BH * FB + KVT) {
        // ======================= kv tf32 GEMM tile =======================
        constexpr int BMk = 128, BNk = 128, BKk = 16;
        constexpr int LDAk = BKk + 4, LDBk = BNk + 8;
        const int t0 = bx - BH * FB;
        const int m0 = (t0 / 12) * BMk;
        const int n0 = (t0 % 12) * BNk;
        float* As = ssm;
        float* Bs = ssm + 3 * BMk * LDAk;
        const float* Ab = x + (long long)m0 * Cc;
        const float* Bb = Wqkv + Cc + n0;
        const int wid = tid >> 5, lane = tid & 31;
        const int wm = (wid >> 2) * 64, wn = (wid & 3) * 32;
        const int g = lane >> 2, tt = lane & 3;
        EpiKV epi{};

        float acc[4][4][4];
#pragma unroll
        for (int i = 0; i < 4; i++)
#pragma unroll
            for (int j2 = 0; j2 < 4; j2++)
#pragma unroll
                for (int r = 0; r < 4; r++) acc[i][j2][r] = 0.f;

        auto stage_load = [&](int s, int k0) {
#pragma unroll
            for (int i = tid; i < BMk * 4; i += 256) {
                int m = i >> 2, kq = i & 3;
                cpa16(&As[s * BMk * LDAk + m * LDAk + kq * 4],
                      Ab + (long long)m * Cc + k0 + kq * 4);
            }
#pragma unroll
            for (int i = tid; i < BKk * (BNk / 4); i += 256) {
                int kk = i / (BNk / 4), nq = i % (BNk / 4);
                cpa16(&Bs[s * BKk * LDBk + kk * LDBk + nq * 4],
                      Bb + (long long)(k0 + kk) * (3 * Cc) + nq * 4);
            }
            asm volatile("cp.async.commit_group;");
        };

        const int KT2 = Cc / BKk;
        stage_load(0, 0);
        stage_load(1, BKk);
        for (int kt = 0; kt < KT2; kt++) {
            const int s = kt % 3;
            if (kt + 2 < KT2) {
                stage_load((kt + 2) % 3, (kt + 2) * BKk);
                asm volatile("cp.async.wait_group 2;");
            } else if (kt + 1 < KT2) {
                asm volatile("cp.async.wait_group 1;");
            } else {
                asm volatile("cp.async.wait_group 0;");
            }
            __syncthreads();
#pragma unroll
            for (int ks = 0; ks < 2; ks++) {
                const int kb = ks * 8;
                float a[4][4], b[4][2];
#pragma unroll
                for (int mf = 0; mf < 4; mf++) {
                    int ml = wm + mf * 16 + g;
                    a[mf][0] = to_tf32(As[s * BMk * LDAk +  ml      * LDAk + kb + tt]);
                    a[mf][1] = to_tf32(As[s * BMk * LDAk + (ml + 8) * LDAk + kb + tt]);
                    a[mf][2] = to_tf32(As[s * BMk * LDAk +  ml      * LDAk + kb + tt + 4]);
                    a[mf][3] = to_tf32(As[s * BMk * LDAk + (ml + 8) * LDAk + kb + tt + 4]);
                }
#pragma unroll
                for (int nf = 0; nf < 4; nf++) {
                    int nb = wn + nf * 8 + g;
                    b[nf][0] = to_tf32(Bs[s * BKk * LDBk + (kb + tt)     * LDBk + nb]);
                    b[nf][1] = to_tf32(Bs[s * BKk * LDBk + (kb + tt + 4) * LDBk + nb]);
                }
#pragma unroll
                for (int mf = 0; mf < 4; mf++)
#pragma unroll
                    for (int nf = 0; nf < 4; nf++)
                        mma_tf32(acc[mf][nf], a[mf], b[nf]);
            }
            __syncthreads();
        }
#pragma unroll
        for (int mf = 0; mf < 4; mf++) {
            int m = m0 + wm + mf * 16 + g;
#pragma unroll
            for (int nf = 0; nf < 4; nf++) {
                int n = n0 + wn + nf * 8 + 2 * tt;
                epi(0, m,     n,     acc[mf][nf][0]);
                epi(0, m,     n + 1, acc[mf][nf][1]);
                epi(0, m + 8, n,     acc[mf][nf][2]);
                epi(0, m + 8, n + 1, acc[mf][nf][3]);
            }
        }
    } else if (bx < BH * FB + KVT + TRT) {
        // ======================= Wk transpose tile =======================
        __shared__ float tsm[32][33];
        const int t2 = bx - (BH * FB + KVT);
        int j0 = (t2 % 24) * 32, c0 = (t2 / 24) * 32;
        int tx = tid & 31, ty = tid >> 5;
#pragma unroll
        for (int i = 0; i < 32; i += 8)
            tsm[ty + i][tx] = Wpkv[(long long)(c0 + ty + i) * (2 * Cc) + j0 + tx];
        __syncthreads();
#pragma unroll
        for (int i = 0; i < 32; i += 8)
            g_s[OWKT + (long long)(j0 + ty + i) * Cc + c0 + tx] = tsm[tx][ty + i];
    }
}

// gather landmarks: lm[bh][l][:] and lm^T[bh][:][l]
__global__ void gather_lm() {
    int gw = blockIdx.x * 8 + (threadIdx.x >> 5);
    int lane = threadIdx.x & 31;
    int bh = gw >> 7, l = gw & 127;
    int idx = g_idx[gw];
    float2 v = ((const float2*)(g_s + OQ + ((long long)bh * Nn + idx) * Dd))[lane];
    ((float2*)(g_s + OLM + (long long)gw * Dd))[lane] = v;
    long long tb = OLMT + (long long)bh * Dd * Ll;
    g_s[tb + (long long)(2 * lane)     * Ll + l] = v.x;
    g_s[tb + (long long)(2 * lane + 1) * Ll + l] = v.y;
}

__global__ void softmax128() {   // in-place on K1, one warp per 128-row
    long long r = (long long)blockIdx.x * 8 + (threadIdx.x >> 5);
    int lane = threadIdx.x & 31;
    float4* row = (float4*)(g_s + OK1 + r * Ll);
    float4 v = row[lane];
    float mx = fmaxf(fmaxf(v.x, v.y), fmaxf(v.z, v.w));
#pragma unroll
    for (int o = 16; o; o >>= 1) mx = fmaxf(mx, __shfl_xor_sync(0xffffffffu, mx, o));
    v.x = expf(v.x - mx); v.y = expf(v.y - mx); v.z = expf(v.z - mx); v.w = expf(v.w - mx);
    float s = v.x + v.y + v.z + v.w;
#pragma unroll
    for (int o = 16; o; o >>= 1) s += __shfl_xor_sync(0xffffffffu, s, o);
    float inv = 1.f / s;
    v.x *= inv; v.y *= inv; v.z *= inv; v.w *= inv;
    row[lane] = v;
}

__global__ void softmax196() {
    long long r = (long long)blockIdx.x * 8 + (threadIdx.x >> 5);
    int lane = threadIdx.x & 31;
    float* row = g_s + OK2 + r * PPAD;
    float v[7], mx = -1e30f;
#pragma unroll
    for (int j = 0; j < 7; j++) { int i = lane + 32*j; v[j] = (i < Pp) ? row[i] : -1e30f; mx = fmaxf(mx, v[j]); }
#pragma unroll
    for (int o = 16; o; o >>= 1) mx = fmaxf(mx, __shfl_xor_sync(0xffffffffu, mx, o));
    float s = 0.f;
#pragma unroll
    for (int j = 0; j < 7; j++) { int i = lane + 32*j; if (i < Pp) { v[j] = expf(v[j] - mx); s += v[j]; } }
#pragma unroll
    for (int o = 16; o; o >>= 1) s += __shfl_xor_sync(0xffffffffu, s, o);
    float inv = 1.f / s;
#pragma unroll
    for (int j = 0; j < 7; j++) { int i = lane + 32*j; if (i < Pp) row[i] = v[j] * inv; }
    if (lane < PPAD - Pp) row[Pp + lane] = 0.f;
}

__global__ __launch_bounds__(384) void attn2_kernel(float* outAttn) {
    extern __shared__ float xos[];
    __shared__ float lg[Hh][Ff];
    __shared__ float wts[Hh][Ff];
    const int bn = blockIdx.x;
    const int tid = threadIdx.x, h = tid >> 5, lane = tid & 31;
    const float* xsrc = g_s + OXO + (long long)bn * Ff * Cc;
    for (int i = tid; i < Ff * Cc / 4; i += 384)
        ((float4*)xos)[i] = ((const float4*)xsrc)[i];
    float ureg[24];
    const float* urow = g_s + OU + ((long long)bn * Hh + h) * Cc;
#pragma unroll
    for (int i = 0; i < 24; i++) ureg[i] = urow[lane + 32 * i];
    __syncthreads();
#pragma unroll
    for (int f = 0; f < Ff; f++) {
        const float* xr = xos + f * Cc;
        float p = 0.f;
#pragma unroll
        for (int i = 0; i < 24; i++) p += ureg[i] * xr[lane + 32 * i];
#pragma unroll
        for (int o = 16; o; o >>= 1) p += __shfl_xor_sync(0xffffffffu, p, o);
        if (lane == 0) lg[h][f] = p;
    }
    __syncwarp();
    float mx = -1e30f;
#pragma unroll
    for (int f = 0; f < Ff; f++) mx = fmaxf(mx, lg[h][f]);
    float s = 0.f;
#pragma unroll
    for (int f = 0; f < Ff; f++) s += expf(lg[h][f] - mx);
    float inv = 1.f / s;
    if (lane < Ff) {
        float w = expf(lg[h][lane] - mx) * inv;
        wts[h][lane] = w;
        int b = bn / Nn, n = bn - b * Nn;
        outAttn[(((long long)(b * Hh + h)) * Nn + n) * Ff + lane] = w;
    }
    __syncwarp();
    float* xw = g_s + OXW + ((long long)bn * Hh + h) * Cc;
#pragma unroll
    for (int i = 0; i < 24; i++) {
        float acc = 0.f;
#pragma unroll
        for (int f = 0; f < Ff; f++) acc += wts[h][f] * xos[f * Cc + lane + 32 * i];
        xw[lane + 32 * i] = acc;
    }
}

// ------------------------- launch -------------------------------------------
extern "C" void kernel_launch(void* const* d_in, const int*, int, void* d_out, int) {
    const float* x     = (const float*)d_in[0];
    const float* Wqkv  = (const float*)d_in[1];
    const float* Wpq   = (const float*)d_in[2];
    const float* Wpkv  = (const float*)d_in[3];
    const float* Wproj = (const float*)d_in[4];
    const float* bproj = (const float*)d_in[5];
    float* out = (float*)d_out;

    float* sc = nullptr;
    cudaGetSymbolAddress((void**)&sc, g_s);

    const int fps_smem = Dd * NS * (int)sizeof(float);       // 100352 B
    cudaFuncSetAttribute(mega_kernel, cudaFuncAttributeMaxDynamicSharedMemorySize, fps_smem);
    const int at2_smem = Ff * Cc * (int)sizeof(float);       // 49152 B
    cudaFuncSetAttribute(attn2_kernel, cudaFuncAttributeMaxDynamicSharedMemorySize, at2_smem);

    // 1) q = x @ Wqkv[:, 0:768]  (3xTF32 — FPS needs near-fp32 q)
    gemm_tf32<128,4,true,EpiQ><<<dim3(6,49,1),256>>>(
        x, Wqkv, Cc, Cc, 3*Cc, 0,0,0,0, 1, EpiQ{});
    norm_kernel<<<9408,256>>>();
    // 2) MEGA: FPS + kv GEMM (k stored transposed) + Wk^T
    mega_kernel<<<GRID_MEGA,256,fps_smem>>>(x, Wqkv, Wpkv);
    gather_lm<<<384,256>>>();
    // 3) kernel_1 logits (tf32: q @ lmT) + row softmax
    gemm_tf32<64,4,false,EpiK1><<<dim3(1,49,BH),256>>>(
        sc+OQ, sc+OLMT, Dd, Dd, Ll,
        (long long)Nn*Dd,0, (long long)Dd*Ll,0, 1, EpiK1{});
    softmax128<<<9408,256>>>();
    // 4) kernel_2 logits (tf32: lm @ kT)
    gemm_tf32<128,2,false,EpiK2><<<dim3(49,1,BH),256>>>(
        sc+OLM, sc+OKk, Dd, Dd, Nn,
        (long long)Ll*Dd,0, (long long)Dd*Nn,0, 1, EpiK2{});
    softmax196<<<6144,256>>>();
    // 5) x1 = kernel_2 @ v  (tf32, composite batch z=bh*16+f)
    gemm_tf32<128,2,false,EpiX1><<<dim3(1,1,BH*Ff),256>>>(
        sc+OK2, sc+OV, PPAD, Ff*PPAD, Dd,
        (long long)Ll*Ff*PPAD, PPAD, (long long)Nn*Dd, (long long)Pp*Dd, Ff, EpiX1{});
    // 6) xo = kernel_1 @ x1  (tf32)
    gemm_tf32<64,4,false,EpiXO><<<dim3(8,49,BH),256>>>(
        sc+OK1, sc+OX1, Ll, Ll, Ff*Dd,
        (long long)Nn*Ll,0, (long long)Ll*Ff*Dd,0, 1, EpiXO{});
    // 7) q2 = xdiag @ W_pq  (tf32, scaled)
    gemm_tf32<128,4,false,EpiQ2><<<dim3(6,49,1),256>>>(
        sc+OXD, Wpq, Cc, Cc, Cc, 0,0,0,0, 1, EpiQ2{});
    // 8) u = q2 @ WkT_h  (batched over h)
    gemm_tf32<128,4,false,EpiU><<<dim3(6,49,Hh),256>>>(
        sc+OQ2, sc+OWKT, Dd, Cc, Cc, 64,0, (long long)64*Cc,0, 1, EpiU{});
    // 9) fused logits + softmax + attn-out + weighted xo
    attn2_kernel<<<Bb*Nn,384,at2_smem>>>(out + (long long)Bb*Nn*Cc);
    // 10) ao = xo_w @ Wv_h
    gemm_tf32<128,2,false,EpiAO><<<dim3(1,49,Hh),256>>>(
        sc+OXW, Wpkv + Cc, Cc, Hh*Cc, 2*Cc, Cc,0, 64,0, 1, EpiAO{});
    // 11) out = ao @ W_proj + b
    gemm_tf32<128,4,false,EpiOut><<<dim3(6,49,1),256>>>(
        sc+OAO, Wproj, Cc, Cc, Cc, 0,0,0,0, 1, EpiOut{out, bproj});
}